// round 9
// baseline (speedup 1.0000x reference)
#include <cuda_runtime.h>
#include <cuda_fp16.h>
#include <math.h>
#include <stdint.h>

// Problem constants
#define BATCH   512
#define NNODES  256
#define MROWS   (BATCH * NNODES)     // 131072
#define FEAT_IN 512
#define GLOB_D  64
#define KIN     576
#define FHID    1024
#define AHID    256
#define FOUT    256
#define NTOT1   (FHID + AHID)        // 1280
#define NHEADS  4
#define LN_EPS  1e-5f

// ---------------------------------------------------------------------------
// Scratch (device globals; no runtime allocation)
// ---------------------------------------------------------------------------
__device__ __half g_inp[(size_t)MROWS * FEAT_IN];      // fp16 LN output [M,512]
__device__ __half g_hid[(size_t)MROWS * FHID];         // fp16 silu hidden [M,1024]
__device__ __half g_ah [(size_t)MROWS * AHID];         // fp16 attn hidden [M,256]
__device__ float  g_scores[(size_t)MROWS * NHEADS];
__device__ float  g_wsm   [(size_t)MROWS * NHEADS];
__device__ __half g_w1t[(size_t)NTOT1 * FEAT_IN];      // [1280,512] (fw1||aw1)^T fp16
__device__ __half g_w2t[(size_t)FOUT * FHID];          // [256,1024] fw2^T fp16
__device__ float  g_ctx1[(size_t)BATCH * NTOT1];       // per-graph ctx contribution

// ---------------------------------------------------------------------------
// PTX helpers (baseline ISA: works at compute_103 target)
// ---------------------------------------------------------------------------
__device__ __forceinline__ uint32_t smem_u32(const void* p) {
    uint32_t a;
    asm("{ .reg .u64 t; cvta.to.shared.u64 t, %1; cvt.u32.u64 %0, t; }"
        : "=r"(a) : "l"(p));
    return a;
}

#define CP_ASYNC16(dst, src) \
    asm volatile("cp.async.cg.shared.global [%0], [%1], 16;" \
        :: "r"(dst), "l"(src))
#define CP_COMMIT()  asm volatile("cp.async.commit_group;" ::: "memory")
#define CP_WAIT1()   asm volatile("cp.async.wait_group 1;" ::: "memory")

#define LDSM_X4(r0, r1, r2, r3, addr) \
    asm volatile("ldmatrix.sync.aligned.m8n8.x4.shared.b16 {%0,%1,%2,%3}, [%4];" \
        : "=r"(r0), "=r"(r1), "=r"(r2), "=r"(r3) : "r"(addr))

#define MMA16816(c, a, b) \
    asm volatile("mma.sync.aligned.m16n8k16.row.col.f32.f16.f16.f32 " \
        "{%0,%1,%2,%3}, {%4,%5,%6,%7}, {%8,%9}, {%0,%1,%2,%3};" \
        : "+f"((c)[0]), "+f"((c)[1]), "+f"((c)[2]), "+f"((c)[3]) \
        : "r"((a)[0]), "r"((a)[1]), "r"((a)[2]), "r"((a)[3]), \
          "r"((b)[0]), "r"((b)[1]))

__device__ __forceinline__ float warp_sum(float v) {
    #pragma unroll
    for (int o = 16; o > 0; o >>= 1) v += __shfl_xor_sync(0xffffffffu, v, o);
    return v;
}

__device__ __forceinline__ float silu(float v) {
    return __fdividef(v, 1.0f + __expf(-v));
}

// ---------------------------------------------------------------------------
// Kernel 1: LayerNorm(concat(nodes, pe)) -> g_inp fp16 [M,512]
// ---------------------------------------------------------------------------
__global__ void prep_kernel(const float* __restrict__ nodes,
                            const float* __restrict__ pe,
                            const float* __restrict__ ln_g,
                            const float* __restrict__ ln_b,
                            __half* __restrict__ inp)
{
    const int row = blockIdx.x;
    const int t   = threadIdx.x;          // 0..127

    float4 v = (t < 64)
        ? ((const float4*)nodes)[(size_t)row * 64 + t]
        : ((const float4*)pe)   [(size_t)row * 64 + (t - 64)];

    float s  = v.x + v.y + v.z + v.w;
    float sq = v.x*v.x + v.y*v.y + v.z*v.z + v.w*v.w;

    __shared__ float ssum[4], ssq[4];
    __shared__ float s_mu, s_rstd;
    const int lane = t & 31, wid = t >> 5;
    float ws = warp_sum(s), wq = warp_sum(sq);
    if (lane == 0) { ssum[wid] = ws; ssq[wid] = wq; }
    __syncthreads();
    if (t == 0) {
        float S = ssum[0] + ssum[1] + ssum[2] + ssum[3];
        float Q = ssq[0]  + ssq[1]  + ssq[2]  + ssq[3];
        float mu  = S * (1.0f / FEAT_IN);
        float var = Q * (1.0f / FEAT_IN) - mu * mu;
        s_mu = mu; s_rstd = rsqrtf(var + LN_EPS);
    }
    __syncthreads();
    const float mu = s_mu, rstd = s_rstd;

    float4 g4 = ((const float4*)ln_g)[t];
    float4 b4 = ((const float4*)ln_b)[t];
    float o0 = (v.x - mu) * rstd * g4.x + b4.x;
    float o1 = (v.y - mu) * rstd * g4.y + b4.y;
    float o2 = (v.z - mu) * rstd * g4.z + b4.z;
    float o3 = (v.w - mu) * rstd * g4.w + b4.w;

    __half* dst = inp + (size_t)row * FEAT_IN + t * 4;
    *(__half2*)(dst)     = __floats2half2_rn(o0, o1);
    *(__half2*)(dst + 2) = __floats2half2_rn(o2, o3);
}

// ---------------------------------------------------------------------------
// Per-graph ctx contribution: ctx1[b,n] = sum_j globs[b,j] * W[512+j, n]
// ---------------------------------------------------------------------------
__global__ void ctx_kernel(const float* __restrict__ globs,
                           const float* __restrict__ fw1,
                           const float* __restrict__ aw1,
                           float* __restrict__ ctx1)
{
    __shared__ float gs[GLOB_D];
    const int b = blockIdx.x;
    if (threadIdx.x < GLOB_D) gs[threadIdx.x] = globs[b * GLOB_D + threadIdx.x];
    __syncthreads();
    for (int n = threadIdx.x; n < NTOT1; n += blockDim.x) {
        float acc = 0.f;
        if (n < FHID) {
            #pragma unroll 8
            for (int j = 0; j < GLOB_D; j++)
                acc = fmaf(gs[j], fw1[(size_t)(FEAT_IN + j) * FHID + n], acc);
        } else {
            #pragma unroll 8
            for (int j = 0; j < GLOB_D; j++)
                acc = fmaf(gs[j], aw1[(size_t)(FEAT_IN + j) * AHID + (n - FHID)], acc);
        }
        ctx1[(size_t)b * NTOT1 + n] = acc;
    }
}

// ---------------------------------------------------------------------------
// Weight transpose + fp16 cast
// ---------------------------------------------------------------------------
__global__ void wtrans_kernel(const float* __restrict__ W1, int N1, int ld1,
                              const float* __restrict__ W2, int N2, int ld2,
                              int K, __half* __restrict__ Wt)
{
    __shared__ float tile[32][33];
    const int nb = blockIdx.x * 32, kb = blockIdx.y * 32;
    const int tx = threadIdx.x, ty = threadIdx.y;
    const int Ntot = N1 + N2;
    for (int i = ty; i < 32; i += 8) {
        int k = kb + i, n = nb + tx;
        float v = 0.f;
        if (k < K && n < Ntot)
            v = (n < N1) ? W1[(size_t)k * ld1 + n] : W2[(size_t)k * ld2 + (n - N1)];
        tile[i][tx] = v;
    }
    __syncthreads();
    for (int i = ty; i < 32; i += 8) {
        int n = nb + i, k = kb + tx;
        if (n < Ntot && k < K)
            Wt[(size_t)n * K + k] = __float2half_rn(tile[tx][i]);
    }
}

// ---------------------------------------------------------------------------
// HGEMM via mma.sync m16n8k16: C[M,N] = A[M,K] @ Bt[N,K]^T (+epilogue)
// CTA tile 128x256, BK=32, 3-stage cp.async pipeline, 16 warps (4m x 4n),
// warp tile 32x64. Smem row stride 40 halfs (80B) -> conflict-free ldmatrix.
// Loader (512 thr): A = 512 x 16B slots (1/thread), B = 1024 slots (2/thread).
// MODE 0 (GEMM1): silu(x + bias + ctx); ncol<1024 -> fp16 outh; else fp16 outa.
// MODE 1 (GEMM3): x + bias1, zero-if-!mask, +residual -> fp32 outf.
// ---------------------------------------------------------------------------
#define NSTAGE    3
#define A_BYTES   10240               // 128*40*2
#define B_BYTES   20480               // 256*40*2
#define GSTAGE_B  (A_BYTES + B_BYTES) // 30720
#define GSMEM     (NSTAGE * GSTAGE_B) // 92160

template<int MODE>
__global__ __launch_bounds__(512, 1) void gemm_mma(
    const __half* __restrict__ A, const __half* __restrict__ Bt, int K,
    const float* __restrict__ bias1, const float* __restrict__ bias2,
    const float* __restrict__ ctx1,
    __half* __restrict__ outh, __half* __restrict__ outa,
    float* __restrict__ outf,
    const int* __restrict__ mask, const float* __restrict__ residual)
{
    extern __shared__ char smem[];
    const uint32_t sbase = smem_u32(smem);
    const int tid    = threadIdx.x;
    const int wid    = tid >> 5;
    const int lane   = tid & 31;
    const int warp_m = wid & 3;        // 4 groups of 32 rows
    const int warp_n = wid >> 2;       // 4 groups of 64 cols
    const int row0   = blockIdx.y * 128;
    const int col0   = blockIdx.x * 256;
    const int iters  = K >> 5;

    // cp.async mapping (512 threads, K-tile = 32 halfs = 4 x 16B chunks/row):
    //   ar in [0,128): row; kc in {0,8,16,24}: k-offset (halfs)
    const int ar = tid >> 2;
    const int kc = (tid & 3) * 8;

    float acc[2][8][4];
    #pragma unroll
    for (int mt = 0; mt < 2; mt++)
        #pragma unroll
        for (int nt = 0; nt < 8; nt++)
            #pragma unroll
            for (int j = 0; j < 4; j++) acc[mt][nt][j] = 0.f;

    // ldmatrix lane-derived offsets
    const int lm = lane & 15, lq = lane >> 4;
    const uint32_t aoff = ((warp_m * 32 + lm) * 40 + lq * 8) * 2;
    const int bn = (lane >> 4) * 8 + (lane & 7);
    const int bk = ((lane >> 3) & 1) * 8;
    const uint32_t boff = ((warp_n * 64 + bn) * 40 + bk) * 2;

    auto load_stage = [&](int s, int kk) {
        const uint32_t dA = sbase + s * GSTAGE_B;
        const uint32_t dB = dA + A_BYTES;
        // A: 128 rows -> 1 chunk per thread
        CP_ASYNC16(dA + (ar * 40 + kc) * 2, &A[(size_t)(row0 + ar) * K + kk + kc]);
        // B: 256 rows -> 2 chunks per thread
        #pragma unroll
        for (int i = 0; i < 2; i++) {
            const int r = ar + i * 128;
            CP_ASYNC16(dB + (r * 40 + kc) * 2, &Bt[(size_t)(col0 + r) * K + kk + kc]);
        }
    };

    load_stage(0, 0);  CP_COMMIT();
    load_stage(1, 32); CP_COMMIT();

    for (int i = 0; i < iters; i++) {
        CP_WAIT1();
        __syncthreads();
        if (i + 2 < iters) load_stage((i + 2) % NSTAGE, (i + 2) * 32);
        CP_COMMIT();

        const int s = i % NSTAGE;
        const uint32_t sA = sbase + s * GSTAGE_B;
        const uint32_t sB = sA + A_BYTES;

        #pragma unroll
        for (int ks = 0; ks < 2; ks++) {
            uint32_t a[2][4];
            #pragma unroll
            for (int mt = 0; mt < 2; mt++)
                LDSM_X4(a[mt][0], a[mt][1], a[mt][2], a[mt][3],
                        sA + aoff + mt * 1280 + ks * 32);
            uint32_t b[8][2];
            #pragma unroll
            for (int np = 0; np < 4; np++) {
                uint32_t r0, r1, r2, r3;
                LDSM_X4(r0, r1, r2, r3, sB + boff + np * 1280 + ks * 32);
                b[np * 2][0]     = r0; b[np * 2][1]     = r1;
                b[np * 2 + 1][0] = r2; b[np * 2 + 1][1] = r3;
            }
            #pragma unroll
            for (int mt = 0; mt < 2; mt++)
                #pragma unroll
                for (int nt = 0; nt < 8; nt++)
                    MMA16816(acc[mt][nt], a[mt], b[nt]);
        }
        // top-of-loop sync (after wait) protects stage reuse (load dist = NSTAGE-1)
    }

    // ---------------- epilogue ----------------
    const int mrow0 = row0 + warp_m * 32 + (lane >> 2);
    const int ncb   = col0 + warp_n * 64 + (lane & 3) * 2;

    #pragma unroll
    for (int mt = 0; mt < 2; mt++) {
        #pragma unroll
        for (int half = 0; half < 2; half++) {     // row, row+8
            const int r = mrow0 + mt * 16 + half * 8;
            const int bg = r >> 8;                 // graph index
            int mv = 1;
            if (MODE == 1) mv = mask[r];
            #pragma unroll
            for (int nt = 0; nt < 8; nt++) {
                const int ncol = ncb + nt * 8;
                float v0 = acc[mt][nt][half * 2];
                float v1 = acc[mt][nt][half * 2 + 1];
                if (MODE == 0) {
                    const float c0 = ctx1[(size_t)bg * NTOT1 + ncol];
                    const float c1 = ctx1[(size_t)bg * NTOT1 + ncol + 1];
                    if (ncol < FHID) {
                        v0 = silu(v0 + bias1[ncol]     + c0);
                        v1 = silu(v1 + bias1[ncol + 1] + c1);
                        *(__half2*)&outh[(size_t)r * FHID + ncol] =
                            __floats2half2_rn(v0, v1);
                    } else {
                        const int a0 = ncol - FHID;
                        v0 = silu(v0 + bias2[a0]     + c0);
                        v1 = silu(v1 + bias2[a0 + 1] + c1);
                        *(__half2*)&outa[(size_t)r * AHID + a0] =
                            __floats2half2_rn(v0, v1);
                    }
                } else {
                    v0 += bias1[ncol];
                    v1 += bias1[ncol + 1];
                    if (!mv) { v0 = 0.f; v1 = 0.f; }
                    float2 o;
                    o.x = v0 + residual[(size_t)r * FOUT + ncol];
                    o.y = v1 + residual[(size_t)r * FOUT + ncol + 1];
                    *(float2*)&outf[(size_t)r * FOUT + ncol] = o;
                }
            }
        }
    }
}

// ---------------------------------------------------------------------------
// scores[M,4] = g_ah[M,256] @ aw2[256,4] + ab2  (one warp per row, fp16 in)
// ---------------------------------------------------------------------------
__global__ void attn2_kernel(const __half* __restrict__ ah,
                             const float* __restrict__ aw2,
                             const float* __restrict__ ab2,
                             float* __restrict__ scores)
{
    const int warp = (blockIdx.x * blockDim.x + threadIdx.x) >> 5;
    const int lane = threadIdx.x & 31;
    if (warp >= MROWS) return;
    const __half2* a2 = (const __half2*)(ah + (size_t)warp * AHID);
    float a0 = 0.f, a1 = 0.f, a2s = 0.f, a3 = 0.f;
    #pragma unroll
    for (int i = 0; i < 4; i++) {
        const int k2 = i * 32 + lane;      // half2 index (k = 2*k2, 2*k2+1)
        __half2 h = a2[k2];
        float f0 = __low2float(h), f1 = __high2float(h);
        float4 w0 = ((const float4*)aw2)[2 * k2];
        float4 w1 = ((const float4*)aw2)[2 * k2 + 1];
        a0  = fmaf(f0, w0.x, fmaf(f1, w1.x, a0));
        a1  = fmaf(f0, w0.y, fmaf(f1, w1.y, a1));
        a2s = fmaf(f0, w0.z, fmaf(f1, w1.z, a2s));
        a3  = fmaf(f0, w0.w, fmaf(f1, w1.w, a3));
    }
    a0 = warp_sum(a0); a1 = warp_sum(a1); a2s = warp_sum(a2s); a3 = warp_sum(a3);
    if (lane == 0)
        ((float4*)scores)[warp] =
            make_float4(a0 + ab2[0], a1 + ab2[1], a2s + ab2[2], a3 + ab2[3]);
}

// ---------------------------------------------------------------------------
// Masked softmax over nodes per (graph, head)
// ---------------------------------------------------------------------------
__global__ void softmax_kernel(const float* __restrict__ scores,
                               const int* __restrict__ mask,
                               float* __restrict__ w)
{
    const int b = blockIdx.x;
    const int n = threadIdx.x;
    const int idx = b * NNODES + n;
    const float NEG = -INFINITY;
    const float inv_scale = 1.0f / 16.0f;

    float4 s = ((const float4*)scores)[idx];
    const bool valid = mask[idx] != 0;
    float v0 = valid ? s.x * inv_scale : NEG;
    float v1 = valid ? s.y * inv_scale : NEG;
    float v2 = valid ? s.z * inv_scale : NEG;
    float v3 = valid ? s.w * inv_scale : NEG;

    __shared__ float4 red[NNODES];
    red[n] = make_float4(v0, v1, v2, v3);
    __syncthreads();
    for (int off = 128; off > 0; off >>= 1) {
        if (n < off) {
            float4 a = red[n], c = red[n + off];
            red[n] = make_float4(fmaxf(a.x, c.x), fmaxf(a.y, c.y),
                                 fmaxf(a.z, c.z), fmaxf(a.w, c.w));
        }
        __syncthreads();
    }
    float4 mx = red[0];
    __syncthreads();

    float e0 = valid ? __expf(v0 - mx.x) : 0.f;
    float e1 = valid ? __expf(v1 - mx.y) : 0.f;
    float e2 = valid ? __expf(v2 - mx.z) : 0.f;
    float e3 = valid ? __expf(v3 - mx.w) : 0.f;

    red[n] = make_float4(e0, e1, e2, e3);
    __syncthreads();
    for (int off = 128; off > 0; off >>= 1) {
        if (n < off) {
            float4 a = red[n], c = red[n + off];
            red[n] = make_float4(a.x + c.x, a.y + c.y, a.z + c.z, a.w + c.w);
        }
        __syncthreads();
    }
    float4 sm = red[0];
    ((float4*)w)[idx] = make_float4(e0 / sm.x, e1 / sm.y, e2 / sm.z, e3 / sm.w);
}

// ---------------------------------------------------------------------------
// pooled[b,c] = sum_n new_nodes[b,n,c] * w[b,n,c/64]
// ---------------------------------------------------------------------------
__global__ void pool_kernel(const float* __restrict__ newn,
                            const float* __restrict__ w,
                            float* __restrict__ pooled)
{
    const int b = blockIdx.x;
    const int c = threadIdx.x;
    __shared__ float ws[NNODES * NHEADS];
    ((float4*)ws)[c] = ((const float4*)(w + (size_t)b * NNODES * NHEADS))[c];
    __syncthreads();

    const int h = c >> 6;
    const float* base = newn + (size_t)b * NNODES * FOUT + c;
    float acc = 0.f;
    #pragma unroll 8
    for (int n = 0; n < NNODES; n++)
        acc = fmaf(base[(size_t)n * FOUT], ws[n * NHEADS + h], acc);
    pooled[b * FOUT + c] = acc;
}

// ---------------------------------------------------------------------------
// Launch
// ---------------------------------------------------------------------------
extern "C" void kernel_launch(void* const* d_in, const int* in_sizes, int n_in,
                              void* d_out, int out_size)
{
    const float* nodes = (const float*)d_in[0];
    const float* pe    = (const float*)d_in[1];
    const int*   mask  = (const int*)d_in[2];
    const float* globs = (const float*)d_in[3];
    const float* ln_g  = (const float*)d_in[4];
    const float* ln_b  = (const float*)d_in[5];
    const float* fw1   = (const float*)d_in[6];
    const float* fb1   = (const float*)d_in[7];
    const float* fw2   = (const float*)d_in[8];
    const float* fb2   = (const float*)d_in[9];
    const float* aw1   = (const float*)d_in[10];
    const float* ab1   = (const float*)d_in[11];
    const float* aw2   = (const float*)d_in[12];
    const float* ab2   = (const float*)d_in[13];

    float* out_nodes  = (float*)d_out;
    float* out_pooled = out_nodes + (size_t)MROWS * FOUT;

    __half *p_inp, *p_hid, *p_ah, *p_w1t, *p_w2t;
    float  *p_scores, *p_wsm, *p_ctx1;
    cudaGetSymbolAddress((void**)&p_inp,    g_inp);
    cudaGetSymbolAddress((void**)&p_hid,    g_hid);
    cudaGetSymbolAddress((void**)&p_ah,     g_ah);
    cudaGetSymbolAddress((void**)&p_scores, g_scores);
    cudaGetSymbolAddress((void**)&p_wsm,    g_wsm);
    cudaGetSymbolAddress((void**)&p_w1t,    g_w1t);
    cudaGetSymbolAddress((void**)&p_w2t,    g_w2t);
    cudaGetSymbolAddress((void**)&p_ctx1,   g_ctx1);

    cudaFuncSetAttribute(gemm_mma<0>, cudaFuncAttributeMaxDynamicSharedMemorySize, GSMEM);
    cudaFuncSetAttribute(gemm_mma<1>, cudaFuncAttributeMaxDynamicSharedMemorySize, GSMEM);
    cudaFuncSetAttribute(gemm_mma<0>, cudaFuncAttributePreferredSharedMemoryCarveout, 100);
    cudaFuncSetAttribute(gemm_mma<1>, cudaFuncAttributePreferredSharedMemoryCarveout, 100);

    // 1) LN + concat -> g_inp fp16 [M,512]
    prep_kernel<<<MROWS, 128>>>(nodes, pe, ln_g, ln_b, p_inp);

    // 2) per-graph ctx contribution (fp32), weight transposes (fp32->fp16)
    ctx_kernel<<<BATCH, 256>>>(globs, fw1, aw1, p_ctx1);
    wtrans_kernel<<<dim3(40, 16), dim3(32, 8)>>>(fw1, FHID, FHID, aw1, AHID, AHID,
                                                 FEAT_IN, p_w1t);
    wtrans_kernel<<<dim3(8, 32),  dim3(32, 8)>>>(fw2, FOUT, FOUT, nullptr, 0, 0,
                                                 FHID, p_w2t);

    // 3) fused GEMM1: [M,512] @ [512,1280] + ctx -> silu -> g_hid / g_ah (fp16)
    gemm_mma<0><<<dim3(NTOT1 / 256, MROWS / 128), 512, GSMEM>>>(
        p_inp, p_w1t, FEAT_IN, fb1, ab1, p_ctx1, p_hid, p_ah,
        nullptr, nullptr, nullptr);

    // 4) head scores -> softmax weights
    attn2_kernel<<<MROWS / 8, 256>>>(p_ah, aw2, ab2, p_scores);
    softmax_kernel<<<BATCH, NNODES>>>(p_scores, mask, p_wsm);

    // 5) GEMM3: [M,1024] @ [1024,256] + bias + mask + residual -> new_nodes
    gemm_mma<1><<<dim3(FOUT / 256, MROWS / 128), 512, GSMEM>>>(
        p_hid, p_w2t, FHID, fb2, nullptr, nullptr, nullptr, nullptr,
        out_nodes, mask, nodes);

    // 6) attention pooling
    pool_kernel<<<BATCH, 256>>>(out_nodes, p_wsm, out_pooled);
}

// round 10
// speedup vs baseline: 1.0545x; 1.0545x over previous
#include <cuda_runtime.h>
#include <cuda_fp16.h>
#include <math.h>
#include <stdint.h>

// Problem constants
#define BATCH   512
#define NNODES  256
#define MROWS   (BATCH * NNODES)     // 131072
#define FEAT_IN 512
#define GLOB_D  64
#define KIN     576
#define FHID    1024
#define AHID    256
#define FOUT    256
#define NTOT1   (FHID + AHID)        // 1280
#define NHEADS  4
#define LN_EPS  1e-5f

// ---------------------------------------------------------------------------
// Scratch (device globals; no runtime allocation)
// ---------------------------------------------------------------------------
__device__ __half g_inp[(size_t)MROWS * FEAT_IN];      // fp16 LN output [M,512]
__device__ __half g_hid[(size_t)MROWS * FHID];         // fp16 silu hidden [M,1024]
__device__ __half g_ah [(size_t)MROWS * AHID];         // fp16 attn hidden [M,256]
__device__ float  g_scores[(size_t)MROWS * NHEADS];
__device__ float  g_wsm   [(size_t)MROWS * NHEADS];
__device__ __half g_w1t[(size_t)NTOT1 * FEAT_IN];      // [1280,512] (fw1||aw1)^T fp16
__device__ __half g_w2t[(size_t)FOUT * FHID];          // [256,1024] fw2^T fp16
__device__ float  g_ctx1[(size_t)BATCH * NTOT1];       // per-graph ctx contribution

// ---------------------------------------------------------------------------
// PTX helpers (baseline ISA: works at compute_103 target)
// ---------------------------------------------------------------------------
__device__ __forceinline__ uint32_t smem_u32(const void* p) {
    uint32_t a;
    asm("{ .reg .u64 t; cvta.to.shared.u64 t, %1; cvt.u32.u64 %0, t; }"
        : "=r"(a) : "l"(p));
    return a;
}

#define CP_ASYNC16(dst, src) \
    asm volatile("cp.async.cg.shared.global [%0], [%1], 16;" \
        :: "r"(dst), "l"(src))
#define CP_COMMIT()  asm volatile("cp.async.commit_group;" ::: "memory")
#define CP_WAIT1()   asm volatile("cp.async.wait_group 1;" ::: "memory")

#define GROUP_BAR(id) \
    asm volatile("bar.sync %0, 256;" :: "r"(id) : "memory")

#define LDSM_X4(r0, r1, r2, r3, addr) \
    asm volatile("ldmatrix.sync.aligned.m8n8.x4.shared.b16 {%0,%1,%2,%3}, [%4];" \
        : "=r"(r0), "=r"(r1), "=r"(r2), "=r"(r3) : "r"(addr))

#define MMA16816(c, a, b) \
    asm volatile("mma.sync.aligned.m16n8k16.row.col.f32.f16.f16.f32 " \
        "{%0,%1,%2,%3}, {%4,%5,%6,%7}, {%8,%9}, {%0,%1,%2,%3};" \
        : "+f"((c)[0]), "+f"((c)[1]), "+f"((c)[2]), "+f"((c)[3]) \
        : "r"((a)[0]), "r"((a)[1]), "r"((a)[2]), "r"((a)[3]), \
          "r"((b)[0]), "r"((b)[1]))

__device__ __forceinline__ float warp_sum(float v) {
    #pragma unroll
    for (int o = 16; o > 0; o >>= 1) v += __shfl_xor_sync(0xffffffffu, v, o);
    return v;
}

__device__ __forceinline__ float silu(float v) {
    return __fdividef(v, 1.0f + __expf(-v));
}

// ---------------------------------------------------------------------------
// Kernel 1: LayerNorm(concat(nodes, pe)) -> g_inp fp16 [M,512]
// ---------------------------------------------------------------------------
__global__ void prep_kernel(const float* __restrict__ nodes,
                            const float* __restrict__ pe,
                            const float* __restrict__ ln_g,
                            const float* __restrict__ ln_b,
                            __half* __restrict__ inp)
{
    const int row = blockIdx.x;
    const int t   = threadIdx.x;          // 0..127

    float4 v = (t < 64)
        ? ((const float4*)nodes)[(size_t)row * 64 + t]
        : ((const float4*)pe)   [(size_t)row * 64 + (t - 64)];

    float s  = v.x + v.y + v.z + v.w;
    float sq = v.x*v.x + v.y*v.y + v.z*v.z + v.w*v.w;

    __shared__ float ssum[4], ssq[4];
    __shared__ float s_mu, s_rstd;
    const int lane = t & 31, wid = t >> 5;
    float ws = warp_sum(s), wq = warp_sum(sq);
    if (lane == 0) { ssum[wid] = ws; ssq[wid] = wq; }
    __syncthreads();
    if (t == 0) {
        float S = ssum[0] + ssum[1] + ssum[2] + ssum[3];
        float Q = ssq[0]  + ssq[1]  + ssq[2]  + ssq[3];
        float mu  = S * (1.0f / FEAT_IN);
        float var = Q * (1.0f / FEAT_IN) - mu * mu;
        s_mu = mu; s_rstd = rsqrtf(var + LN_EPS);
    }
    __syncthreads();
    const float mu = s_mu, rstd = s_rstd;

    float4 g4 = ((const float4*)ln_g)[t];
    float4 b4 = ((const float4*)ln_b)[t];
    float o0 = (v.x - mu) * rstd * g4.x + b4.x;
    float o1 = (v.y - mu) * rstd * g4.y + b4.y;
    float o2 = (v.z - mu) * rstd * g4.z + b4.z;
    float o3 = (v.w - mu) * rstd * g4.w + b4.w;

    __half* dst = inp + (size_t)row * FEAT_IN + t * 4;
    *(__half2*)(dst)     = __floats2half2_rn(o0, o1);
    *(__half2*)(dst + 2) = __floats2half2_rn(o2, o3);
}

// ---------------------------------------------------------------------------
// Per-graph ctx contribution: ctx1[b,n] = sum_j globs[b,j] * W[512+j, n]
// ---------------------------------------------------------------------------
__global__ void ctx_kernel(const float* __restrict__ globs,
                           const float* __restrict__ fw1,
                           const float* __restrict__ aw1,
                           float* __restrict__ ctx1)
{
    __shared__ float gs[GLOB_D];
    const int b = blockIdx.x;
    if (threadIdx.x < GLOB_D) gs[threadIdx.x] = globs[b * GLOB_D + threadIdx.x];
    __syncthreads();
    for (int n = threadIdx.x; n < NTOT1; n += blockDim.x) {
        float acc = 0.f;
        if (n < FHID) {
            #pragma unroll 8
            for (int j = 0; j < GLOB_D; j++)
                acc = fmaf(gs[j], fw1[(size_t)(FEAT_IN + j) * FHID + n], acc);
        } else {
            #pragma unroll 8
            for (int j = 0; j < GLOB_D; j++)
                acc = fmaf(gs[j], aw1[(size_t)(FEAT_IN + j) * AHID + (n - FHID)], acc);
        }
        ctx1[(size_t)b * NTOT1 + n] = acc;
    }
}

// ---------------------------------------------------------------------------
// Weight transpose + fp16 cast
// ---------------------------------------------------------------------------
__global__ void wtrans_kernel(const float* __restrict__ W1, int N1, int ld1,
                              const float* __restrict__ W2, int N2, int ld2,
                              int K, __half* __restrict__ Wt)
{
    __shared__ float tile[32][33];
    const int nb = blockIdx.x * 32, kb = blockIdx.y * 32;
    const int tx = threadIdx.x, ty = threadIdx.y;
    const int Ntot = N1 + N2;
    for (int i = ty; i < 32; i += 8) {
        int k = kb + i, n = nb + tx;
        float v = 0.f;
        if (k < K && n < Ntot)
            v = (n < N1) ? W1[(size_t)k * ld1 + n] : W2[(size_t)k * ld2 + (n - N1)];
        tile[i][tx] = v;
    }
    __syncthreads();
    for (int i = ty; i < 32; i += 8) {
        int n = nb + i, k = kb + tx;
        if (n < Ntot && k < K)
            Wt[(size_t)n * K + k] = __float2half_rn(tile[tx][i]);
    }
}

// ---------------------------------------------------------------------------
// HGEMM via mma.sync m16n8k16: C[M,N] = A[M,K] @ Bt[N,K]^T (+epilogue)
// 512 threads = TWO independent 8-warp groups, each running its own
// 128x128 tile (group g covers cols col0 + g*128) with its own 3-stage
// cp.async pipeline and its own named barrier (bar.sync 1/2, 256).
// No block-wide __syncthreads in the mainloop -> two independent
// instruction streams per SM, occupancy by construction.
// Smem row stride 40 halfs (80B) -> conflict-free ldmatrix.
// MODE 0 (GEMM1): silu(x + bias + ctx); ncol<1024 -> fp16 outh; else fp16 outa.
// MODE 1 (GEMM3): x + bias1, zero-if-!mask, +residual -> fp32 outf.
// ---------------------------------------------------------------------------
#define NSTAGE    3
#define GSTAGE_B  20480                      // (128*40*2) * 2 tiles (A+B)
#define GRP_BYTES (NSTAGE * GSTAGE_B)        // 61440 per group
#define GSMEM     (2 * GRP_BYTES)            // 122880 per block

template<int MODE>
__global__ __launch_bounds__(512, 1) void gemm_mma(
    const __half* __restrict__ A, const __half* __restrict__ Bt, int K,
    const float* __restrict__ bias1, const float* __restrict__ bias2,
    const float* __restrict__ ctx1,
    __half* __restrict__ outh, __half* __restrict__ outa,
    float* __restrict__ outf,
    const int* __restrict__ mask, const float* __restrict__ residual)
{
    extern __shared__ char smem[];
    const int tid    = threadIdx.x;
    const int wid    = tid >> 5;
    const int lane   = tid & 31;
    const int grp    = wid >> 3;             // 0 or 1
    const int gwid   = wid & 7;              // warp within group
    const int gtid   = tid & 255;            // thread within group
    const int warp_m = gwid & 3;             // 4 groups of 32 rows
    const int warp_n = gwid >> 2;            // 2 groups of 64 cols
    const int row0   = blockIdx.y * 128;
    const int col0   = blockIdx.x * 256 + grp * 128;
    const int iters  = K >> 5;
    const int barid  = grp + 1;

    const uint32_t gbase = smem_u32(smem) + grp * GRP_BYTES;

    // cp.async mapping (256 thr/group, K-tile = 32 halfs = 4 x 16B chunks):
    const int ldr = gtid >> 2;               // 0..63 (rows, +64 for i=1)
    const int kc  = (gtid & 3) * 8;          // k-offset in halfs

    float acc[2][8][4];
    #pragma unroll
    for (int mt = 0; mt < 2; mt++)
        #pragma unroll
        for (int nt = 0; nt < 8; nt++)
            #pragma unroll
            for (int j = 0; j < 4; j++) acc[mt][nt][j] = 0.f;

    // ldmatrix lane-derived offsets
    const int lm = lane & 15, lq = lane >> 4;
    const uint32_t aoff = ((warp_m * 32 + lm) * 40 + lq * 8) * 2;
    const int bn = (lane >> 4) * 8 + (lane & 7);
    const int bk = ((lane >> 3) & 1) * 8;
    const uint32_t boff = ((warp_n * 64 + bn) * 40 + bk) * 2;

    auto load_stage = [&](int s, int kk) {
        const uint32_t dA = gbase + s * GSTAGE_B;
        const uint32_t dB = dA + 10240;
        #pragma unroll
        for (int i = 0; i < 2; i++) {
            const int r = ldr + i * 64;
            const uint32_t soff = (r * 40 + kc) * 2;
            CP_ASYNC16(dA + soff, &A [(size_t)(row0 + r) * K + kk + kc]);
            CP_ASYNC16(dB + soff, &Bt[(size_t)(col0 + r) * K + kk + kc]);
        }
    };

    load_stage(0, 0);  CP_COMMIT();
    load_stage(1, 32); CP_COMMIT();

    for (int i = 0; i < iters; i++) {
        CP_WAIT1();
        GROUP_BAR(barid);
        if (i + 2 < iters) load_stage((i + 2) % NSTAGE, (i + 2) * 32);
        CP_COMMIT();

        const int s = i % NSTAGE;
        const uint32_t sA = gbase + s * GSTAGE_B;
        const uint32_t sB = sA + 10240;

        #pragma unroll
        for (int ks = 0; ks < 2; ks++) {
            uint32_t a[2][4];
            #pragma unroll
            for (int mt = 0; mt < 2; mt++)
                LDSM_X4(a[mt][0], a[mt][1], a[mt][2], a[mt][3],
                        sA + aoff + mt * 1280 + ks * 32);
            uint32_t b[8][2];
            #pragma unroll
            for (int np = 0; np < 4; np++) {
                uint32_t r0, r1, r2, r3;
                LDSM_X4(r0, r1, r2, r3, sB + boff + np * 1280 + ks * 32);
                b[np * 2][0]     = r0; b[np * 2][1]     = r1;
                b[np * 2 + 1][0] = r2; b[np * 2 + 1][1] = r3;
            }
            #pragma unroll
            for (int mt = 0; mt < 2; mt++)
                #pragma unroll
                for (int nt = 0; nt < 8; nt++)
                    MMA16816(acc[mt][nt], a[mt], b[nt]);
        }
        // top-of-loop group barrier (after wait) protects stage reuse
    }

    // ---------------- epilogue ----------------
    const int mrow0 = row0 + warp_m * 32 + (lane >> 2);
    const int ncb   = col0 + warp_n * 64 + (lane & 3) * 2;

    #pragma unroll
    for (int mt = 0; mt < 2; mt++) {
        #pragma unroll
        for (int half = 0; half < 2; half++) {     // row, row+8
            const int r = mrow0 + mt * 16 + half * 8;
            const int bg = r >> 8;                 // graph index
            int mv = 1;
            if (MODE == 1) mv = mask[r];
            #pragma unroll
            for (int nt = 0; nt < 8; nt++) {
                const int ncol = ncb + nt * 8;
                float v0 = acc[mt][nt][half * 2];
                float v1 = acc[mt][nt][half * 2 + 1];
                if (MODE == 0) {
                    const float c0 = ctx1[(size_t)bg * NTOT1 + ncol];
                    const float c1 = ctx1[(size_t)bg * NTOT1 + ncol + 1];
                    if (ncol < FHID) {
                        v0 = silu(v0 + bias1[ncol]     + c0);
                        v1 = silu(v1 + bias1[ncol + 1] + c1);
                        *(__half2*)&outh[(size_t)r * FHID + ncol] =
                            __floats2half2_rn(v0, v1);
                    } else {
                        const int a0 = ncol - FHID;
                        v0 = silu(v0 + bias2[a0]     + c0);
                        v1 = silu(v1 + bias2[a0 + 1] + c1);
                        *(__half2*)&outa[(size_t)r * AHID + a0] =
                            __floats2half2_rn(v0, v1);
                    }
                } else {
                    v0 += bias1[ncol];
                    v1 += bias1[ncol + 1];
                    if (!mv) { v0 = 0.f; v1 = 0.f; }
                    float2 o;
                    o.x = v0 + residual[(size_t)r * FOUT + ncol];
                    o.y = v1 + residual[(size_t)r * FOUT + ncol + 1];
                    *(float2*)&outf[(size_t)r * FOUT + ncol] = o;
                }
            }
        }
    }
}

// ---------------------------------------------------------------------------
// scores[M,4] = g_ah[M,256] @ aw2[256,4] + ab2  (one warp per row, fp16 in)
// ---------------------------------------------------------------------------
__global__ void attn2_kernel(const __half* __restrict__ ah,
                             const float* __restrict__ aw2,
                             const float* __restrict__ ab2,
                             float* __restrict__ scores)
{
    const int warp = (blockIdx.x * blockDim.x + threadIdx.x) >> 5;
    const int lane = threadIdx.x & 31;
    if (warp >= MROWS) return;
    const __half2* a2 = (const __half2*)(ah + (size_t)warp * AHID);
    float a0 = 0.f, a1 = 0.f, a2s = 0.f, a3 = 0.f;
    #pragma unroll
    for (int i = 0; i < 4; i++) {
        const int k2 = i * 32 + lane;      // half2 index (k = 2*k2, 2*k2+1)
        __half2 h = a2[k2];
        float f0 = __low2float(h), f1 = __high2float(h);
        float4 w0 = ((const float4*)aw2)[2 * k2];
        float4 w1 = ((const float4*)aw2)[2 * k2 + 1];
        a0  = fmaf(f0, w0.x, fmaf(f1, w1.x, a0));
        a1  = fmaf(f0, w0.y, fmaf(f1, w1.y, a1));
        a2s = fmaf(f0, w0.z, fmaf(f1, w1.z, a2s));
        a3  = fmaf(f0, w0.w, fmaf(f1, w1.w, a3));
    }
    a0 = warp_sum(a0); a1 = warp_sum(a1); a2s = warp_sum(a2s); a3 = warp_sum(a3);
    if (lane == 0)
        ((float4*)scores)[warp] =
            make_float4(a0 + ab2[0], a1 + ab2[1], a2s + ab2[2], a3 + ab2[3]);
}

// ---------------------------------------------------------------------------
// Masked softmax over nodes per (graph, head)
// ---------------------------------------------------------------------------
__global__ void softmax_kernel(const float* __restrict__ scores,
                               const int* __restrict__ mask,
                               float* __restrict__ w)
{
    const int b = blockIdx.x;
    const int n = threadIdx.x;
    const int idx = b * NNODES + n;
    const float NEG = -INFINITY;
    const float inv_scale = 1.0f / 16.0f;

    float4 s = ((const float4*)scores)[idx];
    const bool valid = mask[idx] != 0;
    float v0 = valid ? s.x * inv_scale : NEG;
    float v1 = valid ? s.y * inv_scale : NEG;
    float v2 = valid ? s.z * inv_scale : NEG;
    float v3 = valid ? s.w * inv_scale : NEG;

    __shared__ float4 red[NNODES];
    red[n] = make_float4(v0, v1, v2, v3);
    __syncthreads();
    for (int off = 128; off > 0; off >>= 1) {
        if (n < off) {
            float4 a = red[n], c = red[n + off];
            red[n] = make_float4(fmaxf(a.x, c.x), fmaxf(a.y, c.y),
                                 fmaxf(a.z, c.z), fmaxf(a.w, c.w));
        }
        __syncthreads();
    }
    float4 mx = red[0];
    __syncthreads();

    float e0 = valid ? __expf(v0 - mx.x) : 0.f;
    float e1 = valid ? __expf(v1 - mx.y) : 0.f;
    float e2 = valid ? __expf(v2 - mx.z) : 0.f;
    float e3 = valid ? __expf(v3 - mx.w) : 0.f;

    red[n] = make_float4(e0, e1, e2, e3);
    __syncthreads();
    for (int off = 128; off > 0; off >>= 1) {
        if (n < off) {
            float4 a = red[n], c = red[n + off];
            red[n] = make_float4(a.x + c.x, a.y + c.y, a.z + c.z, a.w + c.w);
        }
        __syncthreads();
    }
    float4 sm = red[0];
    ((float4*)w)[idx] = make_float4(e0 / sm.x, e1 / sm.y, e2 / sm.z, e3 / sm.w);
}

// ---------------------------------------------------------------------------
// pooled[b,c] = sum_n new_nodes[b,n,c] * w[b,n,c/64]
// ---------------------------------------------------------------------------
__global__ void pool_kernel(const float* __restrict__ newn,
                            const float* __restrict__ w,
                            float* __restrict__ pooled)
{
    const int b = blockIdx.x;
    const int c = threadIdx.x;
    __shared__ float ws[NNODES * NHEADS];
    ((float4*)ws)[c] = ((const float4*)(w + (size_t)b * NNODES * NHEADS))[c];
    __syncthreads();

    const int h = c >> 6;
    const float* base = newn + (size_t)b * NNODES * FOUT + c;
    float acc = 0.f;
    #pragma unroll 8
    for (int n = 0; n < NNODES; n++)
        acc = fmaf(base[(size_t)n * FOUT], ws[n * NHEADS + h], acc);
    pooled[b * FOUT + c] = acc;
}

// ---------------------------------------------------------------------------
// Launch
// ---------------------------------------------------------------------------
extern "C" void kernel_launch(void* const* d_in, const int* in_sizes, int n_in,
                              void* d_out, int out_size)
{
    const float* nodes = (const float*)d_in[0];
    const float* pe    = (const float*)d_in[1];
    const int*   mask  = (const int*)d_in[2];
    const float* globs = (const float*)d_in[3];
    const float* ln_g  = (const float*)d_in[4];
    const float* ln_b  = (const float*)d_in[5];
    const float* fw1   = (const float*)d_in[6];
    const float* fb1   = (const float*)d_in[7];
    const float* fw2   = (const float*)d_in[8];
    const float* fb2   = (const float*)d_in[9];
    const float* aw1   = (const float*)d_in[10];
    const float* ab1   = (const float*)d_in[11];
    const float* aw2   = (const float*)d_in[12];
    const float* ab2   = (const float*)d_in[13];

    float* out_nodes  = (float*)d_out;
    float* out_pooled = out_nodes + (size_t)MROWS * FOUT;

    __half *p_inp, *p_hid, *p_ah, *p_w1t, *p_w2t;
    float  *p_scores, *p_wsm, *p_ctx1;
    cudaGetSymbolAddress((void**)&p_inp,    g_inp);
    cudaGetSymbolAddress((void**)&p_hid,    g_hid);
    cudaGetSymbolAddress((void**)&p_ah,     g_ah);
    cudaGetSymbolAddress((void**)&p_scores, g_scores);
    cudaGetSymbolAddress((void**)&p_wsm,    g_wsm);
    cudaGetSymbolAddress((void**)&p_w1t,    g_w1t);
    cudaGetSymbolAddress((void**)&p_w2t,    g_w2t);
    cudaGetSymbolAddress((void**)&p_ctx1,   g_ctx1);

    cudaFuncSetAttribute(gemm_mma<0>, cudaFuncAttributeMaxDynamicSharedMemorySize, GSMEM);
    cudaFuncSetAttribute(gemm_mma<1>, cudaFuncAttributeMaxDynamicSharedMemorySize, GSMEM);
    cudaFuncSetAttribute(gemm_mma<0>, cudaFuncAttributePreferredSharedMemoryCarveout, 100);
    cudaFuncSetAttribute(gemm_mma<1>, cudaFuncAttributePreferredSharedMemoryCarveout, 100);

    // 1) LN + concat -> g_inp fp16 [M,512]
    prep_kernel<<<MROWS, 128>>>(nodes, pe, ln_g, ln_b, p_inp);

    // 2) per-graph ctx contribution (fp32), weight transposes (fp32->fp16)
    ctx_kernel<<<BATCH, 256>>>(globs, fw1, aw1, p_ctx1);
    wtrans_kernel<<<dim3(40, 16), dim3(32, 8)>>>(fw1, FHID, FHID, aw1, AHID, AHID,
                                                 FEAT_IN, p_w1t);
    wtrans_kernel<<<dim3(8, 32),  dim3(32, 8)>>>(fw2, FOUT, FOUT, nullptr, 0, 0,
                                                 FHID, p_w2t);

    // 3) fused GEMM1: [M,512] @ [512,1280] + ctx -> silu -> g_hid / g_ah (fp16)
    //    each CTA covers 256 cols via two independent 128-col warp groups
    gemm_mma<0><<<dim3(NTOT1 / 256, MROWS / 128), 512, GSMEM>>>(
        p_inp, p_w1t, FEAT_IN, fb1, ab1, p_ctx1, p_hid, p_ah,
        nullptr, nullptr, nullptr);

    // 4) head scores -> softmax weights
    attn2_kernel<<<MROWS / 8, 256>>>(p_ah, aw2, ab2, p_scores);
    softmax_kernel<<<BATCH, NNODES>>>(p_scores, mask, p_wsm);

    // 5) GEMM3: [M,1024] @ [1024,256] + bias + mask + residual -> new_nodes
    gemm_mma<1><<<dim3(FOUT / 256, MROWS / 128), 512, GSMEM>>>(
        p_hid, p_w2t, FHID, fb2, nullptr, nullptr, nullptr, nullptr,
        out_nodes, mask, nodes);

    // 6) attention pooling
    pool_kernel<<<BATCH, 256>>>(out_nodes, p_wsm, out_pooled);
}

// round 11
// speedup vs baseline: 1.8097x; 1.7162x over previous
#include <cuda_runtime.h>
#include <cuda_fp16.h>
#include <math.h>
#include <stdint.h>

// Problem constants
#define BATCH   512
#define NNODES  256
#define MROWS   (BATCH * NNODES)     // 131072
#define FEAT_IN 512
#define GLOB_D  64
#define FHID    1024
#define AHID    256
#define FOUT    256
#define NTOT1   (FHID + AHID)        // 1280
#define NHEADS  4
#define LN_EPS  1e-5f

// ---------------------------------------------------------------------------
// Scratch (device globals; no runtime allocation)
// ---------------------------------------------------------------------------
__device__ __half g_inp[(size_t)MROWS * FEAT_IN];      // fp16 LN output [M,512]
__device__ __half g_hid[(size_t)MROWS * FHID];         // fp16 silu hidden (COMPACT rows)
__device__ __half g_ah [(size_t)MROWS * AHID];         // fp16 attn hidden (COMPACT rows)
__device__ float  g_scores[(size_t)MROWS * NHEADS];
__device__ float  g_wsm   [(size_t)MROWS * NHEADS];
__device__ __half g_w1t[(size_t)NTOT1 * FEAT_IN];      // [1280,512] (fw1||aw1)^T fp16
__device__ __half g_w2t[(size_t)FOUT * FHID];          // [256,1024] fw2^T fp16
__device__ float  g_ctx1[(size_t)BATCH * NTOT1];       // per-graph ctx contribution
__device__ int    g_rowidx[MROWS];                     // compact -> original row
__device__ int    g_bcnt[512];
__device__ int    g_boff[512];
__device__ int    g_meta[2];                           // [0]=total valid, [1]=padded

// ---------------------------------------------------------------------------
// PTX helpers (baseline ISA: works at compute_103 target)
// ---------------------------------------------------------------------------
__device__ __forceinline__ uint32_t smem_u32(const void* p) {
    uint32_t a;
    asm("{ .reg .u64 t; cvta.to.shared.u64 t, %1; cvt.u32.u64 %0, t; }"
        : "=r"(a) : "l"(p));
    return a;
}

#define CP_ASYNC16(dst, src) \
    asm volatile("cp.async.cg.shared.global [%0], [%1], 16;" \
        :: "r"(dst), "l"(src))
#define CP_COMMIT()  asm volatile("cp.async.commit_group;" ::: "memory")
#define CP_WAIT2()   asm volatile("cp.async.wait_group 2;" ::: "memory")

#define LDSM_X4(r0, r1, r2, r3, addr) \
    asm volatile("ldmatrix.sync.aligned.m8n8.x4.shared.b16 {%0,%1,%2,%3}, [%4];" \
        : "=r"(r0), "=r"(r1), "=r"(r2), "=r"(r3) : "r"(addr))

#define MMA16816(c, a, b) \
    asm volatile("mma.sync.aligned.m16n8k16.row.col.f32.f16.f16.f32 " \
        "{%0,%1,%2,%3}, {%4,%5,%6,%7}, {%8,%9}, {%0,%1,%2,%3};" \
        : "+f"((c)[0]), "+f"((c)[1]), "+f"((c)[2]), "+f"((c)[3]) \
        : "r"((a)[0]), "r"((a)[1]), "r"((a)[2]), "r"((a)[3]), \
          "r"((b)[0]), "r"((b)[1]))

__device__ __forceinline__ float warp_sum(float v) {
    #pragma unroll
    for (int o = 16; o > 0; o >>= 1) v += __shfl_xor_sync(0xffffffffu, v, o);
    return v;
}

__device__ __forceinline__ float silu(float v) {
    return __fdividef(v, 1.0f + __expf(-v));
}

// ---------------------------------------------------------------------------
// Compaction: count -> scan -> scatter -> pad
// ---------------------------------------------------------------------------
__global__ void count_kernel(const int* __restrict__ mask)
{
    const int t = threadIdx.x, lane = t & 31, wid = t >> 5;
    const int r = blockIdx.x * 256 + t;
    __shared__ int ws[8];
    unsigned bal = __ballot_sync(0xffffffffu, mask[r] != 0);
    if (lane == 0) ws[wid] = __popc(bal);
    __syncthreads();
    if (t == 0) {
        int s = 0;
        #pragma unroll
        for (int i = 0; i < 8; i++) s += ws[i];
        g_bcnt[blockIdx.x] = s;
    }
}

__global__ void scan_kernel()
{
    __shared__ int s[512];
    const int t = threadIdx.x;
    const int c = g_bcnt[t];
    s[t] = c;
    __syncthreads();
    for (int off = 1; off < 512; off <<= 1) {
        int v = (t >= off) ? s[t - off] : 0;
        __syncthreads();
        s[t] += v;
        __syncthreads();
    }
    g_boff[t] = s[t] - c;
    if (t == 511) {
        g_meta[0] = s[511];
        g_meta[1] = ((s[511] + 127) >> 7) << 7;
    }
}

__global__ void scatter_kernel(const int* __restrict__ mask)
{
    const int t = threadIdx.x, lane = t & 31, wid = t >> 5;
    const int r = blockIdx.x * 256 + t;
    __shared__ int ws[8];
    const int v = mask[r] != 0;
    unsigned bal = __ballot_sync(0xffffffffu, v);
    if (lane == 0) ws[wid] = __popc(bal);
    __syncthreads();
    int wpre = 0;
    #pragma unroll
    for (int i = 0; i < 8; i++) if (i < wid) wpre += ws[i];
    if (v) {
        int pos = g_boff[blockIdx.x] + wpre + __popc(bal & ((1u << lane) - 1));
        g_rowidx[pos] = r;
    }
}

__global__ void pad_kernel()
{
    const int total = g_meta[0], npad = g_meta[1];
    for (int i = total + (int)threadIdx.x; i < npad; i += 256)
        g_rowidx[i] = 0;   // row 0 always valid; stores for pads are predicated off
}

// ---------------------------------------------------------------------------
// Kernel: LayerNorm(concat(nodes, pe)) -> g_inp fp16 [M,512]
// ---------------------------------------------------------------------------
__global__ void prep_kernel(const float* __restrict__ nodes,
                            const float* __restrict__ pe,
                            const float* __restrict__ ln_g,
                            const float* __restrict__ ln_b,
                            __half* __restrict__ inp)
{
    const int row = blockIdx.x;
    const int t   = threadIdx.x;          // 0..127

    float4 v = (t < 64)
        ? ((const float4*)nodes)[(size_t)row * 64 + t]
        : ((const float4*)pe)   [(size_t)row * 64 + (t - 64)];

    float s  = v.x + v.y + v.z + v.w;
    float sq = v.x*v.x + v.y*v.y + v.z*v.z + v.w*v.w;

    __shared__ float ssum[4], ssq[4];
    __shared__ float s_mu, s_rstd;
    const int lane = t & 31, wid = t >> 5;
    float ws = warp_sum(s), wq = warp_sum(sq);
    if (lane == 0) { ssum[wid] = ws; ssq[wid] = wq; }
    __syncthreads();
    if (t == 0) {
        float S = ssum[0] + ssum[1] + ssum[2] + ssum[3];
        float Q = ssq[0]  + ssq[1]  + ssq[2]  + ssq[3];
        float mu  = S * (1.0f / FEAT_IN);
        float var = Q * (1.0f / FEAT_IN) - mu * mu;
        s_mu = mu; s_rstd = rsqrtf(var + LN_EPS);
    }
    __syncthreads();
    const float mu = s_mu, rstd = s_rstd;

    float4 g4 = ((const float4*)ln_g)[t];
    float4 b4 = ((const float4*)ln_b)[t];
    float o0 = (v.x - mu) * rstd * g4.x + b4.x;
    float o1 = (v.y - mu) * rstd * g4.y + b4.y;
    float o2 = (v.z - mu) * rstd * g4.z + b4.z;
    float o3 = (v.w - mu) * rstd * g4.w + b4.w;

    __half* dst = inp + (size_t)row * FEAT_IN + t * 4;
    *(__half2*)(dst)     = __floats2half2_rn(o0, o1);
    *(__half2*)(dst + 2) = __floats2half2_rn(o2, o3);
}

// ---------------------------------------------------------------------------
// Per-graph ctx contribution: ctx1[b,n] = sum_j globs[b,j] * W[512+j, n]
// ---------------------------------------------------------------------------
__global__ void ctx_kernel(const float* __restrict__ globs,
                           const float* __restrict__ fw1,
                           const float* __restrict__ aw1,
                           float* __restrict__ ctx1)
{
    __shared__ float gs[GLOB_D];
    const int b = blockIdx.x;
    if (threadIdx.x < GLOB_D) gs[threadIdx.x] = globs[b * GLOB_D + threadIdx.x];
    __syncthreads();
    for (int n = threadIdx.x; n < NTOT1; n += blockDim.x) {
        float acc = 0.f;
        if (n < FHID) {
            #pragma unroll 8
            for (int j = 0; j < GLOB_D; j++)
                acc = fmaf(gs[j], fw1[(size_t)(FEAT_IN + j) * FHID + n], acc);
        } else {
            #pragma unroll 8
            for (int j = 0; j < GLOB_D; j++)
                acc = fmaf(gs[j], aw1[(size_t)(FEAT_IN + j) * AHID + (n - FHID)], acc);
        }
        ctx1[(size_t)b * NTOT1 + n] = acc;
    }
}

// ---------------------------------------------------------------------------
// Weight transpose + fp16 cast
// ---------------------------------------------------------------------------
__global__ void wtrans_kernel(const float* __restrict__ W1, int N1, int ld1,
                              const float* __restrict__ W2, int N2, int ld2,
                              int K, __half* __restrict__ Wt)
{
    __shared__ float tile[32][33];
    const int nb = blockIdx.x * 32, kb = blockIdx.y * 32;
    const int tx = threadIdx.x, ty = threadIdx.y;
    const int Ntot = N1 + N2;
    for (int i = ty; i < 32; i += 8) {
        int k = kb + i, n = nb + tx;
        float v = 0.f;
        if (k < K && n < Ntot)
            v = (n < N1) ? W1[(size_t)k * ld1 + n] : W2[(size_t)k * ld2 + (n - N1)];
        tile[i][tx] = v;
    }
    __syncthreads();
    for (int i = ty; i < 32; i += 8) {
        int n = nb + i, k = kb + tx;
        if (n < Ntot && k < K)
            Wt[(size_t)n * K + k] = __float2half_rn(tile[tx][i]);
    }
}

// ---------------------------------------------------------------------------
// HGEMM via mma.sync m16n8k16 over COMPACTED valid rows.
// CTA tile 128x128, BK=32, 4-stage cp.async pipeline, 8 warps (4m x 2n),
// warp tile 32x64, smem stride 40 halfs. (R7 config = best measured.)
// MODE 0 (GEMM1): A rows gathered via rowidx from full g_inp;
//                 silu(x+bias+ctx) -> dense compact outh / outa (fp16).
// MODE 1 (GEMM3): A dense compact (g_hid); x+bias1+residual[orig] -> outf[orig].
// Grid rows worst-case (MROWS/128); blocks beyond padded count exit.
// Epilogue stores predicated on compact row < total.
// ---------------------------------------------------------------------------
#define NSTAGE    4
#define GSTAGE_B  20480               // (128*40*2) * 2 tiles
#define GSMEM     (NSTAGE * GSTAGE_B) // 81920

template<int MODE>
__global__ __launch_bounds__(256, 2) void gemm_mma(
    const __half* __restrict__ A, const __half* __restrict__ Bt, int K,
    const float* __restrict__ bias1, const float* __restrict__ bias2,
    const float* __restrict__ ctx1,
    __half* __restrict__ outh, __half* __restrict__ outa,
    float* __restrict__ outf,
    const float* __restrict__ residual)
{
    const int total = g_meta[0];
    const int npad  = g_meta[1];
    const int row0  = blockIdx.y * 128;
    if (row0 >= npad) return;

    extern __shared__ char smem[];
    const uint32_t sbase = smem_u32(smem);
    const int tid    = threadIdx.x;
    const int wid    = tid >> 5;
    const int lane   = tid & 31;
    const int warp_m = wid & 3;
    const int warp_n = wid >> 2;
    const int col0   = blockIdx.x * 128;
    const int iters  = K >> 5;

    // cp.async mapping: 16B chunks; A,B each 512 slots -> 2 per thread
    const int ldr = tid >> 2;              // 0..63 (rows; +64 for i=1)
    const int ldk = (tid & 3) * 8;         // k-offset in halfs

    // A row base pointers (gather for MODE 0, dense for MODE 1)
    const __half* Arow[2];
    #pragma unroll
    for (int i = 0; i < 2; i++) {
        const int rc = row0 + ldr + i * 64;
        const int src = (MODE == 0) ? g_rowidx[rc] : rc;
        Arow[i] = A + (size_t)src * K;
    }

    float acc[2][8][4];
    #pragma unroll
    for (int mt = 0; mt < 2; mt++)
        #pragma unroll
        for (int nt = 0; nt < 8; nt++)
            #pragma unroll
            for (int j = 0; j < 4; j++) acc[mt][nt][j] = 0.f;

    // ldmatrix lane-derived offsets
    const int lm = lane & 15, lq = lane >> 4;
    const uint32_t aoff = ((warp_m * 32 + lm) * 40 + lq * 8) * 2;
    const int bn = (lane >> 4) * 8 + (lane & 7);
    const int bk = ((lane >> 3) & 1) * 8;
    const uint32_t boff = ((warp_n * 64 + bn) * 40 + bk) * 2;

    auto load_stage = [&](int s, int kk) {
        const uint32_t dA = sbase + s * GSTAGE_B;
        const uint32_t dB = dA + 10240;
        #pragma unroll
        for (int i = 0; i < 2; i++) {
            const int r = ldr + i * 64;
            const uint32_t soff = (r * 40 + ldk) * 2;
            CP_ASYNC16(dA + soff, Arow[i] + kk + ldk);
            CP_ASYNC16(dB + soff, &Bt[(size_t)(col0 + r) * K + kk + ldk]);
        }
    };

    load_stage(0, 0);  CP_COMMIT();
    load_stage(1, 32); CP_COMMIT();
    load_stage(2, 64); CP_COMMIT();

    for (int i = 0; i < iters; i++) {
        CP_WAIT2();
        __syncthreads();
        if (i + 3 < iters) load_stage((i + 3) % NSTAGE, (i + 3) * 32);
        CP_COMMIT();

        const int s = i % NSTAGE;
        const uint32_t sA = sbase + s * GSTAGE_B;
        const uint32_t sB = sA + 10240;

        #pragma unroll
        for (int ks = 0; ks < 2; ks++) {
            uint32_t a[2][4];
            #pragma unroll
            for (int mt = 0; mt < 2; mt++)
                LDSM_X4(a[mt][0], a[mt][1], a[mt][2], a[mt][3],
                        sA + aoff + mt * 1280 + ks * 32);
            uint32_t b[8][2];
            #pragma unroll
            for (int np = 0; np < 4; np++) {
                uint32_t r0, r1, r2, r3;
                LDSM_X4(r0, r1, r2, r3, sB + boff + np * 1280 + ks * 32);
                b[np * 2][0]     = r0; b[np * 2][1]     = r1;
                b[np * 2 + 1][0] = r2; b[np * 2 + 1][1] = r3;
            }
            #pragma unroll
            for (int mt = 0; mt < 2; mt++)
                #pragma unroll
                for (int nt = 0; nt < 8; nt++)
                    MMA16816(acc[mt][nt], a[mt], b[nt]);
        }
    }

    // ---------------- epilogue (scatter, predicated on rc < total) ---------
    const int rc0 = row0 + warp_m * 32 + (lane >> 2);
    const int ncb = col0 + warp_n * 64 + (lane & 3) * 2;

    #pragma unroll
    for (int mt = 0; mt < 2; mt++) {
        #pragma unroll
        for (int half = 0; half < 2; half++) {
            const int rc = rc0 + mt * 16 + half * 8;
            if (rc >= total) continue;
            const int orig = g_rowidx[rc];
            const int bg   = orig >> 8;
            #pragma unroll
            for (int nt = 0; nt < 8; nt++) {
                const int ncol = ncb + nt * 8;
                float v0 = acc[mt][nt][half * 2];
                float v1 = acc[mt][nt][half * 2 + 1];
                if (MODE == 0) {
                    const float c0 = ctx1[(size_t)bg * NTOT1 + ncol];
                    const float c1 = ctx1[(size_t)bg * NTOT1 + ncol + 1];
                    if (ncol < FHID) {
                        v0 = silu(v0 + bias1[ncol]     + c0);
                        v1 = silu(v1 + bias1[ncol + 1] + c1);
                        *(__half2*)&outh[(size_t)rc * FHID + ncol] =
                            __floats2half2_rn(v0, v1);
                    } else {
                        const int a0 = ncol - FHID;
                        v0 = silu(v0 + bias2[a0]     + c0);
                        v1 = silu(v1 + bias2[a0 + 1] + c1);
                        *(__half2*)&outa[(size_t)rc * AHID + a0] =
                            __floats2half2_rn(v0, v1);
                    }
                } else {
                    float2 o;
                    o.x = v0 + bias1[ncol]     + residual[(size_t)orig * FOUT + ncol];
                    o.y = v1 + bias1[ncol + 1] + residual[(size_t)orig * FOUT + ncol + 1];
                    *(float2*)&outf[(size_t)orig * FOUT + ncol] = o;
                }
            }
        }
    }
}

// ---------------------------------------------------------------------------
// Copy nodes -> out for masked rows (their feats are zero => out = nodes)
// ---------------------------------------------------------------------------
__global__ void copy_masked_kernel(const float* __restrict__ nodes,
                                   const int* __restrict__ mask,
                                   float* __restrict__ out)
{
    const int row = blockIdx.x * 4 + (threadIdx.x >> 6);
    const int c   = threadIdx.x & 63;
    if (mask[row] == 0)
        ((float4*)out)[(size_t)row * 64 + c] =
            ((const float4*)nodes)[(size_t)row * 64 + c];
}

// ---------------------------------------------------------------------------
// scores[orig,4] = g_ah[rc,256] @ aw2 + ab2  (one warp per compact row)
// ---------------------------------------------------------------------------
__global__ void attn2_kernel(const __half* __restrict__ ah,
                             const float* __restrict__ aw2,
                             const float* __restrict__ ab2,
                             float* __restrict__ scores)
{
    const int rc   = (blockIdx.x * blockDim.x + threadIdx.x) >> 5;
    const int lane = threadIdx.x & 31;
    if (rc >= g_meta[0]) return;
    const __half2* a2 = (const __half2*)(ah + (size_t)rc * AHID);
    float a0 = 0.f, a1 = 0.f, a2s = 0.f, a3 = 0.f;
    #pragma unroll
    for (int i = 0; i < 4; i++) {
        const int k2 = i * 32 + lane;
        __half2 h = a2[k2];
        float f0 = __low2float(h), f1 = __high2float(h);
        float4 w0 = ((const float4*)aw2)[2 * k2];
        float4 w1 = ((const float4*)aw2)[2 * k2 + 1];
        a0  = fmaf(f0, w0.x, fmaf(f1, w1.x, a0));
        a1  = fmaf(f0, w0.y, fmaf(f1, w1.y, a1));
        a2s = fmaf(f0, w0.z, fmaf(f1, w1.z, a2s));
        a3  = fmaf(f0, w0.w, fmaf(f1, w1.w, a3));
    }
    a0 = warp_sum(a0); a1 = warp_sum(a1); a2s = warp_sum(a2s); a3 = warp_sum(a3);
    if (lane == 0)
        ((float4*)scores)[g_rowidx[rc]] =
            make_float4(a0 + ab2[0], a1 + ab2[1], a2s + ab2[2], a3 + ab2[3]);
}

// ---------------------------------------------------------------------------
// Masked softmax over nodes per (graph, head)
// ---------------------------------------------------------------------------
__global__ void softmax_kernel(const float* __restrict__ scores,
                               const int* __restrict__ mask,
                               float* __restrict__ w)
{
    const int b = blockIdx.x;
    const int n = threadIdx.x;
    const int idx = b * NNODES + n;
    const float NEG = -INFINITY;
    const float inv_scale = 1.0f / 16.0f;

    const bool valid = mask[idx] != 0;
    float4 s = valid ? ((const float4*)scores)[idx] : make_float4(0, 0, 0, 0);
    float v0 = valid ? s.x * inv_scale : NEG;
    float v1 = valid ? s.y * inv_scale : NEG;
    float v2 = valid ? s.z * inv_scale : NEG;
    float v3 = valid ? s.w * inv_scale : NEG;

    __shared__ float4 red[NNODES];
    red[n] = make_float4(v0, v1, v2, v3);
    __syncthreads();
    for (int off = 128; off > 0; off >>= 1) {
        if (n < off) {
            float4 a = red[n], c = red[n + off];
            red[n] = make_float4(fmaxf(a.x, c.x), fmaxf(a.y, c.y),
                                 fmaxf(a.z, c.z), fmaxf(a.w, c.w));
        }
        __syncthreads();
    }
    float4 mx = red[0];
    __syncthreads();

    float e0 = valid ? __expf(v0 - mx.x) : 0.f;
    float e1 = valid ? __expf(v1 - mx.y) : 0.f;
    float e2 = valid ? __expf(v2 - mx.z) : 0.f;
    float e3 = valid ? __expf(v3 - mx.w) : 0.f;

    red[n] = make_float4(e0, e1, e2, e3);
    __syncthreads();
    for (int off = 128; off > 0; off >>= 1) {
        if (n < off) {
            float4 a = red[n], c = red[n + off];
            red[n] = make_float4(a.x + c.x, a.y + c.y, a.z + c.z, a.w + c.w);
        }
        __syncthreads();
    }
    float4 sm = red[0];
    ((float4*)w)[idx] = make_float4(e0 / sm.x, e1 / sm.y, e2 / sm.z, e3 / sm.w);
}

// ---------------------------------------------------------------------------
// pooled[b,c] = sum_n new_nodes[b,n,c] * w[b,n,c/64]
// ---------------------------------------------------------------------------
__global__ void pool_kernel(const float* __restrict__ newn,
                            const float* __restrict__ w,
                            float* __restrict__ pooled)
{
    const int b = blockIdx.x;
    const int c = threadIdx.x;
    __shared__ float ws[NNODES * NHEADS];
    ((float4*)ws)[c] = ((const float4*)(w + (size_t)b * NNODES * NHEADS))[c];
    __syncthreads();

    const int h = c >> 6;
    const float* base = newn + (size_t)b * NNODES * FOUT + c;
    float acc = 0.f;
    #pragma unroll 8
    for (int n = 0; n < NNODES; n++)
        acc = fmaf(base[(size_t)n * FOUT], ws[n * NHEADS + h], acc);
    pooled[b * FOUT + c] = acc;
}

// ---------------------------------------------------------------------------
// Launch
// ---------------------------------------------------------------------------
extern "C" void kernel_launch(void* const* d_in, const int* in_sizes, int n_in,
                              void* d_out, int out_size)
{
    const float* nodes = (const float*)d_in[0];
    const float* pe    = (const float*)d_in[1];
    const int*   mask  = (const int*)d_in[2];
    const float* globs = (const float*)d_in[3];
    const float* ln_g  = (const float*)d_in[4];
    const float* ln_b  = (const float*)d_in[5];
    const float* fw1   = (const float*)d_in[6];
    const float* fb1   = (const float*)d_in[7];
    const float* fw2   = (const float*)d_in[8];
    const float* fb2   = (const float*)d_in[9];
    const float* aw1   = (const float*)d_in[10];
    const float* ab1   = (const float*)d_in[11];
    const float* aw2   = (const float*)d_in[12];
    const float* ab2   = (const float*)d_in[13];

    float* out_nodes  = (float*)d_out;
    float* out_pooled = out_nodes + (size_t)MROWS * FOUT;

    __half *p_inp, *p_hid, *p_ah, *p_w1t, *p_w2t;
    float  *p_scores, *p_wsm, *p_ctx1;
    cudaGetSymbolAddress((void**)&p_inp,    g_inp);
    cudaGetSymbolAddress((void**)&p_hid,    g_hid);
    cudaGetSymbolAddress((void**)&p_ah,     g_ah);
    cudaGetSymbolAddress((void**)&p_scores, g_scores);
    cudaGetSymbolAddress((void**)&p_wsm,    g_wsm);
    cudaGetSymbolAddress((void**)&p_w1t,    g_w1t);
    cudaGetSymbolAddress((void**)&p_w2t,    g_w2t);
    cudaGetSymbolAddress((void**)&p_ctx1,   g_ctx1);

    cudaFuncSetAttribute(gemm_mma<0>, cudaFuncAttributeMaxDynamicSharedMemorySize, GSMEM);
    cudaFuncSetAttribute(gemm_mma<1>, cudaFuncAttributeMaxDynamicSharedMemorySize, GSMEM);
    cudaFuncSetAttribute(gemm_mma<0>, cudaFuncAttributePreferredSharedMemoryCarveout, 100);
    cudaFuncSetAttribute(gemm_mma<1>, cudaFuncAttributePreferredSharedMemoryCarveout, 100);

    // 1) compaction of valid rows
    count_kernel<<<512, 256>>>(mask);
    scan_kernel<<<1, 512>>>();
    scatter_kernel<<<512, 256>>>(mask);
    pad_kernel<<<1, 256>>>();

    // 2) LN + concat -> g_inp fp16 [M,512]; ctx; weight transposes
    prep_kernel<<<MROWS, 128>>>(nodes, pe, ln_g, ln_b, p_inp);
    ctx_kernel<<<BATCH, 256>>>(globs, fw1, aw1, p_ctx1);
    wtrans_kernel<<<dim3(40, 16), dim3(32, 8)>>>(fw1, FHID, FHID, aw1, AHID, AHID,
                                                 FEAT_IN, p_w1t);
    wtrans_kernel<<<dim3(8, 32),  dim3(32, 8)>>>(fw2, FOUT, FOUT, nullptr, 0, 0,
                                                 FHID, p_w2t);

    // 3) GEMM1 on compacted rows (gathered A): -> dense g_hid / g_ah
    gemm_mma<0><<<dim3(NTOT1 / 128, MROWS / 128), 256, GSMEM>>>(
        p_inp, p_w1t, FEAT_IN, fb1, ab1, p_ctx1, p_hid, p_ah, nullptr, nullptr);

    // 4) head scores (compact -> scatter) -> softmax weights
    attn2_kernel<<<MROWS / 8, 256>>>(p_ah, aw2, ab2, p_scores);
    softmax_kernel<<<BATCH, NNODES>>>(p_scores, mask, p_wsm);

    // 5) GEMM3 on compacted rows (dense A), scatter +bias+residual -> new_nodes
    gemm_mma<1><<<dim3(FOUT / 128, MROWS / 128), 256, GSMEM>>>(
        p_hid, p_w2t, FHID, fb2, nullptr, nullptr, nullptr, nullptr,
        out_nodes, nodes);

    // 6) masked rows: new_nodes = nodes
    copy_masked_kernel<<<MROWS / 4, 256>>>(nodes, mask, out_nodes);

    // 7) attention pooling
    pool_kernel<<<BATCH, 256>>>(out_nodes, p_wsm, out_pooled);
}

// round 13
// speedup vs baseline: 1.8205x; 1.0059x over previous
#include <cuda_runtime.h>
#include <cuda_fp16.h>
#include <math.h>
#include <stdint.h>

// Problem constants
#define BATCH   512
#define NNODES  256
#define MROWS   (BATCH * NNODES)     // 131072
#define FEAT_IN 512
#define GLOB_D  64
#define FHID    1024
#define AHID    256
#define FOUT    256
#define NTOT1   (FHID + AHID)        // 1280
#define NHEADS  4
#define LN_EPS  1e-5f

// ---------------------------------------------------------------------------
// Scratch (device globals; no runtime allocation)
// ---------------------------------------------------------------------------
__device__ __half g_inp[(size_t)MROWS * FEAT_IN];      // fp16 LN output (COMPACT rows)
__device__ __half g_hid[(size_t)MROWS * FHID];         // fp16 silu hidden (COMPACT rows)
__device__ __half g_ah [(size_t)MROWS * AHID];         // fp16 attn hidden (COMPACT rows)
__device__ float  g_scores[(size_t)MROWS * NHEADS];
__device__ float  g_wsm   [(size_t)MROWS * NHEADS];
__device__ __half g_w1t[(size_t)NTOT1 * FEAT_IN];      // [1280,512] (fw1||aw1)^T fp16
__device__ __half g_w2t[(size_t)FOUT * FHID];          // [256,1024] fw2^T fp16
__device__ float  g_ctx1[(size_t)BATCH * NTOT1];       // per-graph ctx contribution
__device__ int    g_rowidx[MROWS];                     // compact -> original row
__device__ int    g_bcnt[512];                         // per-graph valid count
__device__ int    g_boff[512];                         // per-graph compact offset
__device__ int    g_meta[2];                           // [0]=total valid, [1]=padded

// ---------------------------------------------------------------------------
// PTX helpers (baseline ISA: works at compute_103 target)
// ---------------------------------------------------------------------------
__device__ __forceinline__ uint32_t smem_u32(const void* p) {
    uint32_t a;
    asm("{ .reg .u64 t; cvta.to.shared.u64 t, %1; cvt.u32.u64 %0, t; }"
        : "=r"(a) : "l"(p));
    return a;
}

#define CP_ASYNC16(dst, src) \
    asm volatile("cp.async.cg.shared.global [%0], [%1], 16;" \
        :: "r"(dst), "l"(src))
#define CP_COMMIT()  asm volatile("cp.async.commit_group;" ::: "memory")
#define CP_WAIT2()   asm volatile("cp.async.wait_group 2;" ::: "memory")

#define LDSM_X4(r0, r1, r2, r3, addr) \
    asm volatile("ldmatrix.sync.aligned.m8n8.x4.shared.b16 {%0,%1,%2,%3}, [%4];" \
        : "=r"(r0), "=r"(r1), "=r"(r2), "=r"(r3) : "r"(addr))

#define MMA16816(c, a, b) \
    asm volatile("mma.sync.aligned.m16n8k16.row.col.f32.f16.f16.f32 " \
        "{%0,%1,%2,%3}, {%4,%5,%6,%7}, {%8,%9}, {%0,%1,%2,%3};" \
        : "+f"((c)[0]), "+f"((c)[1]), "+f"((c)[2]), "+f"((c)[3]) \
        : "r"((a)[0]), "r"((a)[1]), "r"((a)[2]), "r"((a)[3]), \
          "r"((b)[0]), "r"((b)[1]))

__device__ __forceinline__ float warp_sum(float v) {
    #pragma unroll
    for (int o = 16; o > 0; o >>= 1) v += __shfl_xor_sync(0xffffffffu, v, o);
    return v;
}

__device__ __forceinline__ float silu(float v) {
    return __fdividef(v, 1.0f + __expf(-v));
}

// ---------------------------------------------------------------------------
// Compaction: count -> scan -> scatter -> pad
// ---------------------------------------------------------------------------
__global__ void count_kernel(const int* __restrict__ mask)
{
    const int t = threadIdx.x, lane = t & 31, wid = t >> 5;
    const int r = blockIdx.x * 256 + t;
    __shared__ int ws[8];
    unsigned bal = __ballot_sync(0xffffffffu, mask[r] != 0);
    if (lane == 0) ws[wid] = __popc(bal);
    __syncthreads();
    if (t == 0) {
        int s = 0;
        #pragma unroll
        for (int i = 0; i < 8; i++) s += ws[i];
        g_bcnt[blockIdx.x] = s;
    }
}

__global__ void scan_kernel()
{
    __shared__ int s[512];
    const int t = threadIdx.x;
    const int c = g_bcnt[t];
    s[t] = c;
    __syncthreads();
    for (int off = 1; off < 512; off <<= 1) {
        int v = (t >= off) ? s[t - off] : 0;
        __syncthreads();
        s[t] += v;
        __syncthreads();
    }
    g_boff[t] = s[t] - c;
    if (t == 511) {
        g_meta[0] = s[511];
        g_meta[1] = ((s[511] + 127) >> 7) << 7;
    }
}

__global__ void scatter_kernel(const int* __restrict__ mask)
{
    const int t = threadIdx.x, lane = t & 31, wid = t >> 5;
    const int r = blockIdx.x * 256 + t;
    __shared__ int ws[8];
    const int v = mask[r] != 0;
    unsigned bal = __ballot_sync(0xffffffffu, v);
    if (lane == 0) ws[wid] = __popc(bal);
    __syncthreads();
    int wpre = 0;
    #pragma unroll
    for (int i = 0; i < 8; i++) if (i < wid) wpre += ws[i];
    if (v) {
        int pos = g_boff[blockIdx.x] + wpre + __popc(bal & ((1u << lane) - 1));
        g_rowidx[pos] = r;
    }
}

__global__ void pad_kernel()
{
    const int total = g_meta[0], npad = g_meta[1];
    for (int i = total + (int)threadIdx.x; i < npad; i += 256)
        g_rowidx[i] = 0;   // row 0 always valid; stores for pads are predicated off
}

// ---------------------------------------------------------------------------
// LayerNorm over COMPACT valid rows (gather orig via rowidx, write dense)
// ---------------------------------------------------------------------------
__global__ void prep_kernel(const float* __restrict__ nodes,
                            const float* __restrict__ pe,
                            const float* __restrict__ ln_g,
                            const float* __restrict__ ln_b,
                            __half* __restrict__ inp)
{
    const int rc = blockIdx.x;
    if (rc >= g_meta[0]) return;
    const int row = g_rowidx[rc];
    const int t   = threadIdx.x;          // 0..127

    float4 v = (t < 64)
        ? ((const float4*)nodes)[(size_t)row * 64 + t]
        : ((const float4*)pe)   [(size_t)row * 64 + (t - 64)];

    float s  = v.x + v.y + v.z + v.w;
    float sq = v.x*v.x + v.y*v.y + v.z*v.z + v.w*v.w;

    __shared__ float ssum[4], ssq[4];
    __shared__ float s_mu, s_rstd;
    const int lane = t & 31, wid = t >> 5;
    float ws = warp_sum(s), wq = warp_sum(sq);
    if (lane == 0) { ssum[wid] = ws; ssq[wid] = wq; }
    __syncthreads();
    if (t == 0) {
        float S = ssum[0] + ssum[1] + ssum[2] + ssum[3];
        float Q = ssq[0]  + ssq[1]  + ssq[2]  + ssq[3];
        float mu  = S * (1.0f / FEAT_IN);
        float var = Q * (1.0f / FEAT_IN) - mu * mu;
        s_mu = mu; s_rstd = rsqrtf(var + LN_EPS);
    }
    __syncthreads();
    const float mu = s_mu, rstd = s_rstd;

    float4 g4 = ((const float4*)ln_g)[t];
    float4 b4 = ((const float4*)ln_b)[t];
    float o0 = (v.x - mu) * rstd * g4.x + b4.x;
    float o1 = (v.y - mu) * rstd * g4.y + b4.y;
    float o2 = (v.z - mu) * rstd * g4.z + b4.z;
    float o3 = (v.w - mu) * rstd * g4.w + b4.w;

    __half* dst = inp + (size_t)rc * FEAT_IN + t * 4;
    *(__half2*)(dst)     = __floats2half2_rn(o0, o1);
    *(__half2*)(dst + 2) = __floats2half2_rn(o2, o3);
}

// ---------------------------------------------------------------------------
// Per-graph ctx contribution: ctx1[b,n] = sum_j globs[b,j] * W[512+j, n]
// ---------------------------------------------------------------------------
__global__ void ctx_kernel(const float* __restrict__ globs,
                           const float* __restrict__ fw1,
                           const float* __restrict__ aw1,
                           float* __restrict__ ctx1)
{
    __shared__ float gs[GLOB_D];
    const int b = blockIdx.x;
    if (threadIdx.x < GLOB_D) gs[threadIdx.x] = globs[b * GLOB_D + threadIdx.x];
    __syncthreads();
    for (int n = threadIdx.x; n < NTOT1; n += blockDim.x) {
        float acc = 0.f;
        if (n < FHID) {
            #pragma unroll 8
            for (int j = 0; j < GLOB_D; j++)
                acc = fmaf(gs[j], fw1[(size_t)(FEAT_IN + j) * FHID + n], acc);
        } else {
            #pragma unroll 8
            for (int j = 0; j < GLOB_D; j++)
                acc = fmaf(gs[j], aw1[(size_t)(FEAT_IN + j) * AHID + (n - FHID)], acc);
        }
        ctx1[(size_t)b * NTOT1 + n] = acc;
    }
}

// ---------------------------------------------------------------------------
// Weight transpose + fp16 cast
// ---------------------------------------------------------------------------
__global__ void wtrans_kernel(const float* __restrict__ W1, int N1, int ld1,
                              const float* __restrict__ W2, int N2, int ld2,
                              int K, __half* __restrict__ Wt)
{
    __shared__ float tile[32][33];
    const int nb = blockIdx.x * 32, kb = blockIdx.y * 32;
    const int tx = threadIdx.x, ty = threadIdx.y;
    const int Ntot = N1 + N2;
    for (int i = ty; i < 32; i += 8) {
        int k = kb + i, n = nb + tx;
        float v = 0.f;
        if (k < K && n < Ntot)
            v = (n < N1) ? W1[(size_t)k * ld1 + n] : W2[(size_t)k * ld2 + (n - N1)];
        tile[i][tx] = v;
    }
    __syncthreads();
    for (int i = ty; i < 32; i += 8) {
        int n = nb + i, k = kb + tx;
        if (n < Ntot && k < K)
            Wt[(size_t)n * K + k] = __float2half_rn(tile[tx][i]);
    }
}

// ---------------------------------------------------------------------------
// HGEMM via mma.sync m16n8k16 over COMPACTED valid rows (dense A).
// CTA tile 128x128, BK=32, 4-stage cp.async pipeline, 8 warps (4m x 2n),
// warp tile 32x64, smem stride 40 halfs. (R7 config = best measured.)
// MODE 0 (GEMM1): silu(x+bias+ctx) -> dense compact outh / outa (fp16).
// MODE 1 (GEMM3): x+bias1+residual[orig] -> outf[orig] (scatter).
// Grid rows worst-case (MROWS/128); blocks beyond padded count exit.
// Epilogue stores predicated on compact row < total.
// ---------------------------------------------------------------------------
#define NSTAGE    4
#define GSTAGE_B  20480               // (128*40*2) * 2 tiles
#define GSMEM     (NSTAGE * GSTAGE_B) // 81920

template<int MODE>
__global__ __launch_bounds__(256, 2) void gemm_mma(
    const __half* __restrict__ A, const __half* __restrict__ Bt, int K,
    const float* __restrict__ bias1, const float* __restrict__ bias2,
    const float* __restrict__ ctx1,
    __half* __restrict__ outh, __half* __restrict__ outa,
    float* __restrict__ outf,
    const float* __restrict__ residual)
{
    const int total = g_meta[0];
    const int npad  = g_meta[1];
    const int row0  = blockIdx.y * 128;
    if (row0 >= npad) return;

    extern __shared__ char smem[];
    const uint32_t sbase = smem_u32(smem);
    const int tid    = threadIdx.x;
    const int wid    = tid >> 5;
    const int lane   = tid & 31;
    const int warp_m = wid & 3;
    const int warp_n = wid >> 2;
    const int col0   = blockIdx.x * 128;
    const int iters  = K >> 5;

    // cp.async mapping: 16B chunks; A,B each 512 slots -> 2 per thread
    const int ldr = tid >> 2;              // 0..63 (rows; +64 for i=1)
    const int ldk = (tid & 3) * 8;         // k-offset in halfs

    float acc[2][8][4];
    #pragma unroll
    for (int mt = 0; mt < 2; mt++)
        #pragma unroll
        for (int nt = 0; nt < 8; nt++)
            #pragma unroll
            for (int j = 0; j < 4; j++) acc[mt][nt][j] = 0.f;

    // ldmatrix lane-derived offsets
    const int lm = lane & 15, lq = lane >> 4;
    const uint32_t aoff = ((warp_m * 32 + lm) * 40 + lq * 8) * 2;
    const int bn = (lane >> 4) * 8 + (lane & 7);
    const int bk = ((lane >> 3) & 1) * 8;
    const uint32_t boff = ((warp_n * 64 + bn) * 40 + bk) * 2;

    auto load_stage = [&](int s, int kk) {
        const uint32_t dA = sbase + s * GSTAGE_B;
        const uint32_t dB = dA + 10240;
        #pragma unroll
        for (int i = 0; i < 2; i++) {
            const int r = ldr + i * 64;
            const uint32_t soff = (r * 40 + ldk) * 2;
            CP_ASYNC16(dA + soff, &A [(size_t)(row0 + r) * K + kk + ldk]);
            CP_ASYNC16(dB + soff, &Bt[(size_t)(col0 + r) * K + kk + ldk]);
        }
    };

    load_stage(0, 0);  CP_COMMIT();
    load_stage(1, 32); CP_COMMIT();
    load_stage(2, 64); CP_COMMIT();

    for (int i = 0; i < iters; i++) {
        CP_WAIT2();
        __syncthreads();
        if (i + 3 < iters) load_stage((i + 3) % NSTAGE, (i + 3) * 32);
        CP_COMMIT();

        const int s = i % NSTAGE;
        const uint32_t sA = sbase + s * GSTAGE_B;
        const uint32_t sB = sA + 10240;

        #pragma unroll
        for (int ks = 0; ks < 2; ks++) {
            uint32_t a[2][4];
            #pragma unroll
            for (int mt = 0; mt < 2; mt++)
                LDSM_X4(a[mt][0], a[mt][1], a[mt][2], a[mt][3],
                        sA + aoff + mt * 1280 + ks * 32);
            uint32_t b[8][2];
            #pragma unroll
            for (int np = 0; np < 4; np++) {
                uint32_t r0, r1, r2, r3;
                LDSM_X4(r0, r1, r2, r3, sB + boff + np * 1280 + ks * 32);
                b[np * 2][0]     = r0; b[np * 2][1]     = r1;
                b[np * 2 + 1][0] = r2; b[np * 2 + 1][1] = r3;
            }
            #pragma unroll
            for (int mt = 0; mt < 2; mt++)
                #pragma unroll
                for (int nt = 0; nt < 8; nt++)
                    MMA16816(acc[mt][nt], a[mt], b[nt]);
        }
    }

    // ---------------- epilogue (predicated on rc < total) ------------------
    const int rc0 = row0 + warp_m * 32 + (lane >> 2);
    const int ncb = col0 + warp_n * 64 + (lane & 3) * 2;

    #pragma unroll
    for (int mt = 0; mt < 2; mt++) {
        #pragma unroll
        for (int half = 0; half < 2; half++) {
            const int rc = rc0 + mt * 16 + half * 8;
            if (rc >= total) continue;
            const int orig = g_rowidx[rc];
            const int bg   = orig >> 8;
            #pragma unroll
            for (int nt = 0; nt < 8; nt++) {
                const int ncol = ncb + nt * 8;
                float v0 = acc[mt][nt][half * 2];
                float v1 = acc[mt][nt][half * 2 + 1];
                if (MODE == 0) {
                    const float c0 = ctx1[(size_t)bg * NTOT1 + ncol];
                    const float c1 = ctx1[(size_t)bg * NTOT1 + ncol + 1];
                    if (ncol < FHID) {
                        v0 = silu(v0 + bias1[ncol]     + c0);
                        v1 = silu(v1 + bias1[ncol + 1] + c1);
                        *(__half2*)&outh[(size_t)rc * FHID + ncol] =
                            __floats2half2_rn(v0, v1);
                    } else {
                        const int a0 = ncol - FHID;
                        v0 = silu(v0 + bias2[a0]     + c0);
                        v1 = silu(v1 + bias2[a0 + 1] + c1);
                        *(__half2*)&outa[(size_t)rc * AHID + a0] =
                            __floats2half2_rn(v0, v1);
                    }
                } else {
                    float2 o;
                    o.x = v0 + bias1[ncol]     + residual[(size_t)orig * FOUT + ncol];
                    o.y = v1 + bias1[ncol + 1] + residual[(size_t)orig * FOUT + ncol + 1];
                    *(float2*)&outf[(size_t)orig * FOUT + ncol] = o;
                }
            }
        }
    }
}

// ---------------------------------------------------------------------------
// Copy nodes -> out for masked rows (their feats are zero => out = nodes)
// ---------------------------------------------------------------------------
__global__ void copy_masked_kernel(const float* __restrict__ nodes,
                                   const int* __restrict__ mask,
                                   float* __restrict__ out)
{
    const int row = blockIdx.x * 4 + (threadIdx.x >> 6);
    const int c   = threadIdx.x & 63;
    if (mask[row] == 0)
        ((float4*)out)[(size_t)row * 64 + c] =
            ((const float4*)nodes)[(size_t)row * 64 + c];
}

// ---------------------------------------------------------------------------
// scores[orig,4] = g_ah[rc,256] @ aw2 + ab2  (one warp per compact row)
// ---------------------------------------------------------------------------
__global__ void attn2_kernel(const __half* __restrict__ ah,
                             const float* __restrict__ aw2,
                             const float* __restrict__ ab2,
                             float* __restrict__ scores)
{
    const int rc   = (blockIdx.x * blockDim.x + threadIdx.x) >> 5;
    const int lane = threadIdx.x & 31;
    if (rc >= g_meta[0]) return;
    const __half2* a2 = (const __half2*)(ah + (size_t)rc * AHID);
    float a0 = 0.f, a1 = 0.f, a2s = 0.f, a3 = 0.f;
    #pragma unroll
    for (int i = 0; i < 4; i++) {
        const int k2 = i * 32 + lane;
        __half2 h = a2[k2];
        float f0 = __low2float(h), f1 = __high2float(h);
        float4 w0 = ((const float4*)aw2)[2 * k2];
        float4 w1 = ((const float4*)aw2)[2 * k2 + 1];
        a0  = fmaf(f0, w0.x, fmaf(f1, w1.x, a0));
        a1  = fmaf(f0, w0.y, fmaf(f1, w1.y, a1));
        a2s = fmaf(f0, w0.z, fmaf(f1, w1.z, a2s));
        a3  = fmaf(f0, w0.w, fmaf(f1, w1.w, a3));
    }
    a0 = warp_sum(a0); a1 = warp_sum(a1); a2s = warp_sum(a2s); a3 = warp_sum(a3);
    if (lane == 0)
        ((float4*)scores)[g_rowidx[rc]] =
            make_float4(a0 + ab2[0], a1 + ab2[1], a2s + ab2[2], a3 + ab2[3]);
}

// ---------------------------------------------------------------------------
// Masked softmax over nodes per (graph, head)
// ---------------------------------------------------------------------------
__global__ void softmax_kernel(const float* __restrict__ scores,
                               const int* __restrict__ mask,
                               float* __restrict__ w)
{
    const int b = blockIdx.x;
    const int n = threadIdx.x;
    const int idx = b * NNODES + n;
    const float NEG = -INFINITY;
    const float inv_scale = 1.0f / 16.0f;

    const bool valid = mask[idx] != 0;
    float4 s = valid ? ((const float4*)scores)[idx] : make_float4(0, 0, 0, 0);
    float v0 = valid ? s.x * inv_scale : NEG;
    float v1 = valid ? s.y * inv_scale : NEG;
    float v2 = valid ? s.z * inv_scale : NEG;
    float v3 = valid ? s.w * inv_scale : NEG;

    __shared__ float4 red[NNODES];
    red[n] = make_float4(v0, v1, v2, v3);
    __syncthreads();
    for (int off = 128; off > 0; off >>= 1) {
        if (n < off) {
            float4 a = red[n], c = red[n + off];
            red[n] = make_float4(fmaxf(a.x, c.x), fmaxf(a.y, c.y),
                                 fmaxf(a.z, c.z), fmaxf(a.w, c.w));
        }
        __syncthreads();
    }
    float4 mx = red[0];
    __syncthreads();

    float e0 = valid ? __expf(v0 - mx.x) : 0.f;
    float e1 = valid ? __expf(v1 - mx.y) : 0.f;
    float e2 = valid ? __expf(v2 - mx.z) : 0.f;
    float e3 = valid ? __expf(v3 - mx.w) : 0.f;

    red[n] = make_float4(e0, e1, e2, e3);
    __syncthreads();
    for (int off = 128; off > 0; off >>= 1) {
        if (n < off) {
            float4 a = red[n], c = red[n + off];
            red[n] = make_float4(a.x + c.x, a.y + c.y, a.z + c.z, a.w + c.w);
        }
        __syncthreads();
    }
    float4 sm = red[0];
    ((float4*)w)[idx] = make_float4(e0 / sm.x, e1 / sm.y, e2 / sm.z, e3 / sm.w);
}

// ---------------------------------------------------------------------------
// Attention pooling over valid rows only:
// pooled[b,c] = sum_{valid n} new_nodes[b,n,c] * w[b,n,c/64]
// ---------------------------------------------------------------------------
__global__ void pool_kernel(const float* __restrict__ newn,
                            const float* __restrict__ w,
                            float* __restrict__ pooled)
{
    const int b = blockIdx.x;
    const int c = threadIdx.x;
    __shared__ float ws[NNODES * NHEADS];
    __shared__ int   ridx[NNODES];
    ((float4*)ws)[c] = ((const float4*)(w + (size_t)b * NNODES * NHEADS))[c];
    const int cnt = g_bcnt[b], off = g_boff[b];
    if (c < cnt) ridx[c] = g_rowidx[off + c];
    __syncthreads();

    const int h = c >> 6;
    float acc = 0.f;
    for (int i = 0; i < cnt; i++) {
        const int orig = ridx[i];
        const int ln   = orig & 255;
        acc = fmaf(newn[(size_t)orig * FOUT + c], ws[ln * NHEADS + h], acc);
    }
    pooled[b * FOUT + c] = acc;
}

// ---------------------------------------------------------------------------
// Launch
// ---------------------------------------------------------------------------
extern "C" void kernel_launch(void* const* d_in, const int* in_sizes, int n_in,
                              void* d_out, int out_size)
{
    const float* nodes = (const float*)d_in[0];
    const float* pe    = (const float*)d_in[1];
    const int*   mask  = (const int*)d_in[2];
    const float* globs = (const float*)d_in[3];
    const float* ln_g  = (const float*)d_in[4];
    const float* ln_b  = (const float*)d_in[5];
    const float* fw1   = (const float*)d_in[6];
    const float* fb1   = (const float*)d_in[7];
    const float* fw2   = (const float*)d_in[8];
    const float* fb2   = (const float*)d_in[9];
    const float* aw1   = (const float*)d_in[10];
    const float* ab1   = (const float*)d_in[11];
    const float* aw2   = (const float*)d_in[12];
    const float* ab2   = (const float*)d_in[13];

    float* out_nodes  = (float*)d_out;
    float* out_pooled = out_nodes + (size_t)MROWS * FOUT;

    __half *p_inp, *p_hid, *p_ah, *p_w1t, *p_w2t;
    float  *p_scores, *p_wsm, *p_ctx1;
    cudaGetSymbolAddress((void**)&p_inp,    g_inp);
    cudaGetSymbolAddress((void**)&p_hid,    g_hid);
    cudaGetSymbolAddress((void**)&p_ah,     g_ah);
    cudaGetSymbolAddress((void**)&p_scores, g_scores);
    cudaGetSymbolAddress((void**)&p_wsm,    g_wsm);
    cudaGetSymbolAddress((void**)&p_w1t,    g_w1t);
    cudaGetSymbolAddress((void**)&p_w2t,    g_w2t);
    cudaGetSymbolAddress((void**)&p_ctx1,   g_ctx1);

    cudaFuncSetAttribute(gemm_mma<0>, cudaFuncAttributeMaxDynamicSharedMemorySize, GSMEM);
    cudaFuncSetAttribute(gemm_mma<1>, cudaFuncAttributeMaxDynamicSharedMemorySize, GSMEM);
    cudaFuncSetAttribute(gemm_mma<0>, cudaFuncAttributePreferredSharedMemoryCarveout, 100);
    cudaFuncSetAttribute(gemm_mma<1>, cudaFuncAttributePreferredSharedMemoryCarveout, 100);

    // 1) compaction of valid rows
    count_kernel<<<512, 256>>>(mask);
    scan_kernel<<<1, 512>>>();
    scatter_kernel<<<512, 256>>>(mask);
    pad_kernel<<<1, 256>>>();

    // 2) LN over compact rows -> g_inp dense; ctx; weight transposes
    prep_kernel<<<MROWS, 128>>>(nodes, pe, ln_g, ln_b, p_inp);
    ctx_kernel<<<BATCH, 256>>>(globs, fw1, aw1, p_ctx1);
    wtrans_kernel<<<dim3(40, 16), dim3(32, 8)>>>(fw1, FHID, FHID, aw1, AHID, AHID,
                                                 FEAT_IN, p_w1t);
    wtrans_kernel<<<dim3(8, 32),  dim3(32, 8)>>>(fw2, FOUT, FOUT, nullptr, 0, 0,
                                                 FHID, p_w2t);

    // 3) GEMM1 on compact rows (dense A): -> dense g_hid / g_ah
    gemm_mma<0><<<dim3(NTOT1 / 128, MROWS / 128), 256, GSMEM>>>(
        p_inp, p_w1t, FEAT_IN, fb1, ab1, p_ctx1, p_hid, p_ah, nullptr, nullptr);

    // 4) head scores (compact -> scatter) -> softmax weights
    attn2_kernel<<<MROWS / 8, 256>>>(p_ah, aw2, ab2, p_scores);
    softmax_kernel<<<BATCH, NNODES>>>(p_scores, mask, p_wsm);

    // 5) GEMM3 on compact rows (dense A), scatter +bias+residual -> new_nodes
    gemm_mma<1><<<dim3(FOUT / 128, MROWS / 128), 256, GSMEM>>>(
        p_hid, p_w2t, FHID, fb2, nullptr, nullptr, nullptr, nullptr,
        out_nodes, nodes);

    // 6) masked rows: new_nodes = nodes
    copy_masked_kernel<<<MROWS / 4, 256>>>(nodes, mask, out_nodes);

    // 7) attention pooling (valid rows only)
    pool_kernel<<<BATCH, 256>>>(out_nodes, p_wsm, out_pooled);
}

// round 14
// speedup vs baseline: 2.1187x; 1.1638x over previous
#include <cuda_runtime.h>
#include <cuda_fp16.h>
#include <math.h>
#include <stdint.h>

// Problem constants
#define BATCH   512
#define NNODES  256
#define MROWS   (BATCH * NNODES)     // 131072
#define FEAT_IN 512
#define GLOB_D  64
#define FHID    1024
#define AHID    256
#define FOUT    256
#define NTOT1   (FHID + AHID)        // 1280
#define NHEADS  4
#define LN_EPS  1e-5f

// ---------------------------------------------------------------------------
// Scratch (device globals; no runtime allocation)
// ---------------------------------------------------------------------------
__device__ __half g_inp[(size_t)MROWS * FEAT_IN];      // fp16 LN output (COMPACT rows)
__device__ __half g_hid[(size_t)MROWS * FHID];         // fp16 silu hidden (COMPACT rows)
__device__ float  g_spart[(size_t)2 * MROWS * NHEADS]; // per-tile score partials
__device__ __half g_w1t[(size_t)NTOT1 * FEAT_IN];      // [1280,512] (fw1||aw1)^T fp16
__device__ __half g_w2t[(size_t)FOUT * FHID];          // [256,1024] fw2^T fp16
__device__ float  g_ctx1[(size_t)BATCH * NTOT1];       // per-graph ctx contribution
__device__ int    g_rowidx[MROWS];                     // compact -> original row
__device__ int    g_bcnt[512];                         // per-graph valid count
__device__ int    g_boff[512];                         // per-graph compact offset
__device__ int    g_meta[2];                           // [0]=total valid, [1]=padded

// ---------------------------------------------------------------------------
// PTX helpers (baseline ISA: works at compute_103 target)
// ---------------------------------------------------------------------------
__device__ __forceinline__ uint32_t smem_u32(const void* p) {
    uint32_t a;
    asm("{ .reg .u64 t; cvta.to.shared.u64 t, %1; cvt.u32.u64 %0, t; }"
        : "=r"(a) : "l"(p));
    return a;
}

#define CP_ASYNC16(dst, src) \
    asm volatile("cp.async.cg.shared.global [%0], [%1], 16;" \
        :: "r"(dst), "l"(src))
#define CP_COMMIT()  asm volatile("cp.async.commit_group;" ::: "memory")
#define CP_WAIT2()   asm volatile("cp.async.wait_group 2;" ::: "memory")

#define LDSM_X4(r0, r1, r2, r3, addr) \
    asm volatile("ldmatrix.sync.aligned.m8n8.x4.shared.b16 {%0,%1,%2,%3}, [%4];" \
        : "=r"(r0), "=r"(r1), "=r"(r2), "=r"(r3) : "r"(addr))

#define MMA16816(c, a, b) \
    asm volatile("mma.sync.aligned.m16n8k16.row.col.f32.f16.f16.f32 " \
        "{%0,%1,%2,%3}, {%4,%5,%6,%7}, {%8,%9}, {%0,%1,%2,%3};" \
        : "+f"((c)[0]), "+f"((c)[1]), "+f"((c)[2]), "+f"((c)[3]) \
        : "r"((a)[0]), "r"((a)[1]), "r"((a)[2]), "r"((a)[3]), \
          "r"((b)[0]), "r"((b)[1]))

__device__ __forceinline__ float warp_sum(float v) {
    #pragma unroll
    for (int o = 16; o > 0; o >>= 1) v += __shfl_xor_sync(0xffffffffu, v, o);
    return v;
}

__device__ __forceinline__ float silu(float v) {
    return __fdividef(v, 1.0f + __expf(-v));
}

// ---------------------------------------------------------------------------
// Compaction: count -> scan -> scatter(+pad)
// ---------------------------------------------------------------------------
__global__ void count_kernel(const int* __restrict__ mask)
{
    const int t = threadIdx.x, lane = t & 31, wid = t >> 5;
    const int r = blockIdx.x * 256 + t;
    __shared__ int ws[8];
    unsigned bal = __ballot_sync(0xffffffffu, mask[r] != 0);
    if (lane == 0) ws[wid] = __popc(bal);
    __syncthreads();
    if (t == 0) {
        int s = 0;
        #pragma unroll
        for (int i = 0; i < 8; i++) s += ws[i];
        g_bcnt[blockIdx.x] = s;
    }
}

__global__ void scan_kernel()
{
    __shared__ int s[512];
    const int t = threadIdx.x;
    const int c = g_bcnt[t];
    s[t] = c;
    __syncthreads();
    for (int off = 1; off < 512; off <<= 1) {
        int v = (t >= off) ? s[t - off] : 0;
        __syncthreads();
        s[t] += v;
        __syncthreads();
    }
    g_boff[t] = s[t] - c;
    if (t == 511) {
        g_meta[0] = s[511];
        g_meta[1] = ((s[511] + 127) >> 7) << 7;
    }
}

__global__ void scatter_kernel(const int* __restrict__ mask)
{
    const int t = threadIdx.x, lane = t & 31, wid = t >> 5;
    const int r = blockIdx.x * 256 + t;
    __shared__ int ws[8];
    const int v = mask[r] != 0;
    unsigned bal = __ballot_sync(0xffffffffu, v);
    if (lane == 0) ws[wid] = __popc(bal);
    __syncthreads();
    int wpre = 0;
    #pragma unroll
    for (int i = 0; i < 8; i++) if (i < wid) wpre += ws[i];
    if (v) {
        int pos = g_boff[blockIdx.x] + wpre + __popc(bal & ((1u << lane) - 1));
        g_rowidx[pos] = r;
    }
    // block 511 also pads [total, npad) — disjoint from scatter writes
    if (blockIdx.x == 511) {
        const int total = g_meta[0], npad = g_meta[1];
        for (int i = total + t; i < npad; i += 256) g_rowidx[i] = 0;
    }
}

// ---------------------------------------------------------------------------
// LayerNorm over COMPACT valid rows (gather orig via rowidx, write dense)
// ---------------------------------------------------------------------------
__global__ void prep_kernel(const float* __restrict__ nodes,
                            const float* __restrict__ pe,
                            const float* __restrict__ ln_g,
                            const float* __restrict__ ln_b,
                            __half* __restrict__ inp)
{
    const int rc = blockIdx.x;
    if (rc >= g_meta[0]) return;
    const int row = g_rowidx[rc];
    const int t   = threadIdx.x;          // 0..127

    float4 v = (t < 64)
        ? ((const float4*)nodes)[(size_t)row * 64 + t]
        : ((const float4*)pe)   [(size_t)row * 64 + (t - 64)];

    float s  = v.x + v.y + v.z + v.w;
    float sq = v.x*v.x + v.y*v.y + v.z*v.z + v.w*v.w;

    __shared__ float ssum[4], ssq[4];
    __shared__ float s_mu, s_rstd;
    const int lane = t & 31, wid = t >> 5;
    float ws = warp_sum(s), wq = warp_sum(sq);
    if (lane == 0) { ssum[wid] = ws; ssq[wid] = wq; }
    __syncthreads();
    if (t == 0) {
        float S = ssum[0] + ssum[1] + ssum[2] + ssum[3];
        float Q = ssq[0]  + ssq[1]  + ssq[2]  + ssq[3];
        float mu  = S * (1.0f / FEAT_IN);
        float var = Q * (1.0f / FEAT_IN) - mu * mu;
        s_mu = mu; s_rstd = rsqrtf(var + LN_EPS);
    }
    __syncthreads();
    const float mu = s_mu, rstd = s_rstd;

    float4 g4 = ((const float4*)ln_g)[t];
    float4 b4 = ((const float4*)ln_b)[t];
    float o0 = (v.x - mu) * rstd * g4.x + b4.x;
    float o1 = (v.y - mu) * rstd * g4.y + b4.y;
    float o2 = (v.z - mu) * rstd * g4.z + b4.z;
    float o3 = (v.w - mu) * rstd * g4.w + b4.w;

    __half* dst = inp + (size_t)rc * FEAT_IN + t * 4;
    *(__half2*)(dst)     = __floats2half2_rn(o0, o1);
    *(__half2*)(dst + 2) = __floats2half2_rn(o2, o3);
}

// ---------------------------------------------------------------------------
// Per-graph ctx contribution: ctx1[b,n] = sum_j globs[b,j] * W[512+j, n]
// ---------------------------------------------------------------------------
__global__ void ctx_kernel(const float* __restrict__ globs,
                           const float* __restrict__ fw1,
                           const float* __restrict__ aw1,
                           float* __restrict__ ctx1)
{
    __shared__ float gs[GLOB_D];
    const int b = blockIdx.x;
    if (threadIdx.x < GLOB_D) gs[threadIdx.x] = globs[b * GLOB_D + threadIdx.x];
    __syncthreads();
    for (int n = threadIdx.x; n < NTOT1; n += blockDim.x) {
        float acc = 0.f;
        if (n < FHID) {
            #pragma unroll 8
            for (int j = 0; j < GLOB_D; j++)
                acc = fmaf(gs[j], fw1[(size_t)(FEAT_IN + j) * FHID + n], acc);
        } else {
            #pragma unroll 8
            for (int j = 0; j < GLOB_D; j++)
                acc = fmaf(gs[j], aw1[(size_t)(FEAT_IN + j) * AHID + (n - FHID)], acc);
        }
        ctx1[(size_t)b * NTOT1 + n] = acc;
    }
}

// ---------------------------------------------------------------------------
// Weight transpose + fp16 cast
// ---------------------------------------------------------------------------
__global__ void wtrans_kernel(const float* __restrict__ W1, int N1, int ld1,
                              const float* __restrict__ W2, int N2, int ld2,
                              int K, __half* __restrict__ Wt)
{
    __shared__ float tile[32][33];
    const int nb = blockIdx.x * 32, kb = blockIdx.y * 32;
    const int tx = threadIdx.x, ty = threadIdx.y;
    const int Ntot = N1 + N2;
    for (int i = ty; i < 32; i += 8) {
        int k = kb + i, n = nb + tx;
        float v = 0.f;
        if (k < K && n < Ntot)
            v = (n < N1) ? W1[(size_t)k * ld1 + n] : W2[(size_t)k * ld2 + (n - N1)];
        tile[i][tx] = v;
    }
    __syncthreads();
    for (int i = ty; i < 32; i += 8) {
        int n = nb + i, k = kb + tx;
        if (n < Ntot && k < K)
            Wt[(size_t)n * K + k] = __float2half_rn(tile[tx][i]);
    }
}

// ---------------------------------------------------------------------------
// HGEMM via mma.sync m16n8k16 over COMPACTED valid rows (dense A).
// CTA tile 128x128, BK=32, 4-stage cp.async pipeline, 8 warps (4m x 2n).
// MODE 0 (GEMM1), col tiles <1024: silu(x+bias+ctx) -> fp16 outh (dense).
// MODE 0, col tiles >=1024 (attn): silu(x+ab1+ctx) projected by aw2 in-register,
//   deterministic slot-based smem reduction -> g_spart[tile][rc][4]. No gmem ah.
// MODE 1 (GEMM3): x+bias1+residual[orig] -> outf[orig] (scatter).
// ---------------------------------------------------------------------------
#define NSTAGE    4
#define GSTAGE_B  20480               // (128*40*2) * 2 tiles
#define GSMEM     (NSTAGE * GSTAGE_B) // 81920

template<int MODE>
__global__ __launch_bounds__(256, 2) void gemm_mma(
    const __half* __restrict__ A, const __half* __restrict__ Bt, int K,
    const float* __restrict__ bias1, const float* __restrict__ bias2,
    const float* __restrict__ ctx1, const float* __restrict__ aw2,
    __half* __restrict__ outh, float* __restrict__ spart,
    float* __restrict__ outf, const float* __restrict__ residual)
{
    const int total = g_meta[0];
    const int npad  = g_meta[1];
    const int row0  = blockIdx.y * 128;
    if (row0 >= npad) return;

    extern __shared__ char smem[];
    const uint32_t sbase = smem_u32(smem);
    const int tid    = threadIdx.x;
    const int wid    = tid >> 5;
    const int lane   = tid & 31;
    const int warp_m = wid & 3;
    const int warp_n = wid >> 2;
    const int col0   = blockIdx.x * 128;
    const int iters  = K >> 5;

    const int ldr = tid >> 2;
    const int ldk = (tid & 3) * 8;

    float acc[2][8][4];
    #pragma unroll
    for (int mt = 0; mt < 2; mt++)
        #pragma unroll
        for (int nt = 0; nt < 8; nt++)
            #pragma unroll
            for (int j = 0; j < 4; j++) acc[mt][nt][j] = 0.f;

    const int lm = lane & 15, lq = lane >> 4;
    const uint32_t aoff = ((warp_m * 32 + lm) * 40 + lq * 8) * 2;
    const int bn = (lane >> 4) * 8 + (lane & 7);
    const int bk = ((lane >> 3) & 1) * 8;
    const uint32_t boff = ((warp_n * 64 + bn) * 40 + bk) * 2;

    auto load_stage = [&](int s, int kk) {
        const uint32_t dA = sbase + s * GSTAGE_B;
        const uint32_t dB = dA + 10240;
        #pragma unroll
        for (int i = 0; i < 2; i++) {
            const int r = ldr + i * 64;
            const uint32_t soff = (r * 40 + ldk) * 2;
            CP_ASYNC16(dA + soff, &A [(size_t)(row0 + r) * K + kk + ldk]);
            CP_ASYNC16(dB + soff, &Bt[(size_t)(col0 + r) * K + kk + ldk]);
        }
    };

    load_stage(0, 0);  CP_COMMIT();
    load_stage(1, 32); CP_COMMIT();
    load_stage(2, 64); CP_COMMIT();

    for (int i = 0; i < iters; i++) {
        CP_WAIT2();
        __syncthreads();
        if (i + 3 < iters) load_stage((i + 3) % NSTAGE, (i + 3) * 32);
        CP_COMMIT();

        const int s = i % NSTAGE;
        const uint32_t sA = sbase + s * GSTAGE_B;
        const uint32_t sB = sA + 10240;

        #pragma unroll
        for (int ks = 0; ks < 2; ks++) {
            uint32_t a[2][4];
            #pragma unroll
            for (int mt = 0; mt < 2; mt++)
                LDSM_X4(a[mt][0], a[mt][1], a[mt][2], a[mt][3],
                        sA + aoff + mt * 1280 + ks * 32);
            uint32_t b[8][2];
            #pragma unroll
            for (int np = 0; np < 4; np++) {
                uint32_t r0, r1, r2, r3;
                LDSM_X4(r0, r1, r2, r3, sB + boff + np * 1280 + ks * 32);
                b[np * 2][0]     = r0; b[np * 2][1]     = r1;
                b[np * 2 + 1][0] = r2; b[np * 2 + 1][1] = r3;
            }
            #pragma unroll
            for (int mt = 0; mt < 2; mt++)
                #pragma unroll
                for (int nt = 0; nt < 8; nt++)
                    MMA16816(acc[mt][nt], a[mt], b[nt]);
        }
    }

    // ---------------- epilogue ----------------
    const int rl0 = warp_m * 32 + (lane >> 2);
    const int ncb = col0 + warp_n * 64 + (lane & 3) * 2;

    if (MODE == 0 && col0 >= FHID) {
        // attention tile: project silu(ah) by aw2, deterministic slot reduction.
        // sred[row 128][head 4][slot 8] at smem base (stages 0/1 no longer live).
        float* sred = (float*)smem;
        const int slot = warp_n * 4 + (lane & 3);
        __syncthreads();
        #pragma unroll
        for (int mt = 0; mt < 2; mt++) {
            #pragma unroll
            for (int half = 0; half < 2; half++) {
                const int rl = rl0 + mt * 16 + half * 8;
                const int rc = row0 + rl;
                float p0 = 0.f, p1 = 0.f, p2 = 0.f, p3 = 0.f;
                if (rc < total) {
                    const int bg = g_rowidx[rc] >> 8;
                    #pragma unroll
                    for (int nt = 0; nt < 8; nt++) {
                        const int ncol = ncb + nt * 8;
                        const int a0   = ncol - FHID;
                        float v0 = silu(acc[mt][nt][half * 2]     + bias2[a0] +
                                        ctx1[(size_t)bg * NTOT1 + ncol]);
                        float v1 = silu(acc[mt][nt][half * 2 + 1] + bias2[a0 + 1] +
                                        ctx1[(size_t)bg * NTOT1 + ncol + 1]);
                        float4 w0 = ((const float4*)aw2)[a0];
                        float4 w1 = ((const float4*)aw2)[a0 + 1];
                        p0 = fmaf(v0, w0.x, fmaf(v1, w1.x, p0));
                        p1 = fmaf(v0, w0.y, fmaf(v1, w1.y, p1));
                        p2 = fmaf(v0, w0.z, fmaf(v1, w1.z, p2));
                        p3 = fmaf(v0, w0.w, fmaf(v1, w1.w, p3));
                    }
                }
                sred[(rl * 4 + 0) * 8 + slot] = p0;
                sred[(rl * 4 + 1) * 8 + slot] = p1;
                sred[(rl * 4 + 2) * 8 + slot] = p2;
                sred[(rl * 4 + 3) * 8 + slot] = p3;
            }
        }
        __syncthreads();
        const int tsel = (col0 - FHID) >> 7;     // 0 or 1
        for (int p = tid; p < 512; p += 256) {   // p = rl*4 + h
            const int rc = row0 + (p >> 2);
            if (rc < total) {
                const float* q = &sred[p * 8];
                float s = ((q[0] + q[1]) + (q[2] + q[3])) +
                          ((q[4] + q[5]) + (q[6] + q[7]));
                spart[(size_t)tsel * MROWS * NHEADS + rc * 4 + (p & 3)] = s;
            }
        }
        return;
    }

    #pragma unroll
    for (int mt = 0; mt < 2; mt++) {
        #pragma unroll
        for (int half = 0; half < 2; half++) {
            const int rc = row0 + rl0 + mt * 16 + half * 8;
            if (rc >= total) continue;
            const int orig = g_rowidx[rc];
            const int bg   = orig >> 8;
            #pragma unroll
            for (int nt = 0; nt < 8; nt++) {
                const int ncol = ncb + nt * 8;
                float v0 = acc[mt][nt][half * 2];
                float v1 = acc[mt][nt][half * 2 + 1];
                if (MODE == 0) {
                    v0 = silu(v0 + bias1[ncol]     + ctx1[(size_t)bg * NTOT1 + ncol]);
                    v1 = silu(v1 + bias1[ncol + 1] + ctx1[(size_t)bg * NTOT1 + ncol + 1]);
                    *(__half2*)&outh[(size_t)rc * FHID + ncol] =
                        __floats2half2_rn(v0, v1);
                } else {
                    float2 o;
                    o.x = v0 + bias1[ncol]     + residual[(size_t)orig * FOUT + ncol];
                    o.y = v1 + bias1[ncol + 1] + residual[(size_t)orig * FOUT + ncol + 1];
                    *(float2*)&outf[(size_t)orig * FOUT + ncol] = o;
                }
            }
        }
    }
}

// ---------------------------------------------------------------------------
// Finalize per graph: scores -> masked softmax -> pooling + masked-row copy.
// ---------------------------------------------------------------------------
__global__ void finalize_kernel(const float* __restrict__ nodes,
                                const int* __restrict__ mask,
                                const float* __restrict__ spart,
                                const float* __restrict__ ab2,
                                float* __restrict__ newn,
                                float* __restrict__ pooled)
{
    const int b = blockIdx.x, n = threadIdx.x;
    const int wid = n >> 5, lane = n & 31;
    __shared__ float  ws[NNODES * NHEADS];
    __shared__ int    ridx[NNODES];
    __shared__ int    ilist[NNODES];
    __shared__ int    icnt;
    __shared__ float4 red[NNODES];

    const int cnt = g_bcnt[b], off = g_boff[b];
    if (n == 0) icnt = 0;
    __syncthreads();
    const int valid = mask[b * NNODES + n];
    if (n < cnt) ridx[n] = g_rowidx[off + n];
    if (!valid) { int p = atomicAdd(&icnt, 1); ilist[p] = n; }

    const float NEG = -INFINITY;
    const float inv_scale = 1.0f / 16.0f;
    float v0 = NEG, v1 = NEG, v2 = NEG, v3 = NEG;
    if (n < cnt) {
        const int rc = off + n;
        float4 s0 = ((const float4*)spart)[rc];
        float4 s1 = ((const float4*)spart)[MROWS + rc];
        v0 = (s0.x + s1.x + ab2[0]) * inv_scale;
        v1 = (s0.y + s1.y + ab2[1]) * inv_scale;
        v2 = (s0.z + s1.z + ab2[2]) * inv_scale;
        v3 = (s0.w + s1.w + ab2[3]) * inv_scale;
    }

    red[n] = make_float4(v0, v1, v2, v3);
    __syncthreads();
    for (int o = 128; o > 0; o >>= 1) {
        if (n < o) {
            float4 a = red[n], c = red[n + o];
            red[n] = make_float4(fmaxf(a.x, c.x), fmaxf(a.y, c.y),
                                 fmaxf(a.z, c.z), fmaxf(a.w, c.w));
        }
        __syncthreads();
    }
    float4 mx = red[0];
    __syncthreads();

    float e0 = (n < cnt) ? __expf(v0 - mx.x) : 0.f;
    float e1 = (n < cnt) ? __expf(v1 - mx.y) : 0.f;
    float e2 = (n < cnt) ? __expf(v2 - mx.z) : 0.f;
    float e3 = (n < cnt) ? __expf(v3 - mx.w) : 0.f;

    red[n] = make_float4(e0, e1, e2, e3);
    __syncthreads();
    for (int o = 128; o > 0; o >>= 1) {
        if (n < o) {
            float4 a = red[n], c = red[n + o];
            red[n] = make_float4(a.x + c.x, a.y + c.y, a.z + c.z, a.w + c.w);
        }
        __syncthreads();
    }
    float4 sm = red[0];
    __syncthreads();

    if (n < cnt) {
        const int ln = ridx[n] & 255;
        ((float4*)ws)[ln] = make_float4(e0 / sm.x, e1 / sm.y, e2 / sm.z, e3 / sm.w);
    }
    __syncthreads();

    // pooling over valid rows
    const int h = n >> 6;
    float acc = 0.f;
    for (int i = 0; i < cnt; i++) {
        const int orig = ridx[i];
        acc = fmaf(newn[(size_t)orig * FOUT + n], ws[(orig & 255) * 4 + h], acc);
    }
    pooled[b * FOUT + n] = acc;

    // masked rows: new_nodes = nodes (one warp per row, 2 float4 per lane)
    for (int j = wid; j < icnt; j += 8) {
        const int row = b * NNODES + ilist[j];
        float4*       dst = (float4*)(newn + (size_t)row * FOUT);
        const float4* src = (const float4*)(nodes + (size_t)row * FOUT);
        dst[lane]      = src[lane];
        dst[lane + 32] = src[lane + 32];
    }
}

// ---------------------------------------------------------------------------
// Launch
// ---------------------------------------------------------------------------
extern "C" void kernel_launch(void* const* d_in, const int* in_sizes, int n_in,
                              void* d_out, int out_size)
{
    const float* nodes = (const float*)d_in[0];
    const float* pe    = (const float*)d_in[1];
    const int*   mask  = (const int*)d_in[2];
    const float* globs = (const float*)d_in[3];
    const float* ln_g  = (const float*)d_in[4];
    const float* ln_b  = (const float*)d_in[5];
    const float* fw1   = (const float*)d_in[6];
    const float* fb1   = (const float*)d_in[7];
    const float* fw2   = (const float*)d_in[8];
    const float* fb2   = (const float*)d_in[9];
    const float* aw1   = (const float*)d_in[10];
    const float* ab1   = (const float*)d_in[11];
    const float* aw2   = (const float*)d_in[12];
    const float* ab2   = (const float*)d_in[13];

    float* out_nodes  = (float*)d_out;
    float* out_pooled = out_nodes + (size_t)MROWS * FOUT;

    __half *p_inp, *p_hid, *p_w1t, *p_w2t;
    float  *p_spart, *p_ctx1;
    cudaGetSymbolAddress((void**)&p_inp,   g_inp);
    cudaGetSymbolAddress((void**)&p_hid,   g_hid);
    cudaGetSymbolAddress((void**)&p_spart, g_spart);
    cudaGetSymbolAddress((void**)&p_w1t,   g_w1t);
    cudaGetSymbolAddress((void**)&p_w2t,   g_w2t);
    cudaGetSymbolAddress((void**)&p_ctx1,  g_ctx1);

    cudaFuncSetAttribute(gemm_mma<0>, cudaFuncAttributeMaxDynamicSharedMemorySize, GSMEM);
    cudaFuncSetAttribute(gemm_mma<1>, cudaFuncAttributeMaxDynamicSharedMemorySize, GSMEM);
    cudaFuncSetAttribute(gemm_mma<0>, cudaFuncAttributePreferredSharedMemoryCarveout, 100);
    cudaFuncSetAttribute(gemm_mma<1>, cudaFuncAttributePreferredSharedMemoryCarveout, 100);

    // 1) compaction of valid rows (scatter also pads)
    count_kernel<<<512, 256>>>(mask);
    scan_kernel<<<1, 512>>>();
    scatter_kernel<<<512, 256>>>(mask);

    // 2) LN over compact rows -> g_inp dense; ctx; weight transposes
    prep_kernel<<<MROWS, 128>>>(nodes, pe, ln_g, ln_b, p_inp);
    ctx_kernel<<<BATCH, 256>>>(globs, fw1, aw1, p_ctx1);
    wtrans_kernel<<<dim3(40, 16), dim3(32, 8)>>>(fw1, FHID, FHID, aw1, AHID, AHID,
                                                 FEAT_IN, p_w1t);
    wtrans_kernel<<<dim3(8, 32),  dim3(32, 8)>>>(fw2, FOUT, FOUT, nullptr, 0, 0,
                                                 FHID, p_w2t);

    // 3) GEMM1 on compact rows: hid tiles -> g_hid; attn tiles -> score partials
    gemm_mma<0><<<dim3(NTOT1 / 128, MROWS / 128), 256, GSMEM>>>(
        p_inp, p_w1t, FEAT_IN, fb1, ab1, p_ctx1, aw2, p_hid, p_spart,
        nullptr, nullptr);

    // 4) GEMM3 on compact rows, scatter +bias+residual -> new_nodes
    gemm_mma<1><<<dim3(FOUT / 128, MROWS / 128), 256, GSMEM>>>(
        p_hid, p_w2t, FHID, fb2, nullptr, nullptr, nullptr, nullptr, nullptr,
        out_nodes, nodes);

    // 5) finalize: softmax + pooling + masked-row copy
    finalize_kernel<<<BATCH, NNODES>>>(nodes, mask, p_spart, ab2,
                                       out_nodes, out_pooled);
}

// round 15
// speedup vs baseline: 2.1355x; 1.0079x over previous
#include <cuda_runtime.h>
#include <cuda_fp16.h>
#include <math.h>
#include <stdint.h>

// Problem constants
#define BATCH   512
#define NNODES  256
#define MROWS   (BATCH * NNODES)     // 131072
#define FEAT_IN 512
#define GLOB_D  64
#define FHID    1024
#define AHID    256
#define FOUT    256
#define NTOT1   (FHID + AHID)        // 1280
#define NHEADS  4
#define LN_EPS  1e-5f

// ---------------------------------------------------------------------------
// Scratch (device globals; no runtime allocation)
// ---------------------------------------------------------------------------
__device__ __half g_inp[(size_t)MROWS * FEAT_IN];      // fp16 LN output (COMPACT rows)
__device__ __half g_hid[(size_t)MROWS * FHID];         // fp16 silu hidden (COMPACT rows)
__device__ float  g_spart[(size_t)2 * MROWS * NHEADS]; // per-tile score partials
__device__ __half g_w1t[(size_t)NTOT1 * FEAT_IN];      // [1280,512] (fw1||aw1)^T fp16
__device__ __half g_w2t[(size_t)FOUT * FHID];          // [256,1024] fw2^T fp16
__device__ float  g_ctx1[(size_t)BATCH * NTOT1];       // per-graph ctx contribution
__device__ int    g_rowidx[MROWS];                     // compact -> original row
__device__ int    g_bcnt[512];                         // per-graph valid count
__device__ int    g_boff[512];                         // per-graph compact offset
__device__ int    g_meta[2];                           // [0]=total valid, [1]=padded

// ---------------------------------------------------------------------------
// PTX helpers (baseline ISA: works at compute_103 target)
// ---------------------------------------------------------------------------
__device__ __forceinline__ uint32_t smem_u32(const void* p) {
    uint32_t a;
    asm("{ .reg .u64 t; cvta.to.shared.u64 t, %1; cvt.u32.u64 %0, t; }"
        : "=r"(a) : "l"(p));
    return a;
}

#define CP_ASYNC16(dst, src) \
    asm volatile("cp.async.cg.shared.global [%0], [%1], 16;" \
        :: "r"(dst), "l"(src))
#define CP_COMMIT()  asm volatile("cp.async.commit_group;" ::: "memory")
#define CP_WAIT2()   asm volatile("cp.async.wait_group 2;" ::: "memory")

#define LDSM_X4(r0, r1, r2, r3, addr) \
    asm volatile("ldmatrix.sync.aligned.m8n8.x4.shared.b16 {%0,%1,%2,%3}, [%4];" \
        : "=r"(r0), "=r"(r1), "=r"(r2), "=r"(r3) : "r"(addr))

#define MMA16816(c, a, b) \
    asm volatile("mma.sync.aligned.m16n8k16.row.col.f32.f16.f16.f32 " \
        "{%0,%1,%2,%3}, {%4,%5,%6,%7}, {%8,%9}, {%0,%1,%2,%3};" \
        : "+f"((c)[0]), "+f"((c)[1]), "+f"((c)[2]), "+f"((c)[3]) \
        : "r"((a)[0]), "r"((a)[1]), "r"((a)[2]), "r"((a)[3]), \
          "r"((b)[0]), "r"((b)[1]))

__device__ __forceinline__ float warp_sum(float v) {
    #pragma unroll
    for (int o = 16; o > 0; o >>= 1) v += __shfl_xor_sync(0xffffffffu, v, o);
    return v;
}

__device__ __forceinline__ float silu(float v) {
    return __fdividef(v, 1.0f + __expf(-v));
}

// ---------------------------------------------------------------------------
// Compaction: count -> scan -> scatter(+pad)
// ---------------------------------------------------------------------------
__global__ void count_kernel(const int* __restrict__ mask)
{
    const int t = threadIdx.x, lane = t & 31, wid = t >> 5;
    const int r = blockIdx.x * 256 + t;
    __shared__ int ws[8];
    unsigned bal = __ballot_sync(0xffffffffu, mask[r] != 0);
    if (lane == 0) ws[wid] = __popc(bal);
    __syncthreads();
    if (t == 0) {
        int s = 0;
        #pragma unroll
        for (int i = 0; i < 8; i++) s += ws[i];
        g_bcnt[blockIdx.x] = s;
    }
}

__global__ void scan_kernel()
{
    __shared__ int s[512];
    const int t = threadIdx.x;
    const int c = g_bcnt[t];
    s[t] = c;
    __syncthreads();
    for (int off = 1; off < 512; off <<= 1) {
        int v = (t >= off) ? s[t - off] : 0;
        __syncthreads();
        s[t] += v;
        __syncthreads();
    }
    g_boff[t] = s[t] - c;
    if (t == 511) {
        g_meta[0] = s[511];
        g_meta[1] = ((s[511] + 127) >> 7) << 7;
    }
}

__global__ void scatter_kernel(const int* __restrict__ mask)
{
    const int t = threadIdx.x, lane = t & 31, wid = t >> 5;
    const int r = blockIdx.x * 256 + t;
    __shared__ int ws[8];
    const int v = mask[r] != 0;
    unsigned bal = __ballot_sync(0xffffffffu, v);
    if (lane == 0) ws[wid] = __popc(bal);
    __syncthreads();
    int wpre = 0;
    #pragma unroll
    for (int i = 0; i < 8; i++) if (i < wid) wpre += ws[i];
    if (v) {
        int pos = g_boff[blockIdx.x] + wpre + __popc(bal & ((1u << lane) - 1));
        g_rowidx[pos] = r;
    }
    // block 511 also pads [total, npad) — disjoint from scatter writes
    if (blockIdx.x == 511) {
        const int total = g_meta[0], npad = g_meta[1];
        for (int i = total + t; i < npad; i += 256) g_rowidx[i] = 0;
    }
}

// ---------------------------------------------------------------------------
// LayerNorm over COMPACT valid rows — persistent grid-stride (128 thr/blk,
// one row per iteration). Gathers orig row via rowidx, writes dense fp16.
// ---------------------------------------------------------------------------
#define PREP_GRID 2048

__global__ void prep_kernel(const float* __restrict__ nodes,
                            const float* __restrict__ pe,
                            const float* __restrict__ ln_g,
                            const float* __restrict__ ln_b,
                            __half* __restrict__ inp)
{
    const int t    = threadIdx.x;         // 0..127
    const int lane = t & 31, wid = t >> 5;
    const int total = g_meta[0];

    __shared__ float ssum[4], ssq[4];
    __shared__ float s_mu, s_rstd;

    // per-thread LN params are loop-invariant
    const float4 g4 = ((const float4*)ln_g)[t];
    const float4 b4 = ((const float4*)ln_b)[t];

    for (int rc = blockIdx.x; rc < total; rc += PREP_GRID) {
        const int row = g_rowidx[rc];

        float4 v = (t < 64)
            ? ((const float4*)nodes)[(size_t)row * 64 + t]
            : ((const float4*)pe)   [(size_t)row * 64 + (t - 64)];

        float s  = v.x + v.y + v.z + v.w;
        float sq = v.x*v.x + v.y*v.y + v.z*v.z + v.w*v.w;
        float ws = warp_sum(s), wq = warp_sum(sq);
        if (lane == 0) { ssum[wid] = ws; ssq[wid] = wq; }
        __syncthreads();
        if (t == 0) {
            float S = ssum[0] + ssum[1] + ssum[2] + ssum[3];
            float Q = ssq[0]  + ssq[1]  + ssq[2]  + ssq[3];
            float mu  = S * (1.0f / FEAT_IN);
            float var = Q * (1.0f / FEAT_IN) - mu * mu;
            s_mu = mu; s_rstd = rsqrtf(var + LN_EPS);
        }
        __syncthreads();
        const float mu = s_mu, rstd = s_rstd;

        float o0 = (v.x - mu) * rstd * g4.x + b4.x;
        float o1 = (v.y - mu) * rstd * g4.y + b4.y;
        float o2 = (v.z - mu) * rstd * g4.z + b4.z;
        float o3 = (v.w - mu) * rstd * g4.w + b4.w;

        __half* dst = inp + (size_t)rc * FEAT_IN + t * 4;
        *(__half2*)(dst)     = __floats2half2_rn(o0, o1);
        *(__half2*)(dst + 2) = __floats2half2_rn(o2, o3);
    }
}

// ---------------------------------------------------------------------------
// Per-graph ctx contribution: ctx1[b,n] = sum_j globs[b,j] * W[512+j, n]
// ---------------------------------------------------------------------------
__global__ void ctx_kernel(const float* __restrict__ globs,
                           const float* __restrict__ fw1,
                           const float* __restrict__ aw1,
                           float* __restrict__ ctx1)
{
    __shared__ float gs[GLOB_D];
    const int b = blockIdx.x;
    if (threadIdx.x < GLOB_D) gs[threadIdx.x] = globs[b * GLOB_D + threadIdx.x];
    __syncthreads();
    for (int n = threadIdx.x; n < NTOT1; n += blockDim.x) {
        float acc = 0.f;
        if (n < FHID) {
            #pragma unroll 8
            for (int j = 0; j < GLOB_D; j++)
                acc = fmaf(gs[j], fw1[(size_t)(FEAT_IN + j) * FHID + n], acc);
        } else {
            #pragma unroll 8
            for (int j = 0; j < GLOB_D; j++)
                acc = fmaf(gs[j], aw1[(size_t)(FEAT_IN + j) * AHID + (n - FHID)], acc);
        }
        ctx1[(size_t)b * NTOT1 + n] = acc;
    }
}

// ---------------------------------------------------------------------------
// Weight transpose + fp16 cast
// ---------------------------------------------------------------------------
__global__ void wtrans_kernel(const float* __restrict__ W1, int N1, int ld1,
                              const float* __restrict__ W2, int N2, int ld2,
                              int K, __half* __restrict__ Wt)
{
    __shared__ float tile[32][33];
    const int nb = blockIdx.x * 32, kb = blockIdx.y * 32;
    const int tx = threadIdx.x, ty = threadIdx.y;
    const int Ntot = N1 + N2;
    for (int i = ty; i < 32; i += 8) {
        int k = kb + i, n = nb + tx;
        float v = 0.f;
        if (k < K && n < Ntot)
            v = (n < N1) ? W1[(size_t)k * ld1 + n] : W2[(size_t)k * ld2 + (n - N1)];
        tile[i][tx] = v;
    }
    __syncthreads();
    for (int i = ty; i < 32; i += 8) {
        int n = nb + i, k = kb + tx;
        if (n < Ntot && k < K)
            Wt[(size_t)n * K + k] = __float2half_rn(tile[tx][i]);
    }
}

// ---------------------------------------------------------------------------
// HGEMM via mma.sync m16n8k16 over COMPACTED valid rows (dense A).
// CTA tile 128x128, BK=32, 4-stage cp.async pipeline, 8 warps (4m x 2n).
// MODE 0 (GEMM1), col tiles <1024: silu(x+bias+ctx) -> fp16 outh (dense).
// MODE 0, col tiles >=1024 (attn): silu(x+ab1+ctx) projected by aw2 in-register,
//   deterministic slot-based smem reduction -> g_spart[tile][rc][4]. No gmem ah.
// MODE 1 (GEMM3): x+bias1+residual[orig] -> outf[orig] (scatter).
// ---------------------------------------------------------------------------
#define NSTAGE    4
#define GSTAGE_B  20480               // (128*40*2) * 2 tiles
#define GSMEM     (NSTAGE * GSTAGE_B) // 81920

template<int MODE>
__global__ __launch_bounds__(256, 2) void gemm_mma(
    const __half* __restrict__ A, const __half* __restrict__ Bt, int K,
    const float* __restrict__ bias1, const float* __restrict__ bias2,
    const float* __restrict__ ctx1, const float* __restrict__ aw2,
    __half* __restrict__ outh, float* __restrict__ spart,
    float* __restrict__ outf, const float* __restrict__ residual)
{
    const int total = g_meta[0];
    const int npad  = g_meta[1];
    const int row0  = blockIdx.y * 128;
    if (row0 >= npad) return;

    extern __shared__ char smem[];
    const uint32_t sbase = smem_u32(smem);
    const int tid    = threadIdx.x;
    const int wid    = tid >> 5;
    const int lane   = tid & 31;
    const int warp_m = wid & 3;
    const int warp_n = wid >> 2;
    const int col0   = blockIdx.x * 128;
    const int iters  = K >> 5;

    const int ldr = tid >> 2;
    const int ldk = (tid & 3) * 8;

    float acc[2][8][4];
    #pragma unroll
    for (int mt = 0; mt < 2; mt++)
        #pragma unroll
        for (int nt = 0; nt < 8; nt++)
            #pragma unroll
            for (int j = 0; j < 4; j++) acc[mt][nt][j] = 0.f;

    const int lm = lane & 15, lq = lane >> 4;
    const uint32_t aoff = ((warp_m * 32 + lm) * 40 + lq * 8) * 2;
    const int bn = (lane >> 4) * 8 + (lane & 7);
    const int bk = ((lane >> 3) & 1) * 8;
    const uint32_t boff = ((warp_n * 64 + bn) * 40 + bk) * 2;

    auto load_stage = [&](int s, int kk) {
        const uint32_t dA = sbase + s * GSTAGE_B;
        const uint32_t dB = dA + 10240;
        #pragma unroll
        for (int i = 0; i < 2; i++) {
            const int r = ldr + i * 64;
            const uint32_t soff = (r * 40 + ldk) * 2;
            CP_ASYNC16(dA + soff, &A [(size_t)(row0 + r) * K + kk + ldk]);
            CP_ASYNC16(dB + soff, &Bt[(size_t)(col0 + r) * K + kk + ldk]);
        }
    };

    load_stage(0, 0);  CP_COMMIT();
    load_stage(1, 32); CP_COMMIT();
    load_stage(2, 64); CP_COMMIT();

    for (int i = 0; i < iters; i++) {
        CP_WAIT2();
        __syncthreads();
        if (i + 3 < iters) load_stage((i + 3) % NSTAGE, (i + 3) * 32);
        CP_COMMIT();

        const int s = i % NSTAGE;
        const uint32_t sA = sbase + s * GSTAGE_B;
        const uint32_t sB = sA + 10240;

        #pragma unroll
        for (int ks = 0; ks < 2; ks++) {
            uint32_t a[2][4];
            #pragma unroll
            for (int mt = 0; mt < 2; mt++)
                LDSM_X4(a[mt][0], a[mt][1], a[mt][2], a[mt][3],
                        sA + aoff + mt * 1280 + ks * 32);
            uint32_t b[8][2];
            #pragma unroll
            for (int np = 0; np < 4; np++) {
                uint32_t r0, r1, r2, r3;
                LDSM_X4(r0, r1, r2, r3, sB + boff + np * 1280 + ks * 32);
                b[np * 2][0]     = r0; b[np * 2][1]     = r1;
                b[np * 2 + 1][0] = r2; b[np * 2 + 1][1] = r3;
            }
            #pragma unroll
            for (int mt = 0; mt < 2; mt++)
                #pragma unroll
                for (int nt = 0; nt < 8; nt++)
                    MMA16816(acc[mt][nt], a[mt], b[nt]);
        }
    }

    // ---------------- epilogue ----------------
    const int rl0 = warp_m * 32 + (lane >> 2);
    const int ncb = col0 + warp_n * 64 + (lane & 3) * 2;

    if (MODE == 0 && col0 >= FHID) {
        // attention tile: project silu(ah) by aw2, deterministic slot reduction.
        float* sred = (float*)smem;
        const int slot = warp_n * 4 + (lane & 3);
        __syncthreads();
        #pragma unroll
        for (int mt = 0; mt < 2; mt++) {
            #pragma unroll
            for (int half = 0; half < 2; half++) {
                const int rl = rl0 + mt * 16 + half * 8;
                const int rc = row0 + rl;
                float p0 = 0.f, p1 = 0.f, p2 = 0.f, p3 = 0.f;
                if (rc < total) {
                    const int bg = g_rowidx[rc] >> 8;
                    #pragma unroll
                    for (int nt = 0; nt < 8; nt++) {
                        const int ncol = ncb + nt * 8;
                        const int a0   = ncol - FHID;
                        float v0 = silu(acc[mt][nt][half * 2]     + bias2[a0] +
                                        ctx1[(size_t)bg * NTOT1 + ncol]);
                        float v1 = silu(acc[mt][nt][half * 2 + 1] + bias2[a0 + 1] +
                                        ctx1[(size_t)bg * NTOT1 + ncol + 1]);
                        float4 w0 = ((const float4*)aw2)[a0];
                        float4 w1 = ((const float4*)aw2)[a0 + 1];
                        p0 = fmaf(v0, w0.x, fmaf(v1, w1.x, p0));
                        p1 = fmaf(v0, w0.y, fmaf(v1, w1.y, p1));
                        p2 = fmaf(v0, w0.z, fmaf(v1, w1.z, p2));
                        p3 = fmaf(v0, w0.w, fmaf(v1, w1.w, p3));
                    }
                }
                sred[(rl * 4 + 0) * 8 + slot] = p0;
                sred[(rl * 4 + 1) * 8 + slot] = p1;
                sred[(rl * 4 + 2) * 8 + slot] = p2;
                sred[(rl * 4 + 3) * 8 + slot] = p3;
            }
        }
        __syncthreads();
        const int tsel = (col0 - FHID) >> 7;     // 0 or 1
        for (int p = tid; p < 512; p += 256) {   // p = rl*4 + h
            const int rc = row0 + (p >> 2);
            if (rc < total) {
                const float* q = &sred[p * 8];
                float s = ((q[0] + q[1]) + (q[2] + q[3])) +
                          ((q[4] + q[5]) + (q[6] + q[7]));
                spart[(size_t)tsel * MROWS * NHEADS + rc * 4 + (p & 3)] = s;
            }
        }
        return;
    }

    #pragma unroll
    for (int mt = 0; mt < 2; mt++) {
        #pragma unroll
        for (int half = 0; half < 2; half++) {
            const int rc = row0 + rl0 + mt * 16 + half * 8;
            if (rc >= total) continue;
            const int orig = g_rowidx[rc];
            const int bg   = orig >> 8;
            #pragma unroll
            for (int nt = 0; nt < 8; nt++) {
                const int ncol = ncb + nt * 8;
                float v0 = acc[mt][nt][half * 2];
                float v1 = acc[mt][nt][half * 2 + 1];
                if (MODE == 0) {
                    v0 = silu(v0 + bias1[ncol]     + ctx1[(size_t)bg * NTOT1 + ncol]);
                    v1 = silu(v1 + bias1[ncol + 1] + ctx1[(size_t)bg * NTOT1 + ncol + 1]);
                    *(__half2*)&outh[(size_t)rc * FHID + ncol] =
                        __floats2half2_rn(v0, v1);
                } else {
                    float2 o;
                    o.x = v0 + bias1[ncol]     + residual[(size_t)orig * FOUT + ncol];
                    o.y = v1 + bias1[ncol + 1] + residual[(size_t)orig * FOUT + ncol + 1];
                    *(float2*)&outf[(size_t)orig * FOUT + ncol] = o;
                }
            }
        }
    }
}

// ---------------------------------------------------------------------------
// Finalize per graph: scores -> masked softmax -> pooling + masked-row copy.
// ---------------------------------------------------------------------------
__global__ void finalize_kernel(const float* __restrict__ nodes,
                                const int* __restrict__ mask,
                                const float* __restrict__ spart,
                                const float* __restrict__ ab2,
                                float* __restrict__ newn,
                                float* __restrict__ pooled)
{
    const int b = blockIdx.x, n = threadIdx.x;
    const int wid = n >> 5, lane = n & 31;
    __shared__ float  ws[NNODES * NHEADS];
    __shared__ int    ridx[NNODES];
    __shared__ int    ilist[NNODES];
    __shared__ int    icnt;
    __shared__ float4 red[NNODES];

    const int cnt = g_bcnt[b], off = g_boff[b];
    if (n == 0) icnt = 0;
    __syncthreads();
    const int valid = mask[b * NNODES + n];
    if (n < cnt) ridx[n] = g_rowidx[off + n];
    if (!valid) { int p = atomicAdd(&icnt, 1); ilist[p] = n; }

    const float NEG = -INFINITY;
    const float inv_scale = 1.0f / 16.0f;
    float v0 = NEG, v1 = NEG, v2 = NEG, v3 = NEG;
    if (n < cnt) {
        const int rc = off + n;
        float4 s0 = ((const float4*)spart)[rc];
        float4 s1 = ((const float4*)spart)[MROWS + rc];
        v0 = (s0.x + s1.x + ab2[0]) * inv_scale;
        v1 = (s0.y + s1.y + ab2[1]) * inv_scale;
        v2 = (s0.z + s1.z + ab2[2]) * inv_scale;
        v3 = (s0.w + s1.w + ab2[3]) * inv_scale;
    }

    red[n] = make_float4(v0, v1, v2, v3);
    __syncthreads();
    for (int o = 128; o > 0; o >>= 1) {
        if (n < o) {
            float4 a = red[n], c = red[n + o];
            red[n] = make_float4(fmaxf(a.x, c.x), fmaxf(a.y, c.y),
                                 fmaxf(a.z, c.z), fmaxf(a.w, c.w));
        }
        __syncthreads();
    }
    float4 mx = red[0];
    __syncthreads();

    float e0 = (n < cnt) ? __expf(v0 - mx.x) : 0.f;
    float e1 = (n < cnt) ? __expf(v1 - mx.y) : 0.f;
    float e2 = (n < cnt) ? __expf(v2 - mx.z) : 0.f;
    float e3 = (n < cnt) ? __expf(v3 - mx.w) : 0.f;

    red[n] = make_float4(e0, e1, e2, e3);
    __syncthreads();
    for (int o = 128; o > 0; o >>= 1) {
        if (n < o) {
            float4 a = red[n], c = red[n + o];
            red[n] = make_float4(a.x + c.x, a.y + c.y, a.z + c.z, a.w + c.w);
        }
        __syncthreads();
    }
    float4 sm = red[0];
    __syncthreads();

    if (n < cnt) {
        const int ln = ridx[n] & 255;
        ((float4*)ws)[ln] = make_float4(e0 / sm.x, e1 / sm.y, e2 / sm.z, e3 / sm.w);
    }
    __syncthreads();

    // pooling over valid rows
    const int h = n >> 6;
    float acc = 0.f;
    for (int i = 0; i < cnt; i++) {
        const int orig = ridx[i];
        acc = fmaf(newn[(size_t)orig * FOUT + n], ws[(orig & 255) * 4 + h], acc);
    }
    pooled[b * FOUT + n] = acc;

    // masked rows: new_nodes = nodes (one warp per row, 2 float4 per lane)
    for (int j = wid; j < icnt; j += 8) {
        const int row = b * NNODES + ilist[j];
        float4*       dst = (float4*)(newn + (size_t)row * FOUT);
        const float4* src = (const float4*)(nodes + (size_t)row * FOUT);
        dst[lane]      = src[lane];
        dst[lane + 32] = src[lane + 32];
    }
}

// ---------------------------------------------------------------------------
// Launch
// ---------------------------------------------------------------------------
extern "C" void kernel_launch(void* const* d_in, const int* in_sizes, int n_in,
                              void* d_out, int out_size)
{
    const float* nodes = (const float*)d_in[0];
    const float* pe    = (const float*)d_in[1];
    const int*   mask  = (const int*)d_in[2];
    const float* globs = (const float*)d_in[3];
    const float* ln_g  = (const float*)d_in[4];
    const float* ln_b  = (const float*)d_in[5];
    const float* fw1   = (const float*)d_in[6];
    const float* fb1   = (const float*)d_in[7];
    const float* fw2   = (const float*)d_in[8];
    const float* fb2   = (const float*)d_in[9];
    const float* aw1   = (const float*)d_in[10];
    const float* ab1   = (const float*)d_in[11];
    const float* aw2   = (const float*)d_in[12];
    const float* ab2   = (const float*)d_in[13];

    float* out_nodes  = (float*)d_out;
    float* out_pooled = out_nodes + (size_t)MROWS * FOUT;

    __half *p_inp, *p_hid, *p_w1t, *p_w2t;
    float  *p_spart, *p_ctx1;
    cudaGetSymbolAddress((void**)&p_inp,   g_inp);
    cudaGetSymbolAddress((void**)&p_hid,   g_hid);
    cudaGetSymbolAddress((void**)&p_spart, g_spart);
    cudaGetSymbolAddress((void**)&p_w1t,   g_w1t);
    cudaGetSymbolAddress((void**)&p_w2t,   g_w2t);
    cudaGetSymbolAddress((void**)&p_ctx1,  g_ctx1);

    cudaFuncSetAttribute(gemm_mma<0>, cudaFuncAttributeMaxDynamicSharedMemorySize, GSMEM);
    cudaFuncSetAttribute(gemm_mma<1>, cudaFuncAttributeMaxDynamicSharedMemorySize, GSMEM);
    cudaFuncSetAttribute(gemm_mma<0>, cudaFuncAttributePreferredSharedMemoryCarveout, 100);
    cudaFuncSetAttribute(gemm_mma<1>, cudaFuncAttributePreferredSharedMemoryCarveout, 100);

    // 1) compaction of valid rows (scatter also pads)
    count_kernel<<<512, 256>>>(mask);
    scan_kernel<<<1, 512>>>();
    scatter_kernel<<<512, 256>>>(mask);

    // 2) LN over compact rows (grid-stride) -> g_inp dense; ctx; transposes
    prep_kernel<<<PREP_GRID, 128>>>(nodes, pe, ln_g, ln_b, p_inp);
    ctx_kernel<<<BATCH, 256>>>(globs, fw1, aw1, p_ctx1);
    wtrans_kernel<<<dim3(40, 16), dim3(32, 8)>>>(fw1, FHID, FHID, aw1, AHID, AHID,
                                                 FEAT_IN, p_w1t);
    wtrans_kernel<<<dim3(8, 32),  dim3(32, 8)>>>(fw2, FOUT, FOUT, nullptr, 0, 0,
                                                 FHID, p_w2t);

    // 3) GEMM1 on compact rows: hid tiles -> g_hid; attn tiles -> score partials
    gemm_mma<0><<<dim3(NTOT1 / 128, MROWS / 128), 256, GSMEM>>>(
        p_inp, p_w1t, FEAT_IN, fb1, ab1, p_ctx1, aw2, p_hid, p_spart,
        nullptr, nullptr);

    // 4) GEMM3 on compact rows, scatter +bias+residual -> new_nodes
    gemm_mma<1><<<dim3(FOUT / 128, MROWS / 128), 256, GSMEM>>>(
        p_hid, p_w2t, FHID, fb2, nullptr, nullptr, nullptr, nullptr, nullptr,
        out_nodes, nodes);

    // 5) finalize: softmax + pooling + masked-row copy
    finalize_kernel<<<BATCH, NNODES>>>(nodes, mask, p_spart, ab2,
                                       out_nodes, out_pooled);
}

// round 16
// speedup vs baseline: 2.2846x; 1.0698x over previous
#include <cuda_runtime.h>
#include <cuda_fp16.h>
#include <math.h>
#include <stdint.h>

// Problem constants
#define BATCH   512
#define NNODES  256
#define MROWS   (BATCH * NNODES)     // 131072
#define FEAT_IN 512
#define GLOB_D  64
#define FHID    1024
#define AHID    256
#define FOUT    256
#define NTOT1   (FHID + AHID)        // 1280
#define NHEADS  4
#define LN_EPS  1e-5f

// ---------------------------------------------------------------------------
// Scratch (device globals; no runtime allocation)
// ---------------------------------------------------------------------------
__device__ __half g_inp[(size_t)MROWS * FEAT_IN];      // fp16 LN output (COMPACT rows)
__device__ __half g_hid[(size_t)MROWS * FHID];         // fp16 silu hidden (COMPACT rows)
__device__ float  g_spart[(size_t)2 * MROWS * NHEADS]; // per-tile score partials
__device__ __half g_w1t[(size_t)NTOT1 * FEAT_IN];      // [1280,512] (fw1||aw1)^T fp16
__device__ __half g_w2t[(size_t)FOUT * FHID];          // [256,1024] fw2^T fp16
__device__ float  g_ctx1[(size_t)BATCH * NTOT1];       // per-graph ctx contribution
__device__ int    g_rowidx[MROWS];                     // compact -> original row
__device__ int    g_bcnt[512];                         // per-graph valid count
__device__ int    g_boff[512];                         // per-graph compact offset
__device__ int    g_meta[2];                           // [0]=total valid, [1]=padded

// ---------------------------------------------------------------------------
// PTX helpers (baseline ISA: works at compute_103 target)
// ---------------------------------------------------------------------------
__device__ __forceinline__ uint32_t smem_u32(const void* p) {
    uint32_t a;
    asm("{ .reg .u64 t; cvta.to.shared.u64 t, %1; cvt.u32.u64 %0, t; }"
        : "=r"(a) : "l"(p));
    return a;
}

#define CP_ASYNC16(dst, src) \
    asm volatile("cp.async.cg.shared.global [%0], [%1], 16;" \
        :: "r"(dst), "l"(src))
#define CP_COMMIT()  asm volatile("cp.async.commit_group;" ::: "memory")
#define CP_WAIT2()   asm volatile("cp.async.wait_group 2;" ::: "memory")

#define LDSM_X4(r0, r1, r2, r3, addr) \
    asm volatile("ldmatrix.sync.aligned.m8n8.x4.shared.b16 {%0,%1,%2,%3}, [%4];" \
        : "=r"(r0), "=r"(r1), "=r"(r2), "=r"(r3) : "r"(addr))

#define MMA16816(c, a, b) \
    asm volatile("mma.sync.aligned.m16n8k16.row.col.f32.f16.f16.f32 " \
        "{%0,%1,%2,%3}, {%4,%5,%6,%7}, {%8,%9}, {%0,%1,%2,%3};" \
        : "+f"((c)[0]), "+f"((c)[1]), "+f"((c)[2]), "+f"((c)[3]) \
        : "r"((a)[0]), "r"((a)[1]), "r"((a)[2]), "r"((a)[3]), \
          "r"((b)[0]), "r"((b)[1]))

__device__ __forceinline__ float warp_sum(float v) {
    #pragma unroll
    for (int o = 16; o > 0; o >>= 1) v += __shfl_xor_sync(0xffffffffu, v, o);
    return v;
}

__device__ __forceinline__ float silu(float v) {
    return __fdividef(v, 1.0f + __expf(-v));
}

// ---------------------------------------------------------------------------
// Compaction: count -> scan -> scatter(+pad)
// ---------------------------------------------------------------------------
__global__ void count_kernel(const int* __restrict__ mask)
{
    const int t = threadIdx.x, lane = t & 31, wid = t >> 5;
    const int r = blockIdx.x * 256 + t;
    __shared__ int ws[8];
    unsigned bal = __ballot_sync(0xffffffffu, mask[r] != 0);
    if (lane == 0) ws[wid] = __popc(bal);
    __syncthreads();
    if (t == 0) {
        int s = 0;
        #pragma unroll
        for (int i = 0; i < 8; i++) s += ws[i];
        g_bcnt[blockIdx.x] = s;
    }
}

__global__ void scan_kernel()
{
    __shared__ int s[512];
    const int t = threadIdx.x;
    const int c = g_bcnt[t];
    s[t] = c;
    __syncthreads();
    for (int off = 1; off < 512; off <<= 1) {
        int v = (t >= off) ? s[t - off] : 0;
        __syncthreads();
        s[t] += v;
        __syncthreads();
    }
    g_boff[t] = s[t] - c;
    if (t == 511) {
        g_meta[0] = s[511];
        g_meta[1] = ((s[511] + 127) >> 7) << 7;
    }
}

__global__ void scatter_kernel(const int* __restrict__ mask)
{
    const int t = threadIdx.x, lane = t & 31, wid = t >> 5;
    const int r = blockIdx.x * 256 + t;
    __shared__ int ws[8];
    const int v = mask[r] != 0;
    unsigned bal = __ballot_sync(0xffffffffu, v);
    if (lane == 0) ws[wid] = __popc(bal);
    __syncthreads();
    int wpre = 0;
    #pragma unroll
    for (int i = 0; i < 8; i++) if (i < wid) wpre += ws[i];
    if (v) {
        int pos = g_boff[blockIdx.x] + wpre + __popc(bal & ((1u << lane) - 1));
        g_rowidx[pos] = r;
    }
    // block 511 also pads [total, npad) — disjoint from scatter writes
    if (blockIdx.x == 511) {
        const int total = g_meta[0], npad = g_meta[1];
        for (int i = total + t; i < npad; i += 256) g_rowidx[i] = 0;
    }
}

// ---------------------------------------------------------------------------
// LayerNorm, warp-per-row (no block barriers in the loop). Each warp loads a
// full 512-float row (4 x float4 per lane), shuffles the moments, normalizes
// with ln params staged in smem, writes dense fp16 at compact position.
// ---------------------------------------------------------------------------
#define PREP_GRID 1024

__global__ void prep_kernel(const float* __restrict__ nodes,
                            const float* __restrict__ pe,
                            const float* __restrict__ ln_g,
                            const float* __restrict__ ln_b,
                            __half* __restrict__ inp)
{
    __shared__ float sg[FEAT_IN], sb[FEAT_IN];
    for (int i = threadIdx.x; i < FEAT_IN; i += 256) {
        sg[i] = ln_g[i];
        sb[i] = ln_b[i];
    }
    __syncthreads();

    const int lane   = threadIdx.x & 31;
    const int gwarp  = blockIdx.x * 8 + (threadIdx.x >> 5);
    const int nwarps = PREP_GRID * 8;
    const int total  = g_meta[0];

    for (int rc = gwarp; rc < total; rc += nwarps) {
        const int row = g_rowidx[rc];
        const float4* nrow = (const float4*)nodes + (size_t)row * 64;
        const float4* prow = (const float4*)pe    + (size_t)row * 64;

        float4 a[4];
        a[0] = nrow[lane];
        a[1] = nrow[lane + 32];
        a[2] = prow[lane];
        a[3] = prow[lane + 32];

        float s = 0.f, q = 0.f;
        #pragma unroll
        for (int i = 0; i < 4; i++) {
            s += a[i].x + a[i].y + a[i].z + a[i].w;
            q += a[i].x*a[i].x + a[i].y*a[i].y + a[i].z*a[i].z + a[i].w*a[i].w;
        }
        s = warp_sum(s);
        q = warp_sum(q);
        const float mu   = s * (1.0f / FEAT_IN);
        const float var  = q * (1.0f / FEAT_IN) - mu * mu;
        const float rstd = rsqrtf(var + LN_EPS);

        __half* dst = inp + (size_t)rc * FEAT_IN;
        #pragma unroll
        for (int i = 0; i < 4; i++) {
            const int e4 = (i < 2) ? (lane + i * 32) : (64 + lane + (i - 2) * 32);
            float4 g4 = ((const float4*)sg)[e4];
            float4 b4 = ((const float4*)sb)[e4];
            float o0 = (a[i].x - mu) * rstd * g4.x + b4.x;
            float o1 = (a[i].y - mu) * rstd * g4.y + b4.y;
            float o2 = (a[i].z - mu) * rstd * g4.z + b4.z;
            float o3 = (a[i].w - mu) * rstd * g4.w + b4.w;
            __half2 h0 = __floats2half2_rn(o0, o1);
            __half2 h1 = __floats2half2_rn(o2, o3);
            *(__half2*)(dst + e4 * 4)     = h0;
            *(__half2*)(dst + e4 * 4 + 2) = h1;
        }
    }
}

// ---------------------------------------------------------------------------
// Per-graph ctx contribution: ctx1[b,n] = sum_j globs[b,j] * W[512+j, n]
// ---------------------------------------------------------------------------
__global__ void ctx_kernel(const float* __restrict__ globs,
                           const float* __restrict__ fw1,
                           const float* __restrict__ aw1,
                           float* __restrict__ ctx1)
{
    __shared__ float gs[GLOB_D];
    const int b = blockIdx.x;
    if (threadIdx.x < GLOB_D) gs[threadIdx.x] = globs[b * GLOB_D + threadIdx.x];
    __syncthreads();
    for (int n = threadIdx.x; n < NTOT1; n += blockDim.x) {
        float acc = 0.f;
        if (n < FHID) {
            #pragma unroll 8
            for (int j = 0; j < GLOB_D; j++)
                acc = fmaf(gs[j], fw1[(size_t)(FEAT_IN + j) * FHID + n], acc);
        } else {
            #pragma unroll 8
            for (int j = 0; j < GLOB_D; j++)
                acc = fmaf(gs[j], aw1[(size_t)(FEAT_IN + j) * AHID + (n - FHID)], acc);
        }
        ctx1[(size_t)b * NTOT1 + n] = acc;
    }
}

// ---------------------------------------------------------------------------
// Weight transpose + fp16 cast
// ---------------------------------------------------------------------------
__global__ void wtrans_kernel(const float* __restrict__ W1, int N1, int ld1,
                              const float* __restrict__ W2, int N2, int ld2,
                              int K, __half* __restrict__ Wt)
{
    __shared__ float tile[32][33];
    const int nb = blockIdx.x * 32, kb = blockIdx.y * 32;
    const int tx = threadIdx.x, ty = threadIdx.y;
    const int Ntot = N1 + N2;
    for (int i = ty; i < 32; i += 8) {
        int k = kb + i, n = nb + tx;
        float v = 0.f;
        if (k < K && n < Ntot)
            v = (n < N1) ? W1[(size_t)k * ld1 + n] : W2[(size_t)k * ld2 + (n - N1)];
        tile[i][tx] = v;
    }
    __syncthreads();
    for (int i = ty; i < 32; i += 8) {
        int n = nb + i, k = kb + tx;
        if (n < Ntot && k < K)
            Wt[(size_t)n * K + k] = __float2half_rn(tile[tx][i]);
    }
}

// ---------------------------------------------------------------------------
// HGEMM via mma.sync m16n8k16 over COMPACTED valid rows (dense A).
// CTA tile 128x128, BK=32, 4-stage cp.async pipeline, 8 warps (4m x 2n).
// MODE 0 (GEMM1), col tiles <1024: silu(x+bias+ctx) -> fp16 outh (dense).
// MODE 0, col tiles >=1024 (attn): silu(x+ab1+ctx) projected by aw2 in-register,
//   deterministic slot-based smem reduction -> g_spart[tile][rc][4]. No gmem ah.
// MODE 1 (GEMM3): x+bias1+residual[orig] -> outf[orig] (scatter).
// ---------------------------------------------------------------------------
#define NSTAGE    4
#define GSTAGE_B  20480               // (128*40*2) * 2 tiles
#define GSMEM     (NSTAGE * GSTAGE_B) // 81920

template<int MODE>
__global__ __launch_bounds__(256, 2) void gemm_mma(
    const __half* __restrict__ A, const __half* __restrict__ Bt, int K,
    const float* __restrict__ bias1, const float* __restrict__ bias2,
    const float* __restrict__ ctx1, const float* __restrict__ aw2,
    __half* __restrict__ outh, float* __restrict__ spart,
    float* __restrict__ outf, const float* __restrict__ residual)
{
    const int total = g_meta[0];
    const int npad  = g_meta[1];
    const int row0  = blockIdx.y * 128;
    if (row0 >= npad) return;

    extern __shared__ char smem[];
    const uint32_t sbase = smem_u32(smem);
    const int tid    = threadIdx.x;
    const int wid    = tid >> 5;
    const int lane   = tid & 31;
    const int warp_m = wid & 3;
    const int warp_n = wid >> 2;
    const int col0   = blockIdx.x * 128;
    const int iters  = K >> 5;

    const int ldr = tid >> 2;
    const int ldk = (tid & 3) * 8;

    float acc[2][8][4];
    #pragma unroll
    for (int mt = 0; mt < 2; mt++)
        #pragma unroll
        for (int nt = 0; nt < 8; nt++)
            #pragma unroll
            for (int j = 0; j < 4; j++) acc[mt][nt][j] = 0.f;

    const int lm = lane & 15, lq = lane >> 4;
    const uint32_t aoff = ((warp_m * 32 + lm) * 40 + lq * 8) * 2;
    const int bn = (lane >> 4) * 8 + (lane & 7);
    const int bk = ((lane >> 3) & 1) * 8;
    const uint32_t boff = ((warp_n * 64 + bn) * 40 + bk) * 2;

    auto load_stage = [&](int s, int kk) {
        const uint32_t dA = sbase + s * GSTAGE_B;
        const uint32_t dB = dA + 10240;
        #pragma unroll
        for (int i = 0; i < 2; i++) {
            const int r = ldr + i * 64;
            const uint32_t soff = (r * 40 + ldk) * 2;
            CP_ASYNC16(dA + soff, &A [(size_t)(row0 + r) * K + kk + ldk]);
            CP_ASYNC16(dB + soff, &Bt[(size_t)(col0 + r) * K + kk + ldk]);
        }
    };

    load_stage(0, 0);  CP_COMMIT();
    load_stage(1, 32); CP_COMMIT();
    load_stage(2, 64); CP_COMMIT();

    for (int i = 0; i < iters; i++) {
        CP_WAIT2();
        __syncthreads();
        if (i + 3 < iters) load_stage((i + 3) % NSTAGE, (i + 3) * 32);
        CP_COMMIT();

        const int s = i % NSTAGE;
        const uint32_t sA = sbase + s * GSTAGE_B;
        const uint32_t sB = sA + 10240;

        #pragma unroll
        for (int ks = 0; ks < 2; ks++) {
            uint32_t a[2][4];
            #pragma unroll
            for (int mt = 0; mt < 2; mt++)
                LDSM_X4(a[mt][0], a[mt][1], a[mt][2], a[mt][3],
                        sA + aoff + mt * 1280 + ks * 32);
            uint32_t b[8][2];
            #pragma unroll
            for (int np = 0; np < 4; np++) {
                uint32_t r0, r1, r2, r3;
                LDSM_X4(r0, r1, r2, r3, sB + boff + np * 1280 + ks * 32);
                b[np * 2][0]     = r0; b[np * 2][1]     = r1;
                b[np * 2 + 1][0] = r2; b[np * 2 + 1][1] = r3;
            }
            #pragma unroll
            for (int mt = 0; mt < 2; mt++)
                #pragma unroll
                for (int nt = 0; nt < 8; nt++)
                    MMA16816(acc[mt][nt], a[mt], b[nt]);
        }
    }

    // ---------------- epilogue ----------------
    const int rl0 = warp_m * 32 + (lane >> 2);
    const int ncb = col0 + warp_n * 64 + (lane & 3) * 2;

    if (MODE == 0 && col0 >= FHID) {
        // attention tile: project silu(ah) by aw2, deterministic slot reduction.
        float* sred = (float*)smem;
        const int slot = warp_n * 4 + (lane & 3);
        __syncthreads();
        #pragma unroll
        for (int mt = 0; mt < 2; mt++) {
            #pragma unroll
            for (int half = 0; half < 2; half++) {
                const int rl = rl0 + mt * 16 + half * 8;
                const int rc = row0 + rl;
                float p0 = 0.f, p1 = 0.f, p2 = 0.f, p3 = 0.f;
                if (rc < total) {
                    const int bg = g_rowidx[rc] >> 8;
                    #pragma unroll
                    for (int nt = 0; nt < 8; nt++) {
                        const int ncol = ncb + nt * 8;
                        const int a0   = ncol - FHID;
                        float v0 = silu(acc[mt][nt][half * 2]     + bias2[a0] +
                                        ctx1[(size_t)bg * NTOT1 + ncol]);
                        float v1 = silu(acc[mt][nt][half * 2 + 1] + bias2[a0 + 1] +
                                        ctx1[(size_t)bg * NTOT1 + ncol + 1]);
                        float4 w0 = ((const float4*)aw2)[a0];
                        float4 w1 = ((const float4*)aw2)[a0 + 1];
                        p0 = fmaf(v0, w0.x, fmaf(v1, w1.x, p0));
                        p1 = fmaf(v0, w0.y, fmaf(v1, w1.y, p1));
                        p2 = fmaf(v0, w0.z, fmaf(v1, w1.z, p2));
                        p3 = fmaf(v0, w0.w, fmaf(v1, w1.w, p3));
                    }
                }
                sred[(rl * 4 + 0) * 8 + slot] = p0;
                sred[(rl * 4 + 1) * 8 + slot] = p1;
                sred[(rl * 4 + 2) * 8 + slot] = p2;
                sred[(rl * 4 + 3) * 8 + slot] = p3;
            }
        }
        __syncthreads();
        const int tsel = (col0 - FHID) >> 7;     // 0 or 1
        for (int p = tid; p < 512; p += 256) {   // p = rl*4 + h
            const int rc = row0 + (p >> 2);
            if (rc < total) {
                const float* q = &sred[p * 8];
                float s = ((q[0] + q[1]) + (q[2] + q[3])) +
                          ((q[4] + q[5]) + (q[6] + q[7]));
                spart[(size_t)tsel * MROWS * NHEADS + rc * 4 + (p & 3)] = s;
            }
        }
        return;
    }

    #pragma unroll
    for (int mt = 0; mt < 2; mt++) {
        #pragma unroll
        for (int half = 0; half < 2; half++) {
            const int rc = row0 + rl0 + mt * 16 + half * 8;
            if (rc >= total) continue;
            const int orig = g_rowidx[rc];
            const int bg   = orig >> 8;
            #pragma unroll
            for (int nt = 0; nt < 8; nt++) {
                const int ncol = ncb + nt * 8;
                float v0 = acc[mt][nt][half * 2];
                float v1 = acc[mt][nt][half * 2 + 1];
                if (MODE == 0) {
                    v0 = silu(v0 + bias1[ncol]     + ctx1[(size_t)bg * NTOT1 + ncol]);
                    v1 = silu(v1 + bias1[ncol + 1] + ctx1[(size_t)bg * NTOT1 + ncol + 1]);
                    *(__half2*)&outh[(size_t)rc * FHID + ncol] =
                        __floats2half2_rn(v0, v1);
                } else {
                    float2 o;
                    o.x = v0 + bias1[ncol]     + residual[(size_t)orig * FOUT + ncol];
                    o.y = v1 + bias1[ncol + 1] + residual[(size_t)orig * FOUT + ncol + 1];
                    *(float2*)&outf[(size_t)orig * FOUT + ncol] = o;
                }
            }
        }
    }
}

// ---------------------------------------------------------------------------
// Finalize per graph: scores -> masked softmax -> pooling + masked-row copy.
// ---------------------------------------------------------------------------
__global__ void finalize_kernel(const float* __restrict__ nodes,
                                const int* __restrict__ mask,
                                const float* __restrict__ spart,
                                const float* __restrict__ ab2,
                                float* __restrict__ newn,
                                float* __restrict__ pooled)
{
    const int b = blockIdx.x, n = threadIdx.x;
    const int wid = n >> 5, lane = n & 31;
    __shared__ float  ws[NNODES * NHEADS];
    __shared__ int    ridx[NNODES];
    __shared__ int    ilist[NNODES];
    __shared__ int    icnt;
    __shared__ float4 red[NNODES];

    const int cnt = g_bcnt[b], off = g_boff[b];
    if (n == 0) icnt = 0;
    __syncthreads();
    const int valid = mask[b * NNODES + n];
    if (n < cnt) ridx[n] = g_rowidx[off + n];
    if (!valid) { int p = atomicAdd(&icnt, 1); ilist[p] = n; }

    const float NEG = -INFINITY;
    const float inv_scale = 1.0f / 16.0f;
    float v0 = NEG, v1 = NEG, v2 = NEG, v3 = NEG;
    if (n < cnt) {
        const int rc = off + n;
        float4 s0 = ((const float4*)spart)[rc];
        float4 s1 = ((const float4*)spart)[MROWS + rc];
        v0 = (s0.x + s1.x + ab2[0]) * inv_scale;
        v1 = (s0.y + s1.y + ab2[1]) * inv_scale;
        v2 = (s0.z + s1.z + ab2[2]) * inv_scale;
        v3 = (s0.w + s1.w + ab2[3]) * inv_scale;
    }

    red[n] = make_float4(v0, v1, v2, v3);
    __syncthreads();
    for (int o = 128; o > 0; o >>= 1) {
        if (n < o) {
            float4 a = red[n], c = red[n + o];
            red[n] = make_float4(fmaxf(a.x, c.x), fmaxf(a.y, c.y),
                                 fmaxf(a.z, c.z), fmaxf(a.w, c.w));
        }
        __syncthreads();
    }
    float4 mx = red[0];
    __syncthreads();

    float e0 = (n < cnt) ? __expf(v0 - mx.x) : 0.f;
    float e1 = (n < cnt) ? __expf(v1 - mx.y) : 0.f;
    float e2 = (n < cnt) ? __expf(v2 - mx.z) : 0.f;
    float e3 = (n < cnt) ? __expf(v3 - mx.w) : 0.f;

    red[n] = make_float4(e0, e1, e2, e3);
    __syncthreads();
    for (int o = 128; o > 0; o >>= 1) {
        if (n < o) {
            float4 a = red[n], c = red[n + o];
            red[n] = make_float4(a.x + c.x, a.y + c.y, a.z + c.z, a.w + c.w);
        }
        __syncthreads();
    }
    float4 sm = red[0];
    __syncthreads();

    if (n < cnt) {
        const int ln = ridx[n] & 255;
        ((float4*)ws)[ln] = make_float4(e0 / sm.x, e1 / sm.y, e2 / sm.z, e3 / sm.w);
    }
    __syncthreads();

    // pooling over valid rows
    const int h = n >> 6;
    float acc = 0.f;
    for (int i = 0; i < cnt; i++) {
        const int orig = ridx[i];
        acc = fmaf(newn[(size_t)orig * FOUT + n], ws[(orig & 255) * 4 + h], acc);
    }
    pooled[b * FOUT + n] = acc;

    // masked rows: new_nodes = nodes (one warp per row, 2 float4 per lane)
    for (int j = wid; j < icnt; j += 8) {
        const int row = b * NNODES + ilist[j];
        float4*       dst = (float4*)(newn + (size_t)row * FOUT);
        const float4* src = (const float4*)(nodes + (size_t)row * FOUT);
        dst[lane]      = src[lane];
        dst[lane + 32] = src[lane + 32];
    }
}

// ---------------------------------------------------------------------------
// Launch
// ---------------------------------------------------------------------------
extern "C" void kernel_launch(void* const* d_in, const int* in_sizes, int n_in,
                              void* d_out, int out_size)
{
    const float* nodes = (const float*)d_in[0];
    const float* pe    = (const float*)d_in[1];
    const int*   mask  = (const int*)d_in[2];
    const float* globs = (const float*)d_in[3];
    const float* ln_g  = (const float*)d_in[4];
    const float* ln_b  = (const float*)d_in[5];
    const float* fw1   = (const float*)d_in[6];
    const float* fb1   = (const float*)d_in[7];
    const float* fw2   = (const float*)d_in[8];
    const float* fb2   = (const float*)d_in[9];
    const float* aw1   = (const float*)d_in[10];
    const float* ab1   = (const float*)d_in[11];
    const float* aw2   = (const float*)d_in[12];
    const float* ab2   = (const float*)d_in[13];

    float* out_nodes  = (float*)d_out;
    float* out_pooled = out_nodes + (size_t)MROWS * FOUT;

    __half *p_inp, *p_hid, *p_w1t, *p_w2t;
    float  *p_spart, *p_ctx1;
    cudaGetSymbolAddress((void**)&p_inp,   g_inp);
    cudaGetSymbolAddress((void**)&p_hid,   g_hid);
    cudaGetSymbolAddress((void**)&p_spart, g_spart);
    cudaGetSymbolAddress((void**)&p_w1t,   g_w1t);
    cudaGetSymbolAddress((void**)&p_w2t,   g_w2t);
    cudaGetSymbolAddress((void**)&p_ctx1,  g_ctx1);

    cudaFuncSetAttribute(gemm_mma<0>, cudaFuncAttributeMaxDynamicSharedMemorySize, GSMEM);
    cudaFuncSetAttribute(gemm_mma<1>, cudaFuncAttributeMaxDynamicSharedMemorySize, GSMEM);
    cudaFuncSetAttribute(gemm_mma<0>, cudaFuncAttributePreferredSharedMemoryCarveout, 100);
    cudaFuncSetAttribute(gemm_mma<1>, cudaFuncAttributePreferredSharedMemoryCarveout, 100);

    // 1) compaction of valid rows (scatter also pads)
    count_kernel<<<512, 256>>>(mask);
    scan_kernel<<<1, 512>>>();
    scatter_kernel<<<512, 256>>>(mask);

    // 2) LN over compact rows (warp-per-row) -> g_inp dense; ctx; transposes
    prep_kernel<<<PREP_GRID, 256>>>(nodes, pe, ln_g, ln_b, p_inp);
    ctx_kernel<<<BATCH, 256>>>(globs, fw1, aw1, p_ctx1);
    wtrans_kernel<<<dim3(40, 16), dim3(32, 8)>>>(fw1, FHID, FHID, aw1, AHID, AHID,
                                                 FEAT_IN, p_w1t);
    wtrans_kernel<<<dim3(8, 32),  dim3(32, 8)>>>(fw2, FOUT, FOUT, nullptr, 0, 0,
                                                 FHID, p_w2t);

    // 3) GEMM1 on compact rows: hid tiles -> g_hid; attn tiles -> score partials
    gemm_mma<0><<<dim3(NTOT1 / 128, MROWS / 128), 256, GSMEM>>>(
        p_inp, p_w1t, FEAT_IN, fb1, ab1, p_ctx1, aw2, p_hid, p_spart,
        nullptr, nullptr);

    // 4) GEMM3 on compact rows, scatter +bias+residual -> new_nodes
    gemm_mma<1><<<dim3(FOUT / 128, MROWS / 128), 256, GSMEM>>>(
        p_hid, p_w2t, FHID, fb2, nullptr, nullptr, nullptr, nullptr, nullptr,
        out_nodes, nodes);

    // 5) finalize: softmax + pooling + masked-row copy
    finalize_kernel<<<BATCH, NNODES>>>(nodes, mask, p_spart, ab2,
                                       out_nodes, out_pooled);
}

// round 17
// speedup vs baseline: 2.3425x; 1.0253x over previous
#include <cuda_runtime.h>
#include <cuda_fp16.h>
#include <math.h>
#include <stdint.h>

// Problem constants
#define BATCH   512
#define NNODES  256
#define MROWS   (BATCH * NNODES)     // 131072
#define FEAT_IN 512
#define GLOB_D  64
#define FHID    1024
#define AHID    256
#define FOUT    256
#define NTOT1   (FHID + AHID)        // 1280
#define NHEADS  4
#define LN_EPS  1e-5f

// ---------------------------------------------------------------------------
// Scratch (device globals; no runtime allocation)
// ---------------------------------------------------------------------------
__device__ __half g_inp[(size_t)MROWS * FEAT_IN];      // fp16 LN output (COMPACT rows)
__device__ __half g_hid[(size_t)MROWS * FHID];         // fp16 silu hidden (COMPACT rows)
__device__ float  g_spart[(size_t)2 * MROWS * NHEADS]; // per-tile score partials
__device__ __half g_w1t[(size_t)NTOT1 * FEAT_IN];      // [1280,512] (fw1||aw1)^T fp16
__device__ __half g_w2t[(size_t)FOUT * FHID];          // [256,1024] fw2^T fp16
__device__ float  g_ctx1[(size_t)BATCH * NTOT1];       // per-graph ctx contribution
__device__ int    g_rowidx[MROWS];                     // compact -> original row
__device__ int    g_bcnt[512];                         // per-graph valid count
__device__ int    g_boff[512];                         // per-graph compact offset
__device__ int    g_meta[2];                           // [0]=total valid, [1]=padded

// ---------------------------------------------------------------------------
// PTX helpers (baseline ISA: works at compute_103 target)
// ---------------------------------------------------------------------------
__device__ __forceinline__ uint32_t smem_u32(const void* p) {
    uint32_t a;
    asm("{ .reg .u64 t; cvta.to.shared.u64 t, %1; cvt.u32.u64 %0, t; }"
        : "=r"(a) : "l"(p));
    return a;
}

#define CP_ASYNC16(dst, src) \
    asm volatile("cp.async.cg.shared.global [%0], [%1], 16;" \
        :: "r"(dst), "l"(src))
#define CP_COMMIT()  asm volatile("cp.async.commit_group;" ::: "memory")
#define CP_WAIT2()   asm volatile("cp.async.wait_group 2;" ::: "memory")

#define LDSM_X4(r0, r1, r2, r3, addr) \
    asm volatile("ldmatrix.sync.aligned.m8n8.x4.shared.b16 {%0,%1,%2,%3}, [%4];" \
        : "=r"(r0), "=r"(r1), "=r"(r2), "=r"(r3) : "r"(addr))

#define MMA16816(c, a, b) \
    asm volatile("mma.sync.aligned.m16n8k16.row.col.f32.f16.f16.f32 " \
        "{%0,%1,%2,%3}, {%4,%5,%6,%7}, {%8,%9}, {%0,%1,%2,%3};" \
        : "+f"((c)[0]), "+f"((c)[1]), "+f"((c)[2]), "+f"((c)[3]) \
        : "r"((a)[0]), "r"((a)[1]), "r"((a)[2]), "r"((a)[3]), \
          "r"((b)[0]), "r"((b)[1]))

__device__ __forceinline__ float warp_sum(float v) {
    #pragma unroll
    for (int o = 16; o > 0; o >>= 1) v += __shfl_xor_sync(0xffffffffu, v, o);
    return v;
}

__device__ __forceinline__ float silu(float v) {
    return __fdividef(v, 1.0f + __expf(-v));
}

// ---------------------------------------------------------------------------
// Compaction: count -> scan -> scatter(+pad)
// ---------------------------------------------------------------------------
__global__ void count_kernel(const int* __restrict__ mask)
{
    const int t = threadIdx.x, lane = t & 31, wid = t >> 5;
    const int r = blockIdx.x * 256 + t;
    __shared__ int ws[8];
    unsigned bal = __ballot_sync(0xffffffffu, mask[r] != 0);
    if (lane == 0) ws[wid] = __popc(bal);
    __syncthreads();
    if (t == 0) {
        int s = 0;
        #pragma unroll
        for (int i = 0; i < 8; i++) s += ws[i];
        g_bcnt[blockIdx.x] = s;
    }
}

__global__ void scan_kernel()
{
    __shared__ int s[512];
    const int t = threadIdx.x;
    const int c = g_bcnt[t];
    s[t] = c;
    __syncthreads();
    for (int off = 1; off < 512; off <<= 1) {
        int v = (t >= off) ? s[t - off] : 0;
        __syncthreads();
        s[t] += v;
        __syncthreads();
    }
    g_boff[t] = s[t] - c;
    if (t == 511) {
        g_meta[0] = s[511];
        g_meta[1] = ((s[511] + 127) >> 7) << 7;
    }
}

__global__ void scatter_kernel(const int* __restrict__ mask)
{
    const int t = threadIdx.x, lane = t & 31, wid = t >> 5;
    const int r = blockIdx.x * 256 + t;
    __shared__ int ws[8];
    const int v = mask[r] != 0;
    unsigned bal = __ballot_sync(0xffffffffu, v);
    if (lane == 0) ws[wid] = __popc(bal);
    __syncthreads();
    int wpre = 0;
    #pragma unroll
    for (int i = 0; i < 8; i++) if (i < wid) wpre += ws[i];
    if (v) {
        int pos = g_boff[blockIdx.x] + wpre + __popc(bal & ((1u << lane) - 1));
        g_rowidx[pos] = r;
    }
    // block 511 also pads [total, npad) — disjoint from scatter writes
    if (blockIdx.x == 511) {
        const int total = g_meta[0], npad = g_meta[1];
        for (int i = total + t; i < npad; i += 256) g_rowidx[i] = 0;
    }
}

// ---------------------------------------------------------------------------
// LayerNorm, warp-per-row (no block barriers in the loop).
// ---------------------------------------------------------------------------
#define PREP_GRID 2048

__global__ void prep_kernel(const float* __restrict__ nodes,
                            const float* __restrict__ pe,
                            const float* __restrict__ ln_g,
                            const float* __restrict__ ln_b,
                            __half* __restrict__ inp)
{
    __shared__ float sg[FEAT_IN], sb[FEAT_IN];
    for (int i = threadIdx.x; i < FEAT_IN; i += 256) {
        sg[i] = ln_g[i];
        sb[i] = ln_b[i];
    }
    __syncthreads();

    const int lane   = threadIdx.x & 31;
    const int gwarp  = blockIdx.x * 8 + (threadIdx.x >> 5);
    const int nwarps = PREP_GRID * 8;
    const int total  = g_meta[0];

    for (int rc = gwarp; rc < total; rc += nwarps) {
        const int row = g_rowidx[rc];
        const float4* nrow = (const float4*)nodes + (size_t)row * 64;
        const float4* prow = (const float4*)pe    + (size_t)row * 64;

        float4 a[4];
        a[0] = nrow[lane];
        a[1] = nrow[lane + 32];
        a[2] = prow[lane];
        a[3] = prow[lane + 32];

        float s = 0.f, q = 0.f;
        #pragma unroll
        for (int i = 0; i < 4; i++) {
            s += a[i].x + a[i].y + a[i].z + a[i].w;
            q += a[i].x*a[i].x + a[i].y*a[i].y + a[i].z*a[i].z + a[i].w*a[i].w;
        }
        s = warp_sum(s);
        q = warp_sum(q);
        const float mu   = s * (1.0f / FEAT_IN);
        const float var  = q * (1.0f / FEAT_IN) - mu * mu;
        const float rstd = rsqrtf(var + LN_EPS);

        __half* dst = inp + (size_t)rc * FEAT_IN;
        #pragma unroll
        for (int i = 0; i < 4; i++) {
            const int e4 = (i < 2) ? (lane + i * 32) : (64 + lane + (i - 2) * 32);
            float4 g4 = ((const float4*)sg)[e4];
            float4 b4 = ((const float4*)sb)[e4];
            float o0 = (a[i].x - mu) * rstd * g4.x + b4.x;
            float o1 = (a[i].y - mu) * rstd * g4.y + b4.y;
            float o2 = (a[i].z - mu) * rstd * g4.z + b4.z;
            float o3 = (a[i].w - mu) * rstd * g4.w + b4.w;
            *(__half2*)(dst + e4 * 4)     = __floats2half2_rn(o0, o1);
            *(__half2*)(dst + e4 * 4 + 2) = __floats2half2_rn(o2, o3);
        }
    }
}

// ---------------------------------------------------------------------------
// aux_kernel: one launch covering
//   [0, 640)        : w1t transpose tiles (40 x 16 of 32x32), (fw1||aw1)^T
//   [640, 896)      : w2t transpose tiles (8 x 32 of 32x32), fw2^T
//   [896, 1408)     : ctx1 per-graph contribution (one graph per block)
// block = 256 threads (wtrans path views it as 32x8).
// ---------------------------------------------------------------------------
__device__ __forceinline__ void wtrans_tile(
    const float* W1, int N1, int ld1,
    const float* W2, int N2, int ld2,
    int K, __half* Wt, int nb, int kb, int tx, int ty)
{
    __shared__ float tile[32][33];
    const int Ntot = N1 + N2;
    for (int i = ty; i < 32; i += 8) {
        int k = kb + i, n = nb + tx;
        float v = 0.f;
        if (k < K && n < Ntot)
            v = (n < N1) ? W1[(size_t)k * ld1 + n] : W2[(size_t)k * ld2 + (n - N1)];
        tile[i][tx] = v;
    }
    __syncthreads();
    for (int i = ty; i < 32; i += 8) {
        int n = nb + i, k = kb + tx;
        if (n < Ntot && k < K)
            Wt[(size_t)n * K + k] = __float2half_rn(tile[tx][i]);
    }
}

__global__ void aux_kernel(const float* __restrict__ globs,
                           const float* __restrict__ fw1,
                           const float* __restrict__ aw1,
                           const float* __restrict__ fw2,
                           __half* __restrict__ w1t,
                           __half* __restrict__ w2t,
                           float* __restrict__ ctx1)
{
    const int bx = blockIdx.x;
    const int tid = threadIdx.x;
    const int tx = tid & 31, ty = tid >> 5;

    if (bx < 640) {
        // w1t: nb index 0..39, kb index 0..15
        wtrans_tile(fw1, FHID, FHID, aw1, AHID, AHID, FEAT_IN, w1t,
                    (bx % 40) * 32, (bx / 40) * 32, tx, ty);
    } else if (bx < 896) {
        const int b2 = bx - 640;   // nb 0..7, kb 0..31
        wtrans_tile(fw2, FOUT, FOUT, nullptr, 0, 0, FHID, w2t,
                    (b2 % 8) * 32, (b2 / 8) * 32, tx, ty);
    } else {
        const int b = bx - 896;
        __shared__ float gs[GLOB_D];
        if (tid < GLOB_D) gs[tid] = globs[b * GLOB_D + tid];
        __syncthreads();
        for (int n = tid; n < NTOT1; n += 256) {
            float acc = 0.f;
            if (n < FHID) {
                #pragma unroll 8
                for (int j = 0; j < GLOB_D; j++)
                    acc = fmaf(gs[j], fw1[(size_t)(FEAT_IN + j) * FHID + n], acc);
            } else {
                #pragma unroll 8
                for (int j = 0; j < GLOB_D; j++)
                    acc = fmaf(gs[j], aw1[(size_t)(FEAT_IN + j) * AHID + (n - FHID)], acc);
            }
            ctx1[(size_t)b * NTOT1 + n] = acc;
        }
    }
}

// ---------------------------------------------------------------------------
// HGEMM via mma.sync m16n8k16 over COMPACTED valid rows (dense A).
// CTA tile 128x128, BK=32, 4-stage cp.async pipeline, 8 warps (4m x 2n).
// MODE 0 (GEMM1), col tiles <1024: silu(x+bias+ctx) -> fp16 outh (dense).
// MODE 0, col tiles >=1024 (attn): silu(x+ab1+ctx) projected by aw2 in-register,
//   deterministic slot-based smem reduction -> g_spart[tile][rc][4].
// MODE 1 (GEMM3): x+bias1+residual[orig] -> outf[orig] (scatter).
// ---------------------------------------------------------------------------
#define NSTAGE    4
#define GSTAGE_B  20480               // (128*40*2) * 2 tiles
#define GSMEM     (NSTAGE * GSTAGE_B) // 81920

template<int MODE>
__global__ __launch_bounds__(256, 2) void gemm_mma(
    const __half* __restrict__ A, const __half* __restrict__ Bt, int K,
    const float* __restrict__ bias1, const float* __restrict__ bias2,
    const float* __restrict__ ctx1, const float* __restrict__ aw2,
    __half* __restrict__ outh, float* __restrict__ spart,
    float* __restrict__ outf, const float* __restrict__ residual)
{
    const int total = g_meta[0];
    const int npad  = g_meta[1];
    const int row0  = blockIdx.y * 128;
    if (row0 >= npad) return;

    extern __shared__ char smem[];
    const uint32_t sbase = smem_u32(smem);
    const int tid    = threadIdx.x;
    const int wid    = tid >> 5;
    const int lane   = tid & 31;
    const int warp_m = wid & 3;
    const int warp_n = wid >> 2;
    const int col0   = blockIdx.x * 128;
    const int iters  = K >> 5;

    const int ldr = tid >> 2;
    const int ldk = (tid & 3) * 8;

    float acc[2][8][4];
    #pragma unroll
    for (int mt = 0; mt < 2; mt++)
        #pragma unroll
        for (int nt = 0; nt < 8; nt++)
            #pragma unroll
            for (int j = 0; j < 4; j++) acc[mt][nt][j] = 0.f;

    const int lm = lane & 15, lq = lane >> 4;
    const uint32_t aoff = ((warp_m * 32 + lm) * 40 + lq * 8) * 2;
    const int bn = (lane >> 4) * 8 + (lane & 7);
    const int bk = ((lane >> 3) & 1) * 8;
    const uint32_t boff = ((warp_n * 64 + bn) * 40 + bk) * 2;

    auto load_stage = [&](int s, int kk) {
        const uint32_t dA = sbase + s * GSTAGE_B;
        const uint32_t dB = dA + 10240;
        #pragma unroll
        for (int i = 0; i < 2; i++) {
            const int r = ldr + i * 64;
            const uint32_t soff = (r * 40 + ldk) * 2;
            CP_ASYNC16(dA + soff, &A [(size_t)(row0 + r) * K + kk + ldk]);
            CP_ASYNC16(dB + soff, &Bt[(size_t)(col0 + r) * K + kk + ldk]);
        }
    };

    load_stage(0, 0);  CP_COMMIT();
    load_stage(1, 32); CP_COMMIT();
    load_stage(2, 64); CP_COMMIT();

    for (int i = 0; i < iters; i++) {
        CP_WAIT2();
        __syncthreads();
        if (i + 3 < iters) load_stage((i + 3) % NSTAGE, (i + 3) * 32);
        CP_COMMIT();

        const int s = i % NSTAGE;
        const uint32_t sA = sbase + s * GSTAGE_B;
        const uint32_t sB = sA + 10240;

        #pragma unroll
        for (int ks = 0; ks < 2; ks++) {
            uint32_t a[2][4];
            #pragma unroll
            for (int mt = 0; mt < 2; mt++)
                LDSM_X4(a[mt][0], a[mt][1], a[mt][2], a[mt][3],
                        sA + aoff + mt * 1280 + ks * 32);
            uint32_t b[8][2];
            #pragma unroll
            for (int np = 0; np < 4; np++) {
                uint32_t r0, r1, r2, r3;
                LDSM_X4(r0, r1, r2, r3, sB + boff + np * 1280 + ks * 32);
                b[np * 2][0]     = r0; b[np * 2][1]     = r1;
                b[np * 2 + 1][0] = r2; b[np * 2 + 1][1] = r3;
            }
            #pragma unroll
            for (int mt = 0; mt < 2; mt++)
                #pragma unroll
                for (int nt = 0; nt < 8; nt++)
                    MMA16816(acc[mt][nt], a[mt], b[nt]);
        }
    }

    // ---------------- epilogue ----------------
    const int rl0 = warp_m * 32 + (lane >> 2);
    const int ncb = col0 + warp_n * 64 + (lane & 3) * 2;

    if (MODE == 0 && col0 >= FHID) {
        float* sred = (float*)smem;
        const int slot = warp_n * 4 + (lane & 3);
        __syncthreads();
        #pragma unroll
        for (int mt = 0; mt < 2; mt++) {
            #pragma unroll
            for (int half = 0; half < 2; half++) {
                const int rl = rl0 + mt * 16 + half * 8;
                const int rc = row0 + rl;
                float p0 = 0.f, p1 = 0.f, p2 = 0.f, p3 = 0.f;
                if (rc < total) {
                    const int bg = g_rowidx[rc] >> 8;
                    #pragma unroll
                    for (int nt = 0; nt < 8; nt++) {
                        const int ncol = ncb + nt * 8;
                        const int a0   = ncol - FHID;
                        float v0 = silu(acc[mt][nt][half * 2]     + bias2[a0] +
                                        ctx1[(size_t)bg * NTOT1 + ncol]);
                        float v1 = silu(acc[mt][nt][half * 2 + 1] + bias2[a0 + 1] +
                                        ctx1[(size_t)bg * NTOT1 + ncol + 1]);
                        float4 w0 = ((const float4*)aw2)[a0];
                        float4 w1 = ((const float4*)aw2)[a0 + 1];
                        p0 = fmaf(v0, w0.x, fmaf(v1, w1.x, p0));
                        p1 = fmaf(v0, w0.y, fmaf(v1, w1.y, p1));
                        p2 = fmaf(v0, w0.z, fmaf(v1, w1.z, p2));
                        p3 = fmaf(v0, w0.w, fmaf(v1, w1.w, p3));
                    }
                }
                sred[(rl * 4 + 0) * 8 + slot] = p0;
                sred[(rl * 4 + 1) * 8 + slot] = p1;
                sred[(rl * 4 + 2) * 8 + slot] = p2;
                sred[(rl * 4 + 3) * 8 + slot] = p3;
            }
        }
        __syncthreads();
        const int tsel = (col0 - FHID) >> 7;     // 0 or 1
        for (int p = tid; p < 512; p += 256) {   // p = rl*4 + h
            const int rc = row0 + (p >> 2);
            if (rc < total) {
                const float* q = &sred[p * 8];
                float s = ((q[0] + q[1]) + (q[2] + q[3])) +
                          ((q[4] + q[5]) + (q[6] + q[7]));
                spart[(size_t)tsel * MROWS * NHEADS + rc * 4 + (p & 3)] = s;
            }
        }
        return;
    }

    #pragma unroll
    for (int mt = 0; mt < 2; mt++) {
        #pragma unroll
        for (int half = 0; half < 2; half++) {
            const int rc = row0 + rl0 + mt * 16 + half * 8;
            if (rc >= total) continue;
            const int orig = g_rowidx[rc];
            const int bg   = orig >> 8;
            #pragma unroll
            for (int nt = 0; nt < 8; nt++) {
                const int ncol = ncb + nt * 8;
                float v0 = acc[mt][nt][half * 2];
                float v1 = acc[mt][nt][half * 2 + 1];
                if (MODE == 0) {
                    v0 = silu(v0 + bias1[ncol]     + ctx1[(size_t)bg * NTOT1 + ncol]);
                    v1 = silu(v1 + bias1[ncol + 1] + ctx1[(size_t)bg * NTOT1 + ncol + 1]);
                    *(__half2*)&outh[(size_t)rc * FHID + ncol] =
                        __floats2half2_rn(v0, v1);
                } else {
                    float2 o;
                    o.x = v0 + bias1[ncol]     + residual[(size_t)orig * FOUT + ncol];
                    o.y = v1 + bias1[ncol + 1] + residual[(size_t)orig * FOUT + ncol + 1];
                    *(float2*)&outf[(size_t)orig * FOUT + ncol] = o;
                }
            }
        }
    }
}

// ---------------------------------------------------------------------------
// Finalize per graph: scores -> masked softmax -> pooling + masked-row copy.
// ---------------------------------------------------------------------------
__global__ void finalize_kernel(const float* __restrict__ nodes,
                                const int* __restrict__ mask,
                                const float* __restrict__ spart,
                                const float* __restrict__ ab2,
                                float* __restrict__ newn,
                                float* __restrict__ pooled)
{
    const int b = blockIdx.x, n = threadIdx.x;
    const int wid = n >> 5, lane = n & 31;
    __shared__ float  ws[NNODES * NHEADS];
    __shared__ int    ridx[NNODES];
    __shared__ int    ilist[NNODES];
    __shared__ int    icnt;
    __shared__ float4 red[NNODES];

    const int cnt = g_bcnt[b], off = g_boff[b];
    if (n == 0) icnt = 0;
    __syncthreads();
    const int valid = mask[b * NNODES + n];
    if (n < cnt) ridx[n] = g_rowidx[off + n];
    if (!valid) { int p = atomicAdd(&icnt, 1); ilist[p] = n; }

    const float NEG = -INFINITY;
    const float inv_scale = 1.0f / 16.0f;
    float v0 = NEG, v1 = NEG, v2 = NEG, v3 = NEG;
    if (n < cnt) {
        const int rc = off + n;
        float4 s0 = ((const float4*)spart)[rc];
        float4 s1 = ((const float4*)spart)[MROWS + rc];
        v0 = (s0.x + s1.x + ab2[0]) * inv_scale;
        v1 = (s0.y + s1.y + ab2[1]) * inv_scale;
        v2 = (s0.z + s1.z + ab2[2]) * inv_scale;
        v3 = (s0.w + s1.w + ab2[3]) * inv_scale;
    }

    red[n] = make_float4(v0, v1, v2, v3);
    __syncthreads();
    for (int o = 128; o > 0; o >>= 1) {
        if (n < o) {
            float4 a = red[n], c = red[n + o];
            red[n] = make_float4(fmaxf(a.x, c.x), fmaxf(a.y, c.y),
                                 fmaxf(a.z, c.z), fmaxf(a.w, c.w));
        }
        __syncthreads();
    }
    float4 mx = red[0];
    __syncthreads();

    float e0 = (n < cnt) ? __expf(v0 - mx.x) : 0.f;
    float e1 = (n < cnt) ? __expf(v1 - mx.y) : 0.f;
    float e2 = (n < cnt) ? __expf(v2 - mx.z) : 0.f;
    float e3 = (n < cnt) ? __expf(v3 - mx.w) : 0.f;

    red[n] = make_float4(e0, e1, e2, e3);
    __syncthreads();
    for (int o = 128; o > 0; o >>= 1) {
        if (n < o) {
            float4 a = red[n], c = red[n + o];
            red[n] = make_float4(a.x + c.x, a.y + c.y, a.z + c.z, a.w + c.w);
        }
        __syncthreads();
    }
    float4 sm = red[0];
    __syncthreads();

    if (n < cnt) {
        const int ln = ridx[n] & 255;
        ((float4*)ws)[ln] = make_float4(e0 / sm.x, e1 / sm.y, e2 / sm.z, e3 / sm.w);
    }
    __syncthreads();

    // pooling over valid rows
    const int h = n >> 6;
    float acc = 0.f;
    for (int i = 0; i < cnt; i++) {
        const int orig = ridx[i];
        acc = fmaf(newn[(size_t)orig * FOUT + n], ws[(orig & 255) * 4 + h], acc);
    }
    pooled[b * FOUT + n] = acc;

    // masked rows: new_nodes = nodes (one warp per row, 2 float4 per lane)
    for (int j = wid; j < icnt; j += 8) {
        const int row = b * NNODES + ilist[j];
        float4*       dst = (float4*)(newn + (size_t)row * FOUT);
        const float4* src = (const float4*)(nodes + (size_t)row * FOUT);
        dst[lane]      = src[lane];
        dst[lane + 32] = src[lane + 32];
    }
}

// ---------------------------------------------------------------------------
// Launch
// ---------------------------------------------------------------------------
extern "C" void kernel_launch(void* const* d_in, const int* in_sizes, int n_in,
                              void* d_out, int out_size)
{
    const float* nodes = (const float*)d_in[0];
    const float* pe    = (const float*)d_in[1];
    const int*   mask  = (const int*)d_in[2];
    const float* globs = (const float*)d_in[3];
    const float* ln_g  = (const float*)d_in[4];
    const float* ln_b  = (const float*)d_in[5];
    const float* fw1   = (const float*)d_in[6];
    const float* fb1   = (const float*)d_in[7];
    const float* fw2   = (const float*)d_in[8];
    const float* fb2   = (const float*)d_in[9];
    const float* aw1   = (const float*)d_in[10];
    const float* ab1   = (const float*)d_in[11];
    const float* aw2   = (const float*)d_in[12];
    const float* ab2   = (const float*)d_in[13];

    float* out_nodes  = (float*)d_out;
    float* out_pooled = out_nodes + (size_t)MROWS * FOUT;

    __half *p_inp, *p_hid, *p_w1t, *p_w2t;
    float  *p_spart, *p_ctx1;
    cudaGetSymbolAddress((void**)&p_inp,   g_inp);
    cudaGetSymbolAddress((void**)&p_hid,   g_hid);
    cudaGetSymbolAddress((void**)&p_spart, g_spart);
    cudaGetSymbolAddress((void**)&p_w1t,   g_w1t);
    cudaGetSymbolAddress((void**)&p_w2t,   g_w2t);
    cudaGetSymbolAddress((void**)&p_ctx1,  g_ctx1);

    cudaFuncSetAttribute(gemm_mma<0>, cudaFuncAttributeMaxDynamicSharedMemorySize, GSMEM);
    cudaFuncSetAttribute(gemm_mma<1>, cudaFuncAttributeMaxDynamicSharedMemorySize, GSMEM);
    cudaFuncSetAttribute(gemm_mma<0>, cudaFuncAttributePreferredSharedMemoryCarveout, 100);
    cudaFuncSetAttribute(gemm_mma<1>, cudaFuncAttributePreferredSharedMemoryCarveout, 100);

    // 1) compaction of valid rows (scatter also pads)
    count_kernel<<<512, 256>>>(mask);
    scan_kernel<<<1, 512>>>();
    scatter_kernel<<<512, 256>>>(mask);

    // 2) LN over compact rows (warp-per-row) + fused aux (transposes + ctx)
    prep_kernel<<<PREP_GRID, 256>>>(nodes, pe, ln_g, ln_b, p_inp);
    aux_kernel<<<1408, 256>>>(globs, fw1, aw1, fw2, p_w1t, p_w2t, p_ctx1);

    // 3) GEMM1 on compact rows: hid tiles -> g_hid; attn tiles -> score partials
    gemm_mma<0><<<dim3(NTOT1 / 128, MROWS / 128), 256, GSMEM>>>(
        p_inp, p_w1t, FEAT_IN, fb1, ab1, p_ctx1, aw2, p_hid, p_spart,
        nullptr, nullptr);

    // 4) GEMM3 on compact rows, scatter +bias+residual -> new_nodes
    gemm_mma<1><<<dim3(FOUT / 128, MROWS / 128), 256, GSMEM>>>(
        p_hid, p_w2t, FHID, fb2, nullptr, nullptr, nullptr, nullptr, nullptr,
        out_nodes, nodes);

    // 5) finalize: softmax + pooling + masked-row copy
    finalize_kernel<<<BATCH, NNODES>>>(nodes, mask, p_spart, ab2,
                                       out_nodes, out_pooled);
}